// round 2
// baseline (speedup 1.0000x reference)
#include <cuda_runtime.h>
#include <math.h>
#include <stdint.h>

// Problem dims
#define Bsz 8
#define Ssz 256
#define Vsz 32000
#define Dsz 512
#define Nly 16
#define Rsz 512
#define G4  2048            // 4*R
#define Mtok (Bsz*Ssz)      // 2048 tokens
#define NBR (Nly*Bsz*Rsz)   // 65536

// ---------------- scratch (static device globals; no runtime alloc) ----------
__device__ float g_X   [Mtok*Dsz];                       // X[t*8+b][d]
__device__ float g_Gih [(size_t)Ssz*Nly*Bsz*G4];         // [t][n][b][g] (bias folded in)
__device__ float g_hall[(size_t)Ssz*Nly*Bsz*Rsz];        // h_new per step
__device__ float g_cbuf[2*NBR];                          // c ping-pong
__device__ float g_q   [Mtok*Dsz];
__device__ float g_Wnk [Nly*Dsz*Rsz];                    // Wk @ W_np[n]
__device__ float g_Wnv [Nly*Dsz*Rsz];
__device__ float g_ck  [Nly*Dsz];
__device__ float g_cv  [Nly*Dsz];
__device__ float g_k   [(size_t)Mtok*Nly*Dsz];           // [m][n][d]
__device__ float g_v   [(size_t)Mtok*Nly*Dsz];
__device__ float g_att [Mtok*Dsz];
__device__ float g_mix [Mtok*Dsz];

__device__ __forceinline__ float sigm(float x){ return 1.f/(1.f+expf(-x)); }

// ---------------- generic 64x64x16 tiled fp32 GEMM, C = A * B^T (+bias...) ---
// MODE 0: q     = X @ Wq^T + bq                 C[m*512+j]
// MODE 1: Gih   = X @ W_ih[n]^T + b_ih + b_hh   C[(t*128+n*8+b)*2048+j]
// MODE 2: logit = mix @ head_w^T + head_b       C[(b*256+t)*32000+j]
// MODE 3: k/v   = hall @ Wnk[n]^T + ck[n]       A row=(t*128+n*8+b), C[(m*16+n)*512+j]
// MODE 4: y     = att @ op_w^T + op_b + X       C[m*512+j]
// MODE 5: Wnk[n]= Wk @ W_np[n] (B is K-major)   C[n*D*R + m*512+j]
template<int MODE>
__global__ void __launch_bounds__(256) gemm_k(
    const float* __restrict__ A, const float* __restrict__ Bw,
    float* __restrict__ C, const float* __restrict__ bias,
    const float* __restrict__ bias2, const float* __restrict__ resid)
{
    const int K = 512;
    __shared__ float As[16][64];
    __shared__ float Bs[16][64];
    int tid = threadIdx.x;
    int bn = blockIdx.x, bm = blockIdx.y, n = blockIdx.z;

    const float* Bp = Bw;
    if (MODE==1) Bp += (size_t)n*G4 *K;
    if (MODE==3) Bp += (size_t)n*Dsz*K;
    if (MODE==5) Bp += (size_t)n*Dsz*Rsz;

    int aRow = tid>>2, aC4 = (tid&3)<<2;
    int ty = tid>>4, tx = tid&15;
    float acc[4][4] = {};

    for (int kb=0; kb<K; kb+=16){
        // A tile (K-contiguous rows)
        int am = bm*64 + aRow;
        int ag = am;
        if (MODE==3){ int t=am>>3, b=am&7; ag = t*128 + n*8 + b; }
        float4 av = *(const float4*)(A + (size_t)ag*K + kb + aC4);
        As[aC4+0][aRow]=av.x; As[aC4+1][aRow]=av.y;
        As[aC4+2][aRow]=av.z; As[aC4+3][aRow]=av.w;
        // B tile
        if (MODE==5){
            int idx = tid<<2; int kk = idx>>6, jc = idx&63;
            float4 bv = *(const float4*)(Bp + (size_t)(kb+kk)*Rsz + bn*64 + jc);
            Bs[kk][jc+0]=bv.x; Bs[kk][jc+1]=bv.y; Bs[kk][jc+2]=bv.z; Bs[kk][jc+3]=bv.w;
        } else {
            float4 bv = *(const float4*)(Bp + (size_t)(bn*64 + aRow)*K + kb + aC4);
            Bs[aC4+0][aRow]=bv.x; Bs[aC4+1][aRow]=bv.y;
            Bs[aC4+2][aRow]=bv.z; Bs[aC4+3][aRow]=bv.w;
        }
        __syncthreads();
        #pragma unroll
        for (int k=0;k<16;k++){
            float4 af = *(const float4*)&As[k][ty<<2];
            float4 bf = *(const float4*)&Bs[k][tx<<2];
            float a[4]={af.x,af.y,af.z,af.w};
            float b[4]={bf.x,bf.y,bf.z,bf.w};
            #pragma unroll
            for(int i=0;i<4;i++)
                #pragma unroll
                for(int j=0;j<4;j++) acc[i][j] += a[i]*b[j];
        }
        __syncthreads();
    }

    #pragma unroll
    for(int i=0;i<4;i++){
        int m = bm*64 + (ty<<2) + i;
        #pragma unroll
        for(int j=0;j<4;j++){
            int jc = bn*64 + (tx<<2) + j;
            float v = acc[i][j];
            if (MODE==0){ v += bias[jc]; C[(size_t)m*Dsz+jc]=v; }
            else if (MODE==1){
                v += bias[n*G4+jc] + bias2[n*G4+jc];
                int t=m>>3, b=m&7;
                C[(size_t)(t*128+n*8+b)*G4 + jc]=v;
            }
            else if (MODE==2){
                v += bias[jc];
                int t=m>>3, b=m&7;
                C[(size_t)(b*Ssz+t)*Vsz + jc]=v;
            }
            else if (MODE==3){
                v += bias[n*Dsz+jc];
                C[(size_t)(m*Nly+n)*Dsz + jc]=v;
            }
            else if (MODE==4){
                v += bias[jc] + resid[(size_t)m*Dsz+jc];
                C[(size_t)m*Dsz+jc]=v;
            }
            else { // MODE 5
                C[(size_t)n*Dsz*Rsz + (size_t)m*Rsz + jc]=v;
            }
        }
    }
}

// ---------------- embedding gather: X[t*8+b][d] = emb[x[b][t]][d] ------------
__global__ void __launch_bounds__(256) embed_k(const int* __restrict__ x,
                                               const float* __restrict__ emb)
{
    int idx = blockIdx.x*256 + threadIdx.x;      // < 2048*512
    int m = idx>>9, d = idx&511;
    int t = m>>3, b = m&7;
    g_X[idx] = emb[(size_t)x[b*Ssz+t]*Dsz + d];
}

// ---------------- combined k/v biases: ck = Wk@b_np[n] + bk ------------------
__global__ void __launch_bounds__(256) ckcv_k(const float* __restrict__ in_w,
                                              const float* __restrict__ in_b,
                                              const float* __restrict__ b_np)
{
    int idx = blockIdx.x*256 + threadIdx.x;      // < 16*512
    int n = idx>>9, dc = idx&511;
    const float* Wk = in_w + Dsz*Dsz;
    const float* Wv = in_w + 2*Dsz*Dsz;
    const float* bn = b_np + n*Dsz;
    float sk = in_b[Dsz+dc], sv = in_b[2*Dsz+dc];
    for (int j=0;j<Dsz;j++){
        float bj = bn[j];
        sk += Wk[(size_t)dc*Dsz+j]*bj;
        sv += Wv[(size_t)dc*Dsz+j]*bj;
    }
    g_ck[idx]=sk; g_cv[idx]=sv;
}

// ---------------- one LSTM timestep (the sequential critical path) ----------
__global__ void __launch_bounds__(256) lstm_step(
    const float* __restrict__ Whh, const float* __restrict__ hprev,
    const float* __restrict__ cprev, float* __restrict__ cnew,
    float* __restrict__ hout, const float* __restrict__ Gt)
{
    __shared__ float hs[512][8];     // h_prev[n], [r][b]
    __shared__ float gsm[256][9];    // gates, padded
    int tid = threadIdx.x;
    int chunk = blockIdx.x, n = blockIdx.y;

    for (int idx=tid; idx<4096; idx+=256){
        int b = idx>>9, r = idx&511;
        hs[r][b] = hprev[(size_t)(n*8+b)*Rsz + r];
    }
    __syncthreads();

    int gate = tid>>6, rl = tid&63;
    int g = gate*Rsz + chunk*64 + rl;
    const float* W = Whh + (size_t)(n*G4+g)*Rsz;
    float acc[8] = {};
    #pragma unroll 8
    for (int r=0;r<Rsz;r+=4){
        float4 w4 = *(const float4*)(W + r);
        #pragma unroll
        for (int c=0;c<4;c++){
            float wv = (&w4.x)[c];
            float4 h0 = *(const float4*)&hs[r+c][0];
            float4 h1 = *(const float4*)&hs[r+c][4];
            acc[0]+=wv*h0.x; acc[1]+=wv*h0.y; acc[2]+=wv*h0.z; acc[3]+=wv*h0.w;
            acc[4]+=wv*h1.x; acc[5]+=wv*h1.y; acc[6]+=wv*h1.z; acc[7]+=wv*h1.w;
        }
    }
    #pragma unroll
    for (int b=0;b<8;b++)
        gsm[tid][b] = acc[b] + Gt[(size_t)(n*8+b)*G4 + g];
    __syncthreads();

    for (int idx=tid; idx<512; idx+=256){
        int rl2 = idx>>3, b = idx&7;
        float iv = gsm[rl2      ][b];
        float fv = gsm[ 64+rl2  ][b];
        float gv = gsm[128+rl2  ][b];
        float ov = gsm[192+rl2  ][b];
        size_t off = (size_t)(n*8+b)*Rsz + chunk*64 + rl2;
        float cp = cprev[off];
        float cn = sigm(fv)*cp + sigm(iv)*tanhf(gv);
        cnew[off] = cn;
        hout[off] = sigm(ov)*tanhf(cn);
    }
}

// ---------------- attention per token: scores->softmax->att -----------------
__global__ void __launch_bounds__(256) attn_k()
{
    int m = blockIdx.x, tid = threadIdx.x;
    __shared__ float sq[512];
    __shared__ float sc[8][16];
    __shared__ float sw[8][16];
    sq[tid]     = g_q[(size_t)m*Dsz + tid];
    sq[tid+256] = g_q[(size_t)m*Dsz + tid + 256];
    __syncthreads();
    if (tid < 128){
        int h = tid>>4, nn = tid&15;
        const float* kp = g_k + (size_t)(m*Nly+nn)*Dsz + h*64;
        float s = 0.f;
        #pragma unroll 8
        for (int e=0;e<64;e++) s += sq[h*64+e]*kp[e];
        sc[h][nn] = s*0.125f;   // 1/sqrt(64)
    }
    __syncthreads();
    if (tid < 8){
        float mx = -1e30f;
        for (int nn=0;nn<16;nn++) mx = fmaxf(mx, sc[tid][nn]);
        float e[16], sum = 0.f;
        for (int nn=0;nn<16;nn++){ e[nn]=expf(sc[tid][nn]-mx); sum+=e[nn]; }
        float inv = 1.f/sum;
        for (int nn=0;nn<16;nn++) sw[tid][nn]=e[nn]*inv;
    }
    __syncthreads();
    for (int idx=tid; idx<512; idx+=256){
        int h = idx>>6;
        float s = 0.f;
        #pragma unroll
        for (int nn=0;nn<16;nn++)
            s += sw[h][nn]*g_v[(size_t)(m*Nly+nn)*Dsz + idx];
        g_att[(size_t)m*Dsz + idx] = s;
    }
}

// ---------------- layernorm (in-place on g_mix) ------------------------------
// FIXED: cross-warp totals broadcast through shared memory (previous version
// only produced the correct total inside warp 0 -> mu=0 for 7/8 of each row).
__global__ void __launch_bounds__(256) ln_k(const float* __restrict__ gam,
                                            const float* __restrict__ bet)
{
    int m = blockIdx.x, tid = threadIdx.x;
    __shared__ float sh[8];
    __shared__ float sh2[8];
    float* row = g_mix + (size_t)m*Dsz;
    float v0 = row[tid], v1 = row[tid+256];
    int lane = tid&31, w = tid>>5;

    // mean
    float s = v0+v1;
    #pragma unroll
    for (int o=16;o>0;o>>=1) s += __shfl_xor_sync(0xffffffffu, s, o);
    if (lane==0) sh[w]=s;
    __syncthreads();
    float tot = sh[0]+sh[1]+sh[2]+sh[3]+sh[4]+sh[5]+sh[6]+sh[7];
    float mu = tot*(1.f/512.f);

    // variance
    float d0=v0-mu, d1=v1-mu;
    float s2 = d0*d0+d1*d1;
    #pragma unroll
    for (int o=16;o>0;o>>=1) s2 += __shfl_xor_sync(0xffffffffu, s2, o);
    if (lane==0) sh2[w]=s2;
    __syncthreads();
    float tot2 = sh2[0]+sh2[1]+sh2[2]+sh2[3]+sh2[4]+sh2[5]+sh2[6]+sh2[7];
    float inv = rsqrtf(tot2*(1.f/512.f) + 1e-5f);

    row[tid]     = d0*inv*gam[tid]     + bet[tid];
    row[tid+256] = d1*inv*gam[tid+256] + bet[tid+256];
}

// ---------------- final state copy ------------------------------------------
__global__ void __launch_bounds__(256) copyhc_k(const float* __restrict__ hf,
                                                const float* __restrict__ cf,
                                                float* __restrict__ out)
{
    int idx = blockIdx.x*256 + threadIdx.x;      // < 65536
    const size_t L = (size_t)Bsz*Ssz*Vsz;
    out[L + idx]          = hf[idx];
    out[L + NBR + idx]    = cf[idx];
}

// =============================================================================
extern "C" void kernel_launch(void* const* d_in, const int* in_sizes, int n_in,
                              void* d_out, int out_size)
{
    const int*   x      = (const int*)  d_in[0];
    const float* h0     = (const float*)d_in[1];
    const float* c0     = (const float*)d_in[2];
    const float* emb    = (const float*)d_in[3];
    const float* W_ih   = (const float*)d_in[4];
    const float* b_ih   = (const float*)d_in[5];
    const float* W_hh   = (const float*)d_in[6];
    const float* b_hh   = (const float*)d_in[7];
    const float* W_np   = (const float*)d_in[8];
    const float* b_np   = (const float*)d_in[9];
    const float* in_w   = (const float*)d_in[10];
    const float* in_b   = (const float*)d_in[11];
    const float* op_w   = (const float*)d_in[12];
    const float* op_b   = (const float*)d_in[13];
    const float* ln_g   = (const float*)d_in[14];
    const float* ln_b   = (const float*)d_in[15];
    const float* head_w = (const float*)d_in[16];
    const float* head_b = (const float*)d_in[17];
    float* out = (float*)d_out;

    float *pX,*pGih,*pHall,*pC,*pQ,*pWnk,*pWnv,*pCk,*pCv,*pK,*pV,*pAtt,*pMix;
    cudaGetSymbolAddress((void**)&pX,   g_X);
    cudaGetSymbolAddress((void**)&pGih, g_Gih);
    cudaGetSymbolAddress((void**)&pHall,g_hall);
    cudaGetSymbolAddress((void**)&pC,   g_cbuf);
    cudaGetSymbolAddress((void**)&pQ,   g_q);
    cudaGetSymbolAddress((void**)&pWnk, g_Wnk);
    cudaGetSymbolAddress((void**)&pWnv, g_Wnv);
    cudaGetSymbolAddress((void**)&pCk,  g_ck);
    cudaGetSymbolAddress((void**)&pCv,  g_cv);
    cudaGetSymbolAddress((void**)&pK,   g_k);
    cudaGetSymbolAddress((void**)&pV,   g_v);
    cudaGetSymbolAddress((void**)&pAtt, g_att);
    cudaGetSymbolAddress((void**)&pMix, g_mix);

    // Phase 0: embedding
    embed_k<<<(Mtok*Dsz)/256, 256>>>(x, emb);

    // Phase 1 (parallel pre-scan): gates_ih, q, folded k/v weight products
    gemm_k<1><<<dim3(32,32,16),256>>>(pX, W_ih, pGih, b_ih, b_hh, nullptr);
    gemm_k<0><<<dim3(8,32),    256>>>(pX, in_w, pQ,   in_b, nullptr, nullptr);
    gemm_k<5><<<dim3(8,8,16),  256>>>(in_w +   Dsz*Dsz, W_np, pWnk, nullptr, nullptr, nullptr);
    gemm_k<5><<<dim3(8,8,16),  256>>>(in_w + 2*Dsz*Dsz, W_np, pWnv, nullptr, nullptr, nullptr);
    ckcv_k<<<(Nly*Dsz)/256, 256>>>(in_w, in_b, b_np);

    // Phase 2 (sequential recurrence)
    for (int t=0; t<Ssz; t++){
        const float* hp = t ? pHall + (size_t)(t-1)*NBR : h0;
        const float* cp = t ? pC + (size_t)((t-1)&1)*NBR : c0;
        float* cn = pC + (size_t)(t&1)*NBR;
        lstm_step<<<dim3(8,16),256>>>(W_hh, hp, cp, cn,
                                      pHall + (size_t)t*NBR,
                                      pGih  + (size_t)t*Nly*Bsz*G4);
    }

    // Phase 3 (parallel post-scan): k, v, attention, output proj+residual, LN, head
    gemm_k<3><<<dim3(8,32,16),256>>>(pHall, pWnk, pK, pCk, nullptr, nullptr);
    gemm_k<3><<<dim3(8,32,16),256>>>(pHall, pWnv, pV, pCv, nullptr, nullptr);
    attn_k<<<Mtok,256>>>();
    gemm_k<4><<<dim3(8,32),256>>>(pAtt, op_w, pMix, op_b, nullptr, pX);
    ln_k<<<Mtok,256>>>(ln_g, ln_b);
    gemm_k<2><<<dim3(500,32),256>>>(pMix, head_w, out, head_b, nullptr, nullptr);

    // hf / cf
    copyhc_k<<<NBR/256,256>>>(pHall + (size_t)(Ssz-1)*NBR, pC + (size_t)((Ssz-1)&1)*NBR, out);
}

// round 4
// speedup vs baseline: 1.1708x; 1.1708x over previous
#include <cuda_runtime.h>
#include <math.h>
#include <stdint.h>

// Problem dims
#define Bsz 8
#define Ssz 256
#define Vsz 32000
#define Dsz 512
#define Nly 16
#define Rsz 512
#define G4  2048            // 4*R
#define Mtok (Bsz*Ssz)      // 2048 tokens
#define NBR (Nly*Bsz*Rsz)   // 65536

// ---------------- scratch (static device globals; no runtime alloc) ----------
__device__ float g_X   [Mtok*Dsz];                       // X[t*8+b][d]
__device__ float g_Gih [(size_t)Ssz*Nly*Bsz*G4];         // [t][n][b][g] (bias folded in)
__device__ float g_hall[(size_t)Ssz*Nly*Bsz*Rsz];        // h_new per step
__device__ float g_cbuf[2*NBR];                          // c ping-pong
__device__ float g_q   [Mtok*Dsz];
__device__ float g_Wnk [Nly*Dsz*Rsz];                    // Wk @ W_np[n]
__device__ float g_Wnv [Nly*Dsz*Rsz];
__device__ float g_ck  [Nly*Dsz];
__device__ float g_cv  [Nly*Dsz];
__device__ float g_k   [(size_t)Mtok*Nly*Dsz];           // [m][n][d]
__device__ float g_v   [(size_t)Mtok*Nly*Dsz];
__device__ float g_att [Mtok*Dsz];
__device__ float g_mix [Mtok*Dsz];

__device__ __forceinline__ float sigm(float x){ return 1.f/(1.f+expf(-x)); }

// =============================================================================
// 128x128 tile, 8x8 microtile, KB=8 double-buffered fp32 GEMM, C = A * B^T
// MODE 0: q     = X @ Wq^T + bq                 C[m*512+j]
// MODE 1: Gih   = X @ W_ih[n]^T + b_ih + b_hh   C[(t*128+n*8+b)*2048+j]
// MODE 2: logit = mix @ head_w^T + head_b       C[(b*256+t)*32000+j]
// MODE 3: k/v   = hall @ Wnk[n]^T + ck[n]       A row=(t*128+n*8+b), C[(m*16+n)*512+j]
// MODE 4: y     = att @ op_w^T + op_b + X       C[m*512+j]
// MODE 5: Wnk[n]= Wk @ W_np[n] (B is K-major)   C[n*D*R + m*512+j]
// =============================================================================
template<int MODE>
__global__ void __launch_bounds__(256, 2) gemm_k(
    const float* __restrict__ A, const float* __restrict__ Bw,
    float* __restrict__ C, const float* __restrict__ bias,
    const float* __restrict__ bias2, const float* __restrict__ resid)
{
    const int K = 512;
    __shared__ float As[2][8][132];   // pad 132 -> conflict-free scatter stores
    __shared__ float Bs[2][8][132];
    int tid = threadIdx.x;
    int bn = blockIdx.x, bm = blockIdx.y, n = blockIdx.z;

    const float* Bp = Bw;
    if (MODE==1) Bp += (size_t)n*G4 *K;
    if (MODE==3) Bp += (size_t)n*Dsz*K;
    if (MODE==5) Bp += (size_t)n*Dsz*Rsz;

    // ---- global load mapping ----
    int lRow = tid>>1;              // 0..127
    int lK   = (tid&1)<<2;          // 0 or 4
    int am = bm*128 + lRow;
    int ag = am;
    if (MODE==3){ int t=am>>3, b=am&7; ag = t*128 + n*8 + b; }
    const float* Aptr = A + (size_t)ag*K + lK;

    const float* Bptr;
    int b_k=0, b_j=0;
    if (MODE==5){
        b_k = tid>>5;               // 0..7
        b_j = (tid&31)<<2;          // 0..124
        Bptr = Bp + (size_t)b_k*Rsz + bn*128 + b_j;
    } else {
        Bptr = Bp + (size_t)(bn*128 + lRow)*K + lK;
    }

    int ty = tid>>4, tx = tid&15;

    float acc[8][8] = {};
    float4 aReg, bReg;

    // prologue: stage 0
    aReg = *(const float4*)(Aptr);
    bReg = *(const float4*)(Bptr);
    As[0][lK+0][lRow]=aReg.x; As[0][lK+1][lRow]=aReg.y;
    As[0][lK+2][lRow]=aReg.z; As[0][lK+3][lRow]=aReg.w;
    if (MODE==5){
        *(float4*)&Bs[0][b_k][b_j] = bReg;
    } else {
        Bs[0][lK+0][lRow]=bReg.x; Bs[0][lK+1][lRow]=bReg.y;
        Bs[0][lK+2][lRow]=bReg.z; Bs[0][lK+3][lRow]=bReg.w;
    }
    __syncthreads();

    int buf = 0;
    for (int kb=8; kb<=K; kb+=8){
        bool more = (kb < K);
        if (more){
            aReg = *(const float4*)(Aptr + kb);
            bReg = (MODE==5) ? *(const float4*)(Bptr + (size_t)kb*Rsz)
                             : *(const float4*)(Bptr + kb);
        }
        #pragma unroll
        for (int k=0;k<8;k++){
            float4 a0 = *(const float4*)&As[buf][k][ty<<2];
            float4 a1 = *(const float4*)&As[buf][k][(ty<<2)+64];
            float4 b0 = *(const float4*)&Bs[buf][k][tx<<2];
            float4 b1 = *(const float4*)&Bs[buf][k][(tx<<2)+64];
            float a[8]={a0.x,a0.y,a0.z,a0.w,a1.x,a1.y,a1.z,a1.w};
            float b[8]={b0.x,b0.y,b0.z,b0.w,b1.x,b1.y,b1.z,b1.w};
            #pragma unroll
            for(int i=0;i<8;i++)
                #pragma unroll
                for(int j=0;j<8;j++) acc[i][j] += a[i]*b[j];
        }
        if (more){
            int nb = buf^1;
            As[nb][lK+0][lRow]=aReg.x; As[nb][lK+1][lRow]=aReg.y;
            As[nb][lK+2][lRow]=aReg.z; As[nb][lK+3][lRow]=aReg.w;
            if (MODE==5){
                *(float4*)&Bs[nb][b_k][b_j] = bReg;
            } else {
                Bs[nb][lK+0][lRow]=bReg.x; Bs[nb][lK+1][lRow]=bReg.y;
                Bs[nb][lK+2][lRow]=bReg.z; Bs[nb][lK+3][lRow]=bReg.w;
            }
            __syncthreads();
            buf = nb;
        }
    }

    // ---- epilogue ----
    #pragma unroll
    for(int i=0;i<8;i++){
        int m = bm*128 + (ty<<2) + (i&3) + ((i>>2)<<6);
        #pragma unroll
        for(int j=0;j<8;j++){
            int jc = bn*128 + (tx<<2) + (j&3) + ((j>>2)<<6);
            float v = acc[i][j];
            if (MODE==0){ v += bias[jc]; C[(size_t)m*Dsz+jc]=v; }
            else if (MODE==1){
                v += bias[n*G4+jc] + bias2[n*G4+jc];
                int t=m>>3, b=m&7;
                C[(size_t)(t*128+n*8+b)*G4 + jc]=v;
            }
            else if (MODE==2){
                v += bias[jc];
                int t=m>>3, b=m&7;
                C[(size_t)(b*Ssz+t)*Vsz + jc]=v;
            }
            else if (MODE==3){
                v += bias[n*Dsz+jc];
                C[(size_t)(m*Nly+n)*Dsz + jc]=v;
            }
            else if (MODE==4){
                v += bias[jc] + resid[(size_t)m*Dsz+jc];
                C[(size_t)m*Dsz+jc]=v;
            }
            else { // MODE 5
                C[(size_t)n*Dsz*Rsz + (size_t)m*Rsz + jc]=v;
            }
        }
    }
}

// ---------------- embedding gather: X[t*8+b][d] = emb[x[b][t]][d] ------------
__global__ void __launch_bounds__(256) embed_k(const int* __restrict__ x,
                                               const float* __restrict__ emb)
{
    int idx = blockIdx.x*256 + threadIdx.x;      // < 2048*512
    int m = idx>>9, d = idx&511;
    int t = m>>3, b = m&7;
    g_X[idx] = emb[(size_t)x[b*Ssz+t]*Dsz + d];
}

// ---------------- combined k/v biases: ck = Wk@b_np[n] + bk ------------------
__global__ void __launch_bounds__(256) ckcv_k(const float* __restrict__ in_w,
                                              const float* __restrict__ in_b,
                                              const float* __restrict__ b_np)
{
    int idx = blockIdx.x*256 + threadIdx.x;      // < 16*512
    int n = idx>>9, dc = idx&511;
    const float* Wk = in_w + Dsz*Dsz;
    const float* Wv = in_w + 2*Dsz*Dsz;
    const float* bn = b_np + n*Dsz;
    float sk = in_b[Dsz+dc], sv = in_b[2*Dsz+dc];
    for (int j=0;j<Dsz;j++){
        float bj = bn[j];
        sk += Wk[(size_t)dc*Dsz+j]*bj;
        sv += Wv[(size_t)dc*Dsz+j]*bj;
    }
    g_ck[idx]=sk; g_cv[idx]=sv;
}

// ---------------- one LSTM timestep (the sequential critical path) ----------
__global__ void __launch_bounds__(256) lstm_step(
    const float* __restrict__ Whh, const float* __restrict__ hprev,
    const float* __restrict__ cprev, float* __restrict__ cnew,
    float* __restrict__ hout, const float* __restrict__ Gt)
{
    __shared__ float hs[512][8];     // h_prev[n], [r][b]
    __shared__ float gsm[256][9];    // gates, padded
    int tid = threadIdx.x;
    int chunk = blockIdx.x, n = blockIdx.y;

    for (int idx=tid; idx<4096; idx+=256){
        int b = idx>>9, r = idx&511;
        hs[r][b] = hprev[(size_t)(n*8+b)*Rsz + r];
    }
    __syncthreads();

    int gate = tid>>6, rl = tid&63;
    int g = gate*Rsz + chunk*64 + rl;
    const float* W = Whh + (size_t)(n*G4+g)*Rsz;
    float acc[8] = {};
    #pragma unroll 8
    for (int r=0;r<Rsz;r+=4){
        float4 w4 = *(const float4*)(W + r);
        #pragma unroll
        for (int c=0;c<4;c++){
            float wv = (&w4.x)[c];
            float4 h0 = *(const float4*)&hs[r+c][0];
            float4 h1 = *(const float4*)&hs[r+c][4];
            acc[0]+=wv*h0.x; acc[1]+=wv*h0.y; acc[2]+=wv*h0.z; acc[3]+=wv*h0.w;
            acc[4]+=wv*h1.x; acc[5]+=wv*h1.y; acc[6]+=wv*h1.z; acc[7]+=wv*h1.w;
        }
    }
    #pragma unroll
    for (int b=0;b<8;b++)
        gsm[tid][b] = acc[b] + Gt[(size_t)(n*8+b)*G4 + g];
    __syncthreads();

    for (int idx=tid; idx<512; idx+=256){
        int rl2 = idx>>3, b = idx&7;
        float iv = gsm[rl2      ][b];
        float fv = gsm[ 64+rl2  ][b];
        float gv = gsm[128+rl2  ][b];
        float ov = gsm[192+rl2  ][b];
        size_t off = (size_t)(n*8+b)*Rsz + chunk*64 + rl2;
        float cp = cprev[off];
        float cn = sigm(fv)*cp + sigm(iv)*tanhf(gv);
        cnew[off] = cn;
        hout[off] = sigm(ov)*tanhf(cn);
    }
}

// ---------------- attention per token: scores->softmax->att -----------------
__global__ void __launch_bounds__(256) attn_k()
{
    int m = blockIdx.x, tid = threadIdx.x;
    __shared__ float sq[512];
    __shared__ float sc[8][16];
    __shared__ float sw[8][16];
    sq[tid]     = g_q[(size_t)m*Dsz + tid];
    sq[tid+256] = g_q[(size_t)m*Dsz + tid + 256];
    __syncthreads();
    if (tid < 128){
        int h = tid>>4, nn = tid&15;
        const float* kp = g_k + (size_t)(m*Nly+nn)*Dsz + h*64;
        float s = 0.f;
        #pragma unroll 8
        for (int e=0;e<64;e++) s += sq[h*64+e]*kp[e];
        sc[h][nn] = s*0.125f;   // 1/sqrt(64)
    }
    __syncthreads();
    if (tid < 8){
        float mx = -1e30f;
        for (int nn=0;nn<16;nn++) mx = fmaxf(mx, sc[tid][nn]);
        float e[16], sum = 0.f;
        for (int nn=0;nn<16;nn++){ e[nn]=expf(sc[tid][nn]-mx); sum+=e[nn]; }
        float inv = 1.f/sum;
        for (int nn=0;nn<16;nn++) sw[tid][nn]=e[nn]*inv;
    }
    __syncthreads();
    for (int idx=tid; idx<512; idx+=256){
        int h = idx>>6;
        float s = 0.f;
        #pragma unroll
        for (int nn=0;nn<16;nn++)
            s += sw[h][nn]*g_v[(size_t)(m*Nly+nn)*Dsz + idx];
        g_att[(size_t)m*Dsz + idx] = s;
    }
}

// ---------------- layernorm (in-place on g_mix) ------------------------------
__global__ void __launch_bounds__(256) ln_k(const float* __restrict__ gam,
                                            const float* __restrict__ bet)
{
    int m = blockIdx.x, tid = threadIdx.x;
    __shared__ float sh[8];
    __shared__ float sh2[8];
    float* row = g_mix + (size_t)m*Dsz;
    float v0 = row[tid], v1 = row[tid+256];
    int lane = tid&31, w = tid>>5;

    float s = v0+v1;
    #pragma unroll
    for (int o=16;o>0;o>>=1) s += __shfl_xor_sync(0xffffffffu, s, o);
    if (lane==0) sh[w]=s;
    __syncthreads();
    float tot = sh[0]+sh[1]+sh[2]+sh[3]+sh[4]+sh[5]+sh[6]+sh[7];
    float mu = tot*(1.f/512.f);

    float d0=v0-mu, d1=v1-mu;
    float s2 = d0*d0+d1*d1;
    #pragma unroll
    for (int o=16;o>0;o>>=1) s2 += __shfl_xor_sync(0xffffffffu, s2, o);
    if (lane==0) sh2[w]=s2;
    __syncthreads();
    float tot2 = sh2[0]+sh2[1]+sh2[2]+sh2[3]+sh2[4]+sh2[5]+sh2[6]+sh2[7];
    float inv = rsqrtf(tot2*(1.f/512.f) + 1e-5f);

    row[tid]     = d0*inv*gam[tid]     + bet[tid];
    row[tid+256] = d1*inv*gam[tid+256] + bet[tid+256];
}

// ---------------- final state copy ------------------------------------------
__global__ void __launch_bounds__(256) copyhc_k(const float* __restrict__ hf,
                                                const float* __restrict__ cf,
                                                float* __restrict__ out)
{
    int idx = blockIdx.x*256 + threadIdx.x;      // < 65536
    const size_t L = (size_t)Bsz*Ssz*Vsz;
    out[L + idx]          = hf[idx];
    out[L + NBR + idx]    = cf[idx];
}

// =============================================================================
extern "C" void kernel_launch(void* const* d_in, const int* in_sizes, int n_in,
                              void* d_out, int out_size)
{
    const int*   x      = (const int*)  d_in[0];
    const float* h0     = (const float*)d_in[1];
    const float* c0     = (const float*)d_in[2];
    const float* emb    = (const float*)d_in[3];
    const float* W_ih   = (const float*)d_in[4];
    const float* b_ih   = (const float*)d_in[5];
    const float* W_hh   = (const float*)d_in[6];
    const float* b_hh   = (const float*)d_in[7];
    const float* W_np   = (const float*)d_in[8];
    const float* b_np   = (const float*)d_in[9];
    const float* in_w   = (const float*)d_in[10];
    const float* in_b   = (const float*)d_in[11];
    const float* op_w   = (const float*)d_in[12];
    const float* op_b   = (const float*)d_in[13];
    const float* ln_g   = (const float*)d_in[14];
    const float* ln_b   = (const float*)d_in[15];
    const float* head_w = (const float*)d_in[16];
    const float* head_b = (const float*)d_in[17];
    float* out = (float*)d_out;

    float *pX,*pGih,*pHall,*pC,*pQ,*pWnk,*pWnv,*pCk,*pCv,*pK,*pV,*pAtt,*pMix;
    cudaGetSymbolAddress((void**)&pX,   g_X);
    cudaGetSymbolAddress((void**)&pGih, g_Gih);
    cudaGetSymbolAddress((void**)&pHall,g_hall);
    cudaGetSymbolAddress((void**)&pC,   g_cbuf);
    cudaGetSymbolAddress((void**)&pQ,   g_q);
    cudaGetSymbolAddress((void**)&pWnk, g_Wnk);
    cudaGetSymbolAddress((void**)&pWnv, g_Wnv);
    cudaGetSymbolAddress((void**)&pCk,  g_ck);
    cudaGetSymbolAddress((void**)&pCv,  g_cv);
    cudaGetSymbolAddress((void**)&pK,   g_k);
    cudaGetSymbolAddress((void**)&pV,   g_v);
    cudaGetSymbolAddress((void**)&pAtt, g_att);
    cudaGetSymbolAddress((void**)&pMix, g_mix);

    // Phase 0: embedding
    embed_k<<<(Mtok*Dsz)/256, 256>>>(x, emb);

    // Phase 1 (parallel pre-scan): gates_ih, q, folded k/v weight products
    gemm_k<1><<<dim3(16,16,16),256>>>(pX, W_ih, pGih, b_ih, b_hh, nullptr);
    gemm_k<0><<<dim3(4,16),    256>>>(pX, in_w, pQ,   in_b, nullptr, nullptr);
    gemm_k<5><<<dim3(4,4,16),  256>>>(in_w +   Dsz*Dsz, W_np, pWnk, nullptr, nullptr, nullptr);
    gemm_k<5><<<dim3(4,4,16),  256>>>(in_w + 2*Dsz*Dsz, W_np, pWnv, nullptr, nullptr, nullptr);
    ckcv_k<<<(Nly*Dsz)/256, 256>>>(in_w, in_b, b_np);

    // Phase 2 (sequential recurrence)
    for (int t=0; t<Ssz; t++){
        const float* hp = t ? pHall + (size_t)(t-1)*NBR : h0;
        const float* cp = t ? pC + (size_t)((t-1)&1)*NBR : c0;
        float* cn = pC + (size_t)(t&1)*NBR;
        lstm_step<<<dim3(8,16),256>>>(W_hh, hp, cp, cn,
                                      pHall + (size_t)t*NBR,
                                      pGih  + (size_t)t*Nly*Bsz*G4);
    }

    // Phase 3 (parallel post-scan): k, v, attention, output proj+residual, LN, head
    gemm_k<3><<<dim3(4,16,16),256>>>(pHall, pWnk, pK, pCk, nullptr, nullptr);
    gemm_k<3><<<dim3(4,16,16),256>>>(pHall, pWnv, pV, pCv, nullptr, nullptr);
    attn_k<<<Mtok,256>>>();
    gemm_k<4><<<dim3(4,16),256>>>(pAtt, op_w, pMix, op_b, nullptr, pX);
    ln_k<<<Mtok,256>>>(ln_g, ln_b);
    gemm_k<2><<<dim3(250,16),256>>>(pMix, head_w, out, head_b, nullptr, nullptr);

    // hf / cf
    copyhc_k<<<NBR/256,256>>>(pHall + (size_t)(Ssz-1)*NBR, pC + (size_t)((Ssz-1)&1)*NBR, out);
}

// round 8
// speedup vs baseline: 1.3841x; 1.1822x over previous
#include <cuda_runtime.h>
#include <cuda_bf16.h>
#include <math.h>
#include <stdint.h>

// Problem dims
#define Bsz 8
#define Ssz 256
#define Vsz 32000
#define Dsz 512
#define Nly 16
#define Rsz 512
#define G4  2048            // 4*R
#define Mtok (Bsz*Ssz)      // 2048 tokens
#define NBR (Nly*Bsz*Rsz)   // 65536

// ---------------- scratch (static device globals; no runtime alloc) ----------
__device__ float g_X   [Mtok*Dsz];
__device__ float g_Gih [(size_t)Ssz*Nly*Bsz*G4];         // [t][n][b][g]
__device__ float g_hall[(size_t)Ssz*Nly*Bsz*Rsz];
__device__ float g_cf  [NBR];
__device__ float g_q   [Mtok*Dsz];
__device__ float g_Wnk [Nly*Dsz*Rsz];
__device__ float g_Wnv [Nly*Dsz*Rsz];
__device__ float g_ck  [Nly*Dsz];
__device__ float g_cv  [Nly*Dsz];
__device__ float g_k   [(size_t)Mtok*Nly*Dsz];
__device__ float g_v   [(size_t)Mtok*Nly*Dsz];
__device__ float g_att [Mtok*Dsz];
__device__ float g_mix [Mtok*Dsz];
__device__ unsigned g_bar;

// bf16 split buffers (hi + lo)
__device__ __align__(16) __nv_bfloat16 bWih_h [(size_t)Nly*G4*Dsz];
__device__ __align__(16) __nv_bfloat16 bWih_l [(size_t)Nly*G4*Dsz];
__device__ __align__(16) __nv_bfloat16 bHead_h[(size_t)Vsz*Dsz];
__device__ __align__(16) __nv_bfloat16 bHead_l[(size_t)Vsz*Dsz];
__device__ __align__(16) __nv_bfloat16 bX_h   [Mtok*Dsz];
__device__ __align__(16) __nv_bfloat16 bX_l   [Mtok*Dsz];
__device__ __align__(16) __nv_bfloat16 bHall_h[(size_t)Ssz*NBR];
__device__ __align__(16) __nv_bfloat16 bHall_l[(size_t)Ssz*NBR];
__device__ __align__(16) __nv_bfloat16 bWnk_h [Nly*Dsz*Rsz];
__device__ __align__(16) __nv_bfloat16 bWnk_l [Nly*Dsz*Rsz];
__device__ __align__(16) __nv_bfloat16 bWnv_h [Nly*Dsz*Rsz];
__device__ __align__(16) __nv_bfloat16 bWnv_l [Nly*Dsz*Rsz];
__device__ __align__(16) __nv_bfloat16 bMix_h [Mtok*Dsz];
__device__ __align__(16) __nv_bfloat16 bMix_l [Mtok*Dsz];

__device__ __forceinline__ float sigm(float x){ return 1.f/(1.f+expf(-x)); }

// ======================= PTX helpers (compute_103-safe) ======================
__device__ __forceinline__ void cp16(uint32_t sdst, const void* gsrc){
    asm volatile("cp.async.cg.shared.global [%0], [%1], 16;" :: "r"(sdst), "l"(gsrc));
}
__device__ __forceinline__ void cp_commit(){
    asm volatile("cp.async.commit_group;" ::: "memory");
}
template<int N>
__device__ __forceinline__ void cp_wait(){
    asm volatile("cp.async.wait_group %0;" :: "n"(N) : "memory");
}
__device__ __forceinline__ void ldsm_x4(uint32_t* r, uint32_t addr){
    asm volatile("ldmatrix.sync.aligned.m8n8.x4.shared.b16 {%0,%1,%2,%3}, [%4];"
        : "=r"(r[0]),"=r"(r[1]),"=r"(r[2]),"=r"(r[3]) : "r"(addr));
}
__device__ __forceinline__ void mma16816(float* d, const uint32_t* a, const uint32_t* b){
    asm volatile("mma.sync.aligned.m16n8k16.row.col.f32.bf16.bf16.f32 "
        "{%0,%1,%2,%3}, {%4,%5,%6,%7}, {%8,%9}, {%0,%1,%2,%3};"
        : "+f"(d[0]),"+f"(d[1]),"+f"(d[2]),"+f"(d[3])
        : "r"(a[0]),"r"(a[1]),"r"(a[2]),"r"(a[3]), "r"(b[0]),"r"(b[1]));
}

// ======================= mma.sync bf16-split GEMM ============================
// C(128x128 tile) = A(Mx512) @ B(Nx512)^T in fp32 via bf16 hi/lo (3 products)
// MODE 1: Gih ; MODE 2: head logits ; MODE 3: k/v (A row remap)
#define TG_LD   72                     // padded row (bf16 elts) -> conflict-mild
#define TG_BLK  (128*TG_LD)            // one 128x64 matrix block (padded)
#define TG_SMEM (8*TG_BLK*2)           // 2 stages x {Ah,Al,Bh,Bl} bf16 bytes

template<int MODE>
__global__ void __launch_bounds__(256,1) tgemm_k(
    const __nv_bfloat16* __restrict__ Ah, const __nv_bfloat16* __restrict__ Al,
    const __nv_bfloat16* __restrict__ Bh, const __nv_bfloat16* __restrict__ Bl,
    float* __restrict__ C, const float* __restrict__ bias,
    const float* __restrict__ bias2)
{
    extern __shared__ __align__(16) __nv_bfloat16 smb[];
    uint32_t sbase = (uint32_t)__cvta_generic_to_shared(smb);
    int tid = threadIdx.x, wid = tid>>5, lane = tid&31;
    int wm = wid>>2, wn = wid&3;
    int bn = blockIdx.x, bm = blockIdx.y, nz = blockIdx.z;

    const __nv_bfloat16 *BhP = Bh, *BlP = Bl;
    if (MODE==1){ BhP += (size_t)nz*G4 *512; BlP += (size_t)nz*G4 *512; }
    if (MODE==3){ BhP += (size_t)nz*Dsz*512; BlP += (size_t)nz*Dsz*512; }

    // ---- cp.async load mapping: thread t loads row=t>>1, k-half=(t&1)*32 ----
    int lrow = tid>>1, lk = (tid&1)*32;
    int am = bm*128 + lrow;
    int ag = (MODE==3) ? ((am>>3)*128 + nz*8 + (am&7)) : am;
    const __nv_bfloat16* gAh = Ah  + (size_t)ag*512 + lk;
    const __nv_bfloat16* gAl = Al  + (size_t)ag*512 + lk;
    const __nv_bfloat16* gBh = BhP + (size_t)(bn*128 + lrow)*512 + lk;
    const __nv_bfloat16* gBl = BlP + (size_t)(bn*128 + lrow)*512 + lk;
    uint32_t sRowOff = (uint32_t)(lrow*TG_LD + lk)*2;

    // ---- ldmatrix lane mapping ----
    int aRowL = wm*64 + (lane&15);
    int aColL = (lane>>4)*8;
    int bRowL = wn*32 + ((lane>>4)&1)*8 + (lane&7);
    int bColL = ((lane>>3)&1)*8;

    float acc[4][4][4];
    #pragma unroll
    for (int i=0;i<4;i++){
        #pragma unroll
        for (int j=0;j<4;j++){
            acc[i][j][0]=0.f; acc[i][j][1]=0.f; acc[i][j][2]=0.f; acc[i][j][3]=0.f;
        }
    }

    // stage issue helper (4x16B per matrix block)
    auto issue = [&](int s, int kb){
        uint32_t d0 = sbase + (uint32_t)((s*4+0)*TG_BLK)*2 + sRowOff;
        uint32_t d1 = sbase + (uint32_t)((s*4+1)*TG_BLK)*2 + sRowOff;
        uint32_t d2 = sbase + (uint32_t)((s*4+2)*TG_BLK)*2 + sRowOff;
        uint32_t d3 = sbase + (uint32_t)((s*4+3)*TG_BLK)*2 + sRowOff;
        #pragma unroll
        for (int i=0;i<4;i++){
            cp16(d0 + i*16, gAh + kb + i*8);
            cp16(d1 + i*16, gAl + kb + i*8);
            cp16(d2 + i*16, gBh + kb + i*8);
            cp16(d3 + i*16, gBl + kb + i*8);
        }
        cp_commit();
    };

    issue(0, 0);
    for (int c=0;c<8;c++){
        int s = c&1;
        if (c<7) issue(s^1, (c+1)*64);
        if (c<7) cp_wait<1>(); else cp_wait<0>();
        __syncthreads();

        #pragma unroll
        for (int ks=0; ks<4; ks++){
            int kc = ks*16;
            uint32_t ah[4][4], al[4][4];
            #pragma unroll
            for (int mf=0; mf<4; mf++){
                uint32_t addrh = sbase + (uint32_t)((s*4+0)*TG_BLK + (aRowL+mf*16)*TG_LD + aColL + kc)*2;
                uint32_t addrl = sbase + (uint32_t)((s*4+1)*TG_BLK + (aRowL+mf*16)*TG_LD + aColL + kc)*2;
                ldsm_x4(ah[mf], addrh);
                ldsm_x4(al[mf], addrl);
            }
            uint32_t bh[2][4], bl[2][4];
            #pragma unroll
            for (int nfh=0; nfh<2; nfh++){
                uint32_t addrh = sbase + (uint32_t)((s*4+2)*TG_BLK + (bRowL+nfh*16)*TG_LD + bColL + kc)*2;
                uint32_t addrl = sbase + (uint32_t)((s*4+3)*TG_BLK + (bRowL+nfh*16)*TG_LD + bColL + kc)*2;
                ldsm_x4(bh[nfh], addrh);
                ldsm_x4(bl[nfh], addrl);
            }
            #pragma unroll
            for (int mf=0; mf<4; mf++){
                #pragma unroll
                for (int nf=0; nf<4; nf++){
                    const uint32_t* bhp = &bh[nf>>1][(nf&1)*2];
                    const uint32_t* blp = &bl[nf>>1][(nf&1)*2];
                    mma16816(acc[mf][nf], ah[mf], bhp);
                    mma16816(acc[mf][nf], ah[mf], blp);
                    mma16816(acc[mf][nf], al[mf], bhp);
                }
            }
        }
        __syncthreads();
    }

    // ---- epilogue: d-frag rows lane/4, lane/4+8 ; cols 2*(lane%4)+{0,1} ----
    int rA = lane>>2, cA = (lane&3)*2;
    #pragma unroll
    for (int mf=0; mf<4; mf++){
        #pragma unroll
        for (int nf=0; nf<4; nf++){
            #pragma unroll
            for (int half=0; half<2; half++){
                int m  = bm*128 + wm*64 + mf*16 + rA + half*8;
                int jc = bn*128 + wn*32 + nf*8 + cA;
                float v0 = acc[mf][nf][half*2+0];
                float v1 = acc[mf][nf][half*2+1];
                if (MODE==1){
                    v0 += bias[nz*G4+jc]   + bias2[nz*G4+jc];
                    v1 += bias[nz*G4+jc+1] + bias2[nz*G4+jc+1];
                    int t=m>>3, b=m&7;
                    float2 w = {v0,v1};
                    *(float2*)&C[(size_t)(t*128+nz*8+b)*G4 + jc] = w;
                } else if (MODE==2){
                    v0 += bias[jc]; v1 += bias[jc+1];
                    int t=m>>3, b=m&7;
                    float2 w = {v0,v1};
                    *(float2*)&C[(size_t)(b*Ssz+t)*Vsz + jc] = w;
                } else {
                    v0 += bias[nz*Dsz+jc]; v1 += bias[nz*Dsz+jc+1];
                    float2 w = {v0,v1};
                    *(float2*)&C[(size_t)(m*Nly+nz)*Dsz + jc] = w;
                }
            }
        }
    }
}

// ---------------- fp32 -> bf16 hi/lo split -----------------------------------
__global__ void __launch_bounds__(256) split_k(const float* __restrict__ src,
                                              __nv_bfloat16* __restrict__ hi,
                                              __nv_bfloat16* __restrict__ lo,
                                              int n)
{
    int i = blockIdx.x*256 + threadIdx.x;
    if (i < n){
        float x = src[i];
        __nv_bfloat16 h = __float2bfloat16(x);
        hi[i] = h;
        lo[i] = __float2bfloat16(x - __bfloat162float(h));
    }
}

// ---------------- SIMT 128x128 GEMM (small modes 0,4,5) ----------------------
template<int MODE>
__global__ void __launch_bounds__(256, 2) gemm_k(
    const float* __restrict__ A, const float* __restrict__ Bw,
    float* __restrict__ C, const float* __restrict__ bias,
    const float* __restrict__ resid)
{
    const int K = 512;
    __shared__ float As[2][8][132];
    __shared__ float Bs[2][8][132];
    int tid = threadIdx.x;
    int bn = blockIdx.x, bm = blockIdx.y, n = blockIdx.z;

    const float* Bp = Bw;
    if (MODE==5) Bp += (size_t)n*Dsz*Rsz;

    int lRow = tid>>1, lK = (tid&1)<<2;
    const float* Aptr = A + (size_t)(bm*128+lRow)*K + lK;
    const float* Bptr;
    int b_k=0, b_j=0;
    if (MODE==5){
        b_k = tid>>5; b_j = (tid&31)<<2;
        Bptr = Bp + (size_t)b_k*Rsz + bn*128 + b_j;
    } else {
        Bptr = Bp + (size_t)(bn*128 + lRow)*K + lK;
    }
    int ty = tid>>4, tx = tid&15;
    float acc[8][8] = {};
    float4 aReg, bReg;

    aReg = *(const float4*)(Aptr);
    bReg = *(const float4*)(Bptr);
    As[0][lK+0][lRow]=aReg.x; As[0][lK+1][lRow]=aReg.y;
    As[0][lK+2][lRow]=aReg.z; As[0][lK+3][lRow]=aReg.w;
    if (MODE==5){ *(float4*)&Bs[0][b_k][b_j] = bReg; }
    else {
        Bs[0][lK+0][lRow]=bReg.x; Bs[0][lK+1][lRow]=bReg.y;
        Bs[0][lK+2][lRow]=bReg.z; Bs[0][lK+3][lRow]=bReg.w;
    }
    __syncthreads();

    int buf = 0;
    for (int kb=8; kb<=K; kb+=8){
        bool more = (kb < K);
        if (more){
            aReg = *(const float4*)(Aptr + kb);
            bReg = (MODE==5) ? *(const float4*)(Bptr + (size_t)kb*Rsz)
                             : *(const float4*)(Bptr + kb);
        }
        #pragma unroll
        for (int k=0;k<8;k++){
            float4 a0 = *(const float4*)&As[buf][k][ty<<2];
            float4 a1 = *(const float4*)&As[buf][k][(ty<<2)+64];
            float4 b0 = *(const float4*)&Bs[buf][k][tx<<2];
            float4 b1 = *(const float4*)&Bs[buf][k][(tx<<2)+64];
            float a[8]={a0.x,a0.y,a0.z,a0.w,a1.x,a1.y,a1.z,a1.w};
            float b[8]={b0.x,b0.y,b0.z,b0.w,b1.x,b1.y,b1.z,b1.w};
            #pragma unroll
            for(int i=0;i<8;i++)
                #pragma unroll
                for(int j=0;j<8;j++) acc[i][j] += a[i]*b[j];
        }
        if (more){
            int nb = buf^1;
            As[nb][lK+0][lRow]=aReg.x; As[nb][lK+1][lRow]=aReg.y;
            As[nb][lK+2][lRow]=aReg.z; As[nb][lK+3][lRow]=aReg.w;
            if (MODE==5){ *(float4*)&Bs[nb][b_k][b_j] = bReg; }
            else {
                Bs[nb][lK+0][lRow]=bReg.x; Bs[nb][lK+1][lRow]=bReg.y;
                Bs[nb][lK+2][lRow]=bReg.z; Bs[nb][lK+3][lRow]=bReg.w;
            }
            __syncthreads();
            buf = nb;
        }
    }

    #pragma unroll
    for(int i=0;i<8;i++){
        int m = bm*128 + (ty<<2) + (i&3) + ((i>>2)<<6);
        #pragma unroll
        for(int j=0;j<8;j++){
            int jc = bn*128 + (tx<<2) + (j&3) + ((j>>2)<<6);
            float v = acc[i][j];
            if (MODE==0){ v += bias[jc]; C[(size_t)m*Dsz+jc]=v; }
            else if (MODE==4){ v += bias[jc] + resid[(size_t)m*Dsz+jc]; C[(size_t)m*Dsz+jc]=v; }
            else { C[(size_t)n*Dsz*Rsz + (size_t)m*Rsz + jc]=v; }
        }
    }
}

// ---------------- embedding gather ------------------------------------------
__global__ void __launch_bounds__(256) embed_k(const int* __restrict__ x,
                                               const float* __restrict__ emb)
{
    int idx = blockIdx.x*256 + threadIdx.x;
    int m = idx>>9, d = idx&511;
    int t = m>>3, b = m&7;
    g_X[idx] = emb[(size_t)x[b*Ssz+t]*Dsz + d];
}

// ---------------- combined k/v biases ----------------------------------------
__global__ void __launch_bounds__(256) ckcv_k(const float* __restrict__ in_w,
                                              const float* __restrict__ in_b,
                                              const float* __restrict__ b_np)
{
    int idx = blockIdx.x*256 + threadIdx.x;
    int n = idx>>9, dc = idx&511;
    const float* Wk = in_w + Dsz*Dsz;
    const float* Wv = in_w + 2*Dsz*Dsz;
    const float* bn = b_np + n*Dsz;
    float sk = in_b[Dsz+dc], sv = in_b[2*Dsz+dc];
    for (int j=0;j<Dsz;j++){
        float bj = bn[j];
        sk += Wk[(size_t)dc*Dsz+j]*bj;
        sv += Wv[(size_t)dc*Dsz+j]*bj;
    }
    g_ck[idx]=sk; g_cv[idx]=sv;
}

// ---------------- persistent LSTM recurrence ---------------------------------
__global__ void zero_bar_k(){ g_bar = 0u; }

__global__ void __launch_bounds__(256,1) lstm_persist(
    const float* __restrict__ Whh, const float* __restrict__ h0,
    const float* __restrict__ c0, float* __restrict__ hall,
    const float* __restrict__ Gih, float* __restrict__ cfinal)
{
    __shared__ float hs[512][8];
    __shared__ float gsm[256][9];
    __shared__ float cs[64][8];
    int tid = threadIdx.x;
    int chunk = blockIdx.x & 7, n = blockIdx.x >> 3;

    for (int idx=tid; idx<512; idx+=256){
        int rl=idx>>3, b=idx&7;
        cs[rl][b] = c0[(size_t)(n*8+b)*Rsz + chunk*64 + rl];
    }

    int gate = tid>>6, rl = tid&63;
    int g = gate*Rsz + chunk*64 + rl;
    const float* W = Whh + (size_t)(n*G4+g)*Rsz;

    for (int t=0; t<Ssz; t++){
        const float* hprev = t ? hall + (size_t)(t-1)*NBR : h0;
        for (int idx=tid; idx<4096; idx+=256){
            int b = idx>>9, r = idx&511;
            hs[r][b] = hprev[(size_t)(n*8+b)*Rsz + r];
        }
        __syncthreads();

        float acc[8] = {};
        #pragma unroll 8
        for (int r=0;r<Rsz;r+=4){
            float4 w4 = *(const float4*)(W + r);
            #pragma unroll
            for (int c=0;c<4;c++){
                float wv = (&w4.x)[c];
                float4 hA = *(const float4*)&hs[r+c][0];
                float4 hB = *(const float4*)&hs[r+c][4];
                acc[0]+=wv*hA.x; acc[1]+=wv*hA.y; acc[2]+=wv*hA.z; acc[3]+=wv*hA.w;
                acc[4]+=wv*hB.x; acc[5]+=wv*hB.y; acc[6]+=wv*hB.z; acc[7]+=wv*hB.w;
            }
        }
        const float* Gt = Gih + (size_t)t*Nly*Bsz*G4;
        #pragma unroll
        for (int b=0;b<8;b++)
            gsm[tid][b] = acc[b] + Gt[(size_t)(n*8+b)*G4 + g];
        __syncthreads();

        for (int idx=tid; idx<512; idx+=256){
            int rl2 = idx>>3, b = idx&7;
            float iv = gsm[rl2      ][b];
            float fv = gsm[ 64+rl2  ][b];
            float gv = gsm[128+rl2  ][b];
            float ov = gsm[192+rl2  ][b];
            float cp = cs[rl2][b];
            float cn = sigm(fv)*cp + sigm(iv)*tanhf(gv);
            cs[rl2][b] = cn;
            hall[(size_t)t*NBR + (size_t)(n*8+b)*Rsz + chunk*64 + rl2] = sigm(ov)*tanhf(cn);
        }
        __threadfence();
        __syncthreads();
        if (tid==0){
            atomicAdd(&g_bar, 1u);
            unsigned target = 128u*(unsigned)(t+1);
            while (atomicAdd(&g_bar, 0u) < target) { }
            __threadfence();
        }
        __syncthreads();
    }

    for (int idx=tid; idx<512; idx+=256){
        int rl2 = idx>>3, b = idx&7;
        cfinal[(size_t)(n*8+b)*Rsz + chunk*64 + rl2] = cs[rl2][b];
    }
}

// ---------------- attention per token ----------------------------------------
__global__ void __launch_bounds__(256) attn_k()
{
    int m = blockIdx.x, tid = threadIdx.x;
    __shared__ float sq[512];
    __shared__ float sc[8][16];
    __shared__ float sw[8][16];
    sq[tid]     = g_q[(size_t)m*Dsz + tid];
    sq[tid+256] = g_q[(size_t)m*Dsz + tid + 256];
    __syncthreads();
    if (tid < 128){
        int h = tid>>4, nn = tid&15;
        const float* kp = g_k + (size_t)(m*Nly+nn)*Dsz + h*64;
        float s = 0.f;
        #pragma unroll 8
        for (int e=0;e<64;e++) s += sq[h*64+e]*kp[e];
        sc[h][nn] = s*0.125f;
    }
    __syncthreads();
    if (tid < 8){
        float mx = -1e30f;
        for (int nn=0;nn<16;nn++) mx = fmaxf(mx, sc[tid][nn]);
        float e[16], sum = 0.f;
        for (int nn=0;nn<16;nn++){ e[nn]=expf(sc[tid][nn]-mx); sum+=e[nn]; }
        float inv = 1.f/sum;
        for (int nn=0;nn<16;nn++) sw[tid][nn]=e[nn]*inv;
    }
    __syncthreads();
    for (int idx=tid; idx<512; idx+=256){
        int h = idx>>6;
        float s = 0.f;
        #pragma unroll
        for (int nn=0;nn<16;nn++)
            s += sw[h][nn]*g_v[(size_t)(m*Nly+nn)*Dsz + idx];
        g_att[(size_t)m*Dsz + idx] = s;
    }
}

// ---------------- layernorm (in-place on g_mix) ------------------------------
__global__ void __launch_bounds__(256) ln_k(const float* __restrict__ gam,
                                            const float* __restrict__ bet)
{
    int m = blockIdx.x, tid = threadIdx.x;
    __shared__ float sh[8];
    __shared__ float sh2[8];
    float* row = g_mix + (size_t)m*Dsz;
    float v0 = row[tid], v1 = row[tid+256];
    int lane = tid&31, w = tid>>5;

    float s = v0+v1;
    #pragma unroll
    for (int o=16;o>0;o>>=1) s += __shfl_xor_sync(0xffffffffu, s, o);
    if (lane==0) sh[w]=s;
    __syncthreads();
    float tot = sh[0]+sh[1]+sh[2]+sh[3]+sh[4]+sh[5]+sh[6]+sh[7];
    float mu = tot*(1.f/512.f);

    float d0=v0-mu, d1=v1-mu;
    float s2 = d0*d0+d1*d1;
    #pragma unroll
    for (int o=16;o>0;o>>=1) s2 += __shfl_xor_sync(0xffffffffu, s2, o);
    if (lane==0) sh2[w]=s2;
    __syncthreads();
    float tot2 = sh2[0]+sh2[1]+sh2[2]+sh2[3]+sh2[4]+sh2[5]+sh2[6]+sh2[7];
    float inv = rsqrtf(tot2*(1.f/512.f) + 1e-5f);

    row[tid]     = d0*inv*gam[tid]     + bet[tid];
    row[tid+256] = d1*inv*gam[tid+256] + bet[tid+256];
}

// ---------------- final state copy ------------------------------------------
__global__ void __launch_bounds__(256) copyhc_k(const float* __restrict__ hf,
                                                const float* __restrict__ cf,
                                                float* __restrict__ out)
{
    int idx = blockIdx.x*256 + threadIdx.x;
    const size_t L = (size_t)Bsz*Ssz*Vsz;
    out[L + idx]       = hf[idx];
    out[L + NBR + idx] = cf[idx];
}

// =============================================================================
extern "C" void kernel_launch(void* const* d_in, const int* in_sizes, int n_in,
                              void* d_out, int out_size)
{
    const int*   x      = (const int*)  d_in[0];
    const float* h0     = (const float*)d_in[1];
    const float* c0     = (const float*)d_in[2];
    const float* emb    = (const float*)d_in[3];
    const float* W_ih   = (const float*)d_in[4];
    const float* b_ih   = (const float*)d_in[5];
    const float* W_hh   = (const float*)d_in[6];
    const float* b_hh   = (const float*)d_in[7];
    const float* W_np   = (const float*)d_in[8];
    const float* b_np   = (const float*)d_in[9];
    const float* in_w   = (const float*)d_in[10];
    const float* in_b   = (const float*)d_in[11];
    const float* op_w   = (const float*)d_in[12];
    const float* op_b   = (const float*)d_in[13];
    const float* ln_g   = (const float*)d_in[14];
    const float* ln_b   = (const float*)d_in[15];
    const float* head_w = (const float*)d_in[16];
    const float* head_b = (const float*)d_in[17];
    float* out = (float*)d_out;

    cudaFuncSetAttribute(tgemm_k<1>, cudaFuncAttributeMaxDynamicSharedMemorySize, TG_SMEM);
    cudaFuncSetAttribute(tgemm_k<2>, cudaFuncAttributeMaxDynamicSharedMemorySize, TG_SMEM);
    cudaFuncSetAttribute(tgemm_k<3>, cudaFuncAttributeMaxDynamicSharedMemorySize, TG_SMEM);

    float *pX,*pGih,*pHall,*pCf,*pQ,*pWnk,*pWnv,*pCk,*pCv,*pK,*pV,*pAtt,*pMix;
    __nv_bfloat16 *pWihH,*pWihL,*pHeadH,*pHeadL,*pXH,*pXL,*pHallH,*pHallL;
    __nv_bfloat16 *pWnkH,*pWnkL,*pWnvH,*pWnvL,*pMixH,*pMixL;
    cudaGetSymbolAddress((void**)&pX,    g_X);
    cudaGetSymbolAddress((void**)&pGih,  g_Gih);
    cudaGetSymbolAddress((void**)&pHall, g_hall);
    cudaGetSymbolAddress((void**)&pCf,   g_cf);
    cudaGetSymbolAddress((void**)&pQ,    g_q);
    cudaGetSymbolAddress((void**)&pWnk,  g_Wnk);
    cudaGetSymbolAddress((void**)&pWnv,  g_Wnv);
    cudaGetSymbolAddress((void**)&pCk,   g_ck);
    cudaGetSymbolAddress((void**)&pCv,   g_cv);
    cudaGetSymbolAddress((void**)&pK,    g_k);
    cudaGetSymbolAddress((void**)&pV,    g_v);
    cudaGetSymbolAddress((void**)&pAtt,  g_att);
    cudaGetSymbolAddress((void**)&pMix,  g_mix);
    cudaGetSymbolAddress((void**)&pWihH, bWih_h);  cudaGetSymbolAddress((void**)&pWihL, bWih_l);
    cudaGetSymbolAddress((void**)&pHeadH,bHead_h); cudaGetSymbolAddress((void**)&pHeadL,bHead_l);
    cudaGetSymbolAddress((void**)&pXH,   bX_h);    cudaGetSymbolAddress((void**)&pXL,   bX_l);
    cudaGetSymbolAddress((void**)&pHallH,bHall_h); cudaGetSymbolAddress((void**)&pHallL,bHall_l);
    cudaGetSymbolAddress((void**)&pWnkH, bWnk_h);  cudaGetSymbolAddress((void**)&pWnkL, bWnk_l);
    cudaGetSymbolAddress((void**)&pWnvH, bWnv_h);  cudaGetSymbolAddress((void**)&pWnvL, bWnv_l);
    cudaGetSymbolAddress((void**)&pMixH, bMix_h);  cudaGetSymbolAddress((void**)&pMixL, bMix_l);

    // Phase 0: embedding + weight/input bf16 splits
    embed_k<<<(Mtok*Dsz)/256, 256>>>(x, emb);
    split_k<<<(Mtok*Dsz)/256,256>>>(pX, pXH, pXL, Mtok*Dsz);
    split_k<<<(Nly*G4*Dsz)/256,256>>>(W_ih, pWihH, pWihL, Nly*G4*Dsz);
    split_k<<<(Vsz*Dsz)/256,256>>>(head_w, pHeadH, pHeadL, Vsz*Dsz);

    // Phase 1: gates_ih (tensor), q (SIMT), Wnk/Wnv (SIMT) + splits
    tgemm_k<1><<<dim3(16,16,16),256,TG_SMEM>>>(pXH,pXL,pWihH,pWihL,pGih,b_ih,b_hh);
    gemm_k<0><<<dim3(4,16),256>>>(pX, in_w, pQ, in_b, nullptr);
    gemm_k<5><<<dim3(4,4,16),256>>>(in_w +   Dsz*Dsz, W_np, pWnk, nullptr, nullptr);
    gemm_k<5><<<dim3(4,4,16),256>>>(in_w + 2*Dsz*Dsz, W_np, pWnv, nullptr, nullptr);
    split_k<<<(Nly*Dsz*Rsz)/256,256>>>(pWnk, pWnkH, pWnkL, Nly*Dsz*Rsz);
    split_k<<<(Nly*Dsz*Rsz)/256,256>>>(pWnv, pWnvH, pWnvL, Nly*Dsz*Rsz);
    ckcv_k<<<(Nly*Dsz)/256, 256>>>(in_w, in_b, b_np);

    // Phase 2: persistent recurrence (one kernel, grid barrier per step)
    zero_bar_k<<<1,1>>>();
    lstm_persist<<<128,256>>>(W_hh, h0, c0, pHall, pGih, pCf);

    // Phase 3: k/v (tensor), attention, out-proj (SIMT), LN, head (tensor)
    split_k<<<((int)((size_t)Ssz*NBR)/256),256>>>(pHall, pHallH, pHallL, Ssz*NBR);
    tgemm_k<3><<<dim3(4,16,16),256,TG_SMEM>>>(pHallH,pHallL,pWnkH,pWnkL,pK,pCk,nullptr);
    tgemm_k<3><<<dim3(4,16,16),256,TG_SMEM>>>(pHallH,pHallL,pWnvH,pWnvL,pV,pCv,nullptr);
    attn_k<<<Mtok,256>>>();
    gemm_k<4><<<dim3(4,16),256>>>(pAtt, op_w, pMix, op_b, pX);
    ln_k<<<Mtok,256>>>(ln_g, ln_b);
    split_k<<<(Mtok*Dsz)/256,256>>>(pMix, pMixH, pMixL, Mtok*Dsz);
    tgemm_k<2><<<dim3(250,16),256,TG_SMEM>>>(pMixH,pMixL,pHeadH,pHeadL,out,head_b,nullptr);

    // hf / cf
    copyhc_k<<<NBR/256,256>>>(pHall + (size_t)(Ssz-1)*NBR, pCf, out);
}

// round 9
// speedup vs baseline: 1.5562x; 1.1243x over previous
#include <cuda_runtime.h>
#include <cuda_bf16.h>
#include <math.h>
#include <stdint.h>

// Problem dims
#define Bsz 8
#define Ssz 256
#define Vsz 32000
#define Dsz 512
#define Nly 16
#define Rsz 512
#define G4  2048            // 4*R
#define Mtok (Bsz*Ssz)      // 2048 tokens
#define NBR (Nly*Bsz*Rsz)   // 65536

// ---------------- scratch (static device globals; no runtime alloc) ----------
__device__ float g_X   [Mtok*Dsz];
__device__ float g_Gih [(size_t)Ssz*Nly*Bsz*G4];         // [t][n][b][g]
__device__ float g_hall[NBR];                            // final-step h only (hf)
__device__ float g_cf  [NBR];
__device__ float g_q   [Mtok*Dsz];
__device__ float g_Wnk [Nly*Dsz*Rsz];
__device__ float g_Wnv [Nly*Dsz*Rsz];
__device__ float g_ck  [Nly*Dsz];
__device__ float g_cv  [Nly*Dsz];
__device__ float g_k   [(size_t)Mtok*Nly*Dsz];
__device__ float g_v   [(size_t)Mtok*Nly*Dsz];
__device__ float g_att [Mtok*Dsz];
__device__ float g_mix [Mtok*Dsz];
__device__ unsigned g_bar;

// bf16 split buffers (hi + lo)
__device__ __align__(16) __nv_bfloat16 bWih_h [(size_t)Nly*G4*Dsz];
__device__ __align__(16) __nv_bfloat16 bWih_l [(size_t)Nly*G4*Dsz];
__device__ __align__(16) __nv_bfloat16 bWhh_h [(size_t)Nly*G4*Dsz];
__device__ __align__(16) __nv_bfloat16 bWhh_l [(size_t)Nly*G4*Dsz];
__device__ __align__(16) __nv_bfloat16 bHead_h[(size_t)Vsz*Dsz];
__device__ __align__(16) __nv_bfloat16 bHead_l[(size_t)Vsz*Dsz];
__device__ __align__(16) __nv_bfloat16 bX_h   [Mtok*Dsz];
__device__ __align__(16) __nv_bfloat16 bX_l   [Mtok*Dsz];
__device__ __align__(16) __nv_bfloat16 bHall_h[(size_t)Ssz*NBR];
__device__ __align__(16) __nv_bfloat16 bHall_l[(size_t)Ssz*NBR];
__device__ __align__(16) __nv_bfloat16 bWnk_h [Nly*Dsz*Rsz];
__device__ __align__(16) __nv_bfloat16 bWnk_l [Nly*Dsz*Rsz];
__device__ __align__(16) __nv_bfloat16 bWnv_h [Nly*Dsz*Rsz];
__device__ __align__(16) __nv_bfloat16 bWnv_l [Nly*Dsz*Rsz];
__device__ __align__(16) __nv_bfloat16 bMix_h [Mtok*Dsz];
__device__ __align__(16) __nv_bfloat16 bMix_l [Mtok*Dsz];

__device__ __forceinline__ float sigm(float x){ return 1.f/(1.f+expf(-x)); }

// ======================= PTX helpers (compute_103-safe) ======================
__device__ __forceinline__ void cp16(uint32_t sdst, const void* gsrc){
    asm volatile("cp.async.cg.shared.global [%0], [%1], 16;" :: "r"(sdst), "l"(gsrc));
}
__device__ __forceinline__ void cp_commit(){
    asm volatile("cp.async.commit_group;" ::: "memory");
}
template<int N>
__device__ __forceinline__ void cp_wait(){
    asm volatile("cp.async.wait_group %0;" :: "n"(N) : "memory");
}
__device__ __forceinline__ void ldsm_x4(uint32_t* r, uint32_t addr){
    asm volatile("ldmatrix.sync.aligned.m8n8.x4.shared.b16 {%0,%1,%2,%3}, [%4];"
        : "=r"(r[0]),"=r"(r[1]),"=r"(r[2]),"=r"(r[3]) : "r"(addr));
}
__device__ __forceinline__ void mma16816(float* d, const uint32_t* a, const uint32_t* b){
    asm volatile("mma.sync.aligned.m16n8k16.row.col.f32.bf16.bf16.f32 "
        "{%0,%1,%2,%3}, {%4,%5,%6,%7}, {%8,%9}, {%0,%1,%2,%3};"
        : "+f"(d[0]),"+f"(d[1]),"+f"(d[2]),"+f"(d[3])
        : "r"(a[0]),"r"(a[1]),"r"(a[2]),"r"(a[3]), "r"(b[0]),"r"(b[1]));
}

// ======================= mma.sync bf16-split GEMM (unchanged, passing) =======
#define TG_LD   72
#define TG_BLK  (128*TG_LD)
#define TG_SMEM (8*TG_BLK*2)

template<int MODE>
__global__ void __launch_bounds__(256,1) tgemm_k(
    const __nv_bfloat16* __restrict__ Ah, const __nv_bfloat16* __restrict__ Al,
    const __nv_bfloat16* __restrict__ Bh, const __nv_bfloat16* __restrict__ Bl,
    float* __restrict__ C, const float* __restrict__ bias,
    const float* __restrict__ bias2)
{
    extern __shared__ __align__(16) __nv_bfloat16 smb[];
    uint32_t sbase = (uint32_t)__cvta_generic_to_shared(smb);
    int tid = threadIdx.x, wid = tid>>5, lane = tid&31;
    int wm = wid>>2, wn = wid&3;
    int bn = blockIdx.x, bm = blockIdx.y, nz = blockIdx.z;

    const __nv_bfloat16 *BhP = Bh, *BlP = Bl;
    if (MODE==1){ BhP += (size_t)nz*G4 *512; BlP += (size_t)nz*G4 *512; }
    if (MODE==3){ BhP += (size_t)nz*Dsz*512; BlP += (size_t)nz*Dsz*512; }

    int lrow = tid>>1, lk = (tid&1)*32;
    int am = bm*128 + lrow;
    int ag = (MODE==3) ? ((am>>3)*128 + nz*8 + (am&7)) : am;
    const __nv_bfloat16* gAh = Ah  + (size_t)ag*512 + lk;
    const __nv_bfloat16* gAl = Al  + (size_t)ag*512 + lk;
    const __nv_bfloat16* gBh = BhP + (size_t)(bn*128 + lrow)*512 + lk;
    const __nv_bfloat16* gBl = BlP + (size_t)(bn*128 + lrow)*512 + lk;
    uint32_t sRowOff = (uint32_t)(lrow*TG_LD + lk)*2;

    int aRowL = wm*64 + (lane&15);
    int aColL = (lane>>4)*8;
    int bRowL = wn*32 + ((lane>>4)&1)*8 + (lane&7);
    int bColL = ((lane>>3)&1)*8;

    float acc[4][4][4];
    #pragma unroll
    for (int i=0;i<4;i++){
        #pragma unroll
        for (int j=0;j<4;j++){
            acc[i][j][0]=0.f; acc[i][j][1]=0.f; acc[i][j][2]=0.f; acc[i][j][3]=0.f;
        }
    }

    auto issue = [&](int s, int kb){
        uint32_t d0 = sbase + (uint32_t)((s*4+0)*TG_BLK)*2 + sRowOff;
        uint32_t d1 = sbase + (uint32_t)((s*4+1)*TG_BLK)*2 + sRowOff;
        uint32_t d2 = sbase + (uint32_t)((s*4+2)*TG_BLK)*2 + sRowOff;
        uint32_t d3 = sbase + (uint32_t)((s*4+3)*TG_BLK)*2 + sRowOff;
        #pragma unroll
        for (int i=0;i<4;i++){
            cp16(d0 + i*16, gAh + kb + i*8);
            cp16(d1 + i*16, gAl + kb + i*8);
            cp16(d2 + i*16, gBh + kb + i*8);
            cp16(d3 + i*16, gBl + kb + i*8);
        }
        cp_commit();
    };

    issue(0, 0);
    for (int c=0;c<8;c++){
        int s = c&1;
        if (c<7) issue(s^1, (c+1)*64);
        if (c<7) cp_wait<1>(); else cp_wait<0>();
        __syncthreads();

        #pragma unroll
        for (int ks=0; ks<4; ks++){
            int kc = ks*16;
            uint32_t ah[4][4], al[4][4];
            #pragma unroll
            for (int mf=0; mf<4; mf++){
                uint32_t addrh = sbase + (uint32_t)((s*4+0)*TG_BLK + (aRowL+mf*16)*TG_LD + aColL + kc)*2;
                uint32_t addrl = sbase + (uint32_t)((s*4+1)*TG_BLK + (aRowL+mf*16)*TG_LD + aColL + kc)*2;
                ldsm_x4(ah[mf], addrh);
                ldsm_x4(al[mf], addrl);
            }
            uint32_t bh[2][4], bl[2][4];
            #pragma unroll
            for (int nfh=0; nfh<2; nfh++){
                uint32_t addrh = sbase + (uint32_t)((s*4+2)*TG_BLK + (bRowL+nfh*16)*TG_LD + bColL + kc)*2;
                uint32_t addrl = sbase + (uint32_t)((s*4+3)*TG_BLK + (bRowL+nfh*16)*TG_LD + bColL + kc)*2;
                ldsm_x4(bh[nfh], addrh);
                ldsm_x4(bl[nfh], addrl);
            }
            #pragma unroll
            for (int mf=0; mf<4; mf++){
                #pragma unroll
                for (int nf=0; nf<4; nf++){
                    const uint32_t* bhp = &bh[nf>>1][(nf&1)*2];
                    const uint32_t* blp = &bl[nf>>1][(nf&1)*2];
                    mma16816(acc[mf][nf], ah[mf], bhp);
                    mma16816(acc[mf][nf], ah[mf], blp);
                    mma16816(acc[mf][nf], al[mf], bhp);
                }
            }
        }
        __syncthreads();
    }

    int rA = lane>>2, cA = (lane&3)*2;
    #pragma unroll
    for (int mf=0; mf<4; mf++){
        #pragma unroll
        for (int nf=0; nf<4; nf++){
            #pragma unroll
            for (int half=0; half<2; half++){
                int m  = bm*128 + wm*64 + mf*16 + rA + half*8;
                int jc = bn*128 + wn*32 + nf*8 + cA;
                float v0 = acc[mf][nf][half*2+0];
                float v1 = acc[mf][nf][half*2+1];
                if (MODE==1){
                    v0 += bias[nz*G4+jc]   + bias2[nz*G4+jc];
                    v1 += bias[nz*G4+jc+1] + bias2[nz*G4+jc+1];
                    int t=m>>3, b=m&7;
                    float2 w = {v0,v1};
                    *(float2*)&C[(size_t)(t*128+nz*8+b)*G4 + jc] = w;
                } else if (MODE==2){
                    v0 += bias[jc]; v1 += bias[jc+1];
                    int t=m>>3, b=m&7;
                    float2 w = {v0,v1};
                    *(float2*)&C[(size_t)(b*Ssz+t)*Vsz + jc] = w;
                } else {
                    v0 += bias[nz*Dsz+jc]; v1 += bias[nz*Dsz+jc+1];
                    float2 w = {v0,v1};
                    *(float2*)&C[(size_t)(m*Nly+nz)*Dsz + jc] = w;
                }
            }
        }
    }
}

// ---------------- fp32 -> bf16 hi/lo split -----------------------------------
__global__ void __launch_bounds__(256) split_k(const float* __restrict__ src,
                                              __nv_bfloat16* __restrict__ hi,
                                              __nv_bfloat16* __restrict__ lo,
                                              int n)
{
    int i = blockIdx.x*256 + threadIdx.x;
    if (i < n){
        float x = src[i];
        __nv_bfloat16 h = __float2bfloat16(x);
        hi[i] = h;
        lo[i] = __float2bfloat16(x - __bfloat162float(h));
    }
}

// ---------------- SIMT 128x128 GEMM (small modes 0,4,5) ----------------------
template<int MODE>
__global__ void __launch_bounds__(256, 2) gemm_k(
    const float* __restrict__ A, const float* __restrict__ Bw,
    float* __restrict__ C, const float* __restrict__ bias,
    const float* __restrict__ resid)
{
    const int K = 512;
    __shared__ float As[2][8][132];
    __shared__ float Bs[2][8][132];
    int tid = threadIdx.x;
    int bn = blockIdx.x, bm = blockIdx.y, n = blockIdx.z;

    const float* Bp = Bw;
    if (MODE==5) Bp += (size_t)n*Dsz*Rsz;

    int lRow = tid>>1, lK = (tid&1)<<2;
    const float* Aptr = A + (size_t)(bm*128+lRow)*K + lK;
    const float* Bptr;
    int b_k=0, b_j=0;
    if (MODE==5){
        b_k = tid>>5; b_j = (tid&31)<<2;
        Bptr = Bp + (size_t)b_k*Rsz + bn*128 + b_j;
    } else {
        Bptr = Bp + (size_t)(bn*128 + lRow)*K + lK;
    }
    int ty = tid>>4, tx = tid&15;
    float acc[8][8] = {};
    float4 aReg, bReg;

    aReg = *(const float4*)(Aptr);
    bReg = *(const float4*)(Bptr);
    As[0][lK+0][lRow]=aReg.x; As[0][lK+1][lRow]=aReg.y;
    As[0][lK+2][lRow]=aReg.z; As[0][lK+3][lRow]=aReg.w;
    if (MODE==5){ *(float4*)&Bs[0][b_k][b_j] = bReg; }
    else {
        Bs[0][lK+0][lRow]=bReg.x; Bs[0][lK+1][lRow]=bReg.y;
        Bs[0][lK+2][lRow]=bReg.z; Bs[0][lK+3][lRow]=bReg.w;
    }
    __syncthreads();

    int buf = 0;
    for (int kb=8; kb<=K; kb+=8){
        bool more = (kb < K);
        if (more){
            aReg = *(const float4*)(Aptr + kb);
            bReg = (MODE==5) ? *(const float4*)(Bptr + (size_t)kb*Rsz)
                             : *(const float4*)(Bptr + kb);
        }
        #pragma unroll
        for (int k=0;k<8;k++){
            float4 a0 = *(const float4*)&As[buf][k][ty<<2];
            float4 a1 = *(const float4*)&As[buf][k][(ty<<2)+64];
            float4 b0 = *(const float4*)&Bs[buf][k][tx<<2];
            float4 b1 = *(const float4*)&Bs[buf][k][(tx<<2)+64];
            float a[8]={a0.x,a0.y,a0.z,a0.w,a1.x,a1.y,a1.z,a1.w};
            float b[8]={b0.x,b0.y,b0.z,b0.w,b1.x,b1.y,b1.z,b1.w};
            #pragma unroll
            for(int i=0;i<8;i++)
                #pragma unroll
                for(int j=0;j<8;j++) acc[i][j] += a[i]*b[j];
        }
        if (more){
            int nb = buf^1;
            As[nb][lK+0][lRow]=aReg.x; As[nb][lK+1][lRow]=aReg.y;
            As[nb][lK+2][lRow]=aReg.z; As[nb][lK+3][lRow]=aReg.w;
            if (MODE==5){ *(float4*)&Bs[nb][b_k][b_j] = bReg; }
            else {
                Bs[nb][lK+0][lRow]=bReg.x; Bs[nb][lK+1][lRow]=bReg.y;
                Bs[nb][lK+2][lRow]=bReg.z; Bs[nb][lK+3][lRow]=bReg.w;
            }
            __syncthreads();
            buf = nb;
        }
    }

    #pragma unroll
    for(int i=0;i<8;i++){
        int m = bm*128 + (ty<<2) + (i&3) + ((i>>2)<<6);
        #pragma unroll
        for(int j=0;j<8;j++){
            int jc = bn*128 + (tx<<2) + (j&3) + ((j>>2)<<6);
            float v = acc[i][j];
            if (MODE==0){ v += bias[jc]; C[(size_t)m*Dsz+jc]=v; }
            else if (MODE==4){ v += bias[jc] + resid[(size_t)m*Dsz+jc]; C[(size_t)m*Dsz+jc]=v; }
            else { C[(size_t)n*Dsz*Rsz + (size_t)m*Rsz + jc]=v; }
        }
    }
}

// ---------------- embedding gather ------------------------------------------
__global__ void __launch_bounds__(256) embed_k(const int* __restrict__ x,
                                               const float* __restrict__ emb)
{
    int idx = blockIdx.x*256 + threadIdx.x;
    int m = idx>>9, d = idx&511;
    int t = m>>3, b = m&7;
    g_X[idx] = emb[(size_t)x[b*Ssz+t]*Dsz + d];
}

// ---------------- combined k/v biases ----------------------------------------
__global__ void __launch_bounds__(256) ckcv_k(const float* __restrict__ in_w,
                                              const float* __restrict__ in_b,
                                              const float* __restrict__ b_np)
{
    int idx = blockIdx.x*256 + threadIdx.x;
    int n = idx>>9, dc = idx&511;
    const float* Wk = in_w + Dsz*Dsz;
    const float* Wv = in_w + 2*Dsz*Dsz;
    const float* bn = b_np + n*Dsz;
    float sk = in_b[Dsz+dc], sv = in_b[2*Dsz+dc];
    for (int j=0;j<Dsz;j++){
        float bj = bn[j];
        sk += Wk[(size_t)dc*Dsz+j]*bj;
        sv += Wv[(size_t)dc*Dsz+j]*bj;
    }
    g_ck[idx]=sk; g_cv[idx]=sv;
}

// ---------------- persistent LSTM recurrence (HMMA bf16-split) ---------------
// 128 CTAs: blockIdx = n*8 + chunk. CTA computes gates[256x8] for its layer n,
// rows m = gate*64 + rloc (rloc = chunk's 64 r-values), via m16n8k16:
//   gates = (Wh+Wl)[256x512] . (hh+hl)^T[512x8]   (3 products, drop lo*lo)
// W staged L2->smem (cp.async double-buffer), h in smem, split written to
// bHall hi/lo each step; fp32 h only at final step (for hf).
#define LSW 40                     // W smem row stride (elts): 80B, cp-aligned + ldsm bank-clean
#define LSH 536                    // h smem row stride (elts): 1072B, 16B-aligned + LDS bank-clean
#define L_WSBLK (256*LSW)          // one W (stage,part) block in elts
#define L_OFF_HH (4*L_WSBLK*2)     // after 4 W blocks (2 stages x hi/lo)
#define L_OFF_HL (L_OFF_HH + 8*LSH*2)
#define L_OFF_GA (L_OFF_HL + 8*LSH*2)
#define L_OFF_CS (L_OFF_GA + 256*9*4)
#define L_SMEM   (L_OFF_CS + 64*9*4)

__global__ void zero_bar_k(){ g_bar = 0u; }

__global__ void __launch_bounds__(256,1) lstm_mma(
    const __nv_bfloat16* __restrict__ Wh, const __nv_bfloat16* __restrict__ Wl,
    const float* __restrict__ h0, const float* __restrict__ c0,
    float* __restrict__ hfinal,
    __nv_bfloat16* __restrict__ hall_h, __nv_bfloat16* __restrict__ hall_l,
    const float* __restrict__ Gih, float* __restrict__ cfinal)
{
    extern __shared__ __align__(16) char sm[];
    uint32_t sbase = (uint32_t)__cvta_generic_to_shared(sm);
    __nv_bfloat16* hh_s = (__nv_bfloat16*)(sm + L_OFF_HH);
    __nv_bfloat16* hl_s = (__nv_bfloat16*)(sm + L_OFF_HL);
    float* ga = (float*)(sm + L_OFF_GA);   // [256][9]
    float* cs = (float*)(sm + L_OFF_CS);   // [64][9]

    int tid = threadIdx.x, wid = tid>>5, lane = tid&31;
    int chunk = blockIdx.x & 7, n = blockIdx.x >> 3;

    // W global base for this CTA's row m (m = gate*64 + rloc)
    int m_row = tid;                       // cp mapping: thread t loads row t
    int gateT = m_row>>6, rlocT = m_row&63;
    size_t grow = (size_t)(n*G4 + gateT*512 + chunk*64 + rlocT)*512;
    const __nv_bfloat16* gWh = Wh + grow;
    const __nv_bfloat16* gWl = Wl + grow;

    // init c
    for (int idx=tid; idx<512; idx+=256){
        int b = idx>>6, r = idx&63;
        cs[r*9+b] = c0[(size_t)(n*8+b)*Rsz + chunk*64 + r];
    }

    // ldmatrix lane addressing for A frags
    int aRow = lane&15, aCol = (lane>>4)*8;
    // b-frag LDS addressing
    int bN = lane>>2, bK2 = 2*(lane&3);

    for (int t=0; t<Ssz; t++){
        // ---- load h (prev) into smem hi/lo ----
        if (t==0){
            for (int idx=tid; idx<4096; idx+=256){
                int b = idx>>9, r = idx&511;
                float v = h0[(size_t)(n*8+b)*Rsz + r];
                __nv_bfloat16 h = __float2bfloat16(v);
                hh_s[b*LSH + r] = h;
                hl_s[b*LSH + r] = __float2bfloat16(v - __bfloat162float(h));
            }
        } else {
            const __nv_bfloat16* ph = hall_h + (size_t)(t-1)*NBR + (size_t)(n*8)*Rsz;
            const __nv_bfloat16* pl = hall_l + (size_t)(t-1)*NBR + (size_t)(n*8)*Rsz;
            for (int idx=tid; idx<512; idx+=256){
                int b = idx>>6, r8 = (idx&63)*8;
                *(uint4*)(hh_s + b*LSH + r8) = *(const uint4*)(ph + b*Rsz + r8);
                *(uint4*)(hl_s + b*LSH + r8) = *(const uint4*)(pl + b*Rsz + r8);
            }
        }
        __syncthreads();

        // ---- stage W chunk kc into stage s (hi:p0, lo:p1) ----
        auto issueW = [&](int kc, int s){
            uint32_t dh = sbase + (uint32_t)((s*2+0)*L_WSBLK + m_row*LSW)*2;
            uint32_t dl = sbase + (uint32_t)((s*2+1)*L_WSBLK + m_row*LSW)*2;
            const __nv_bfloat16* sh = gWh + kc*32;
            const __nv_bfloat16* sl = gWl + kc*32;
            #pragma unroll
            for (int i=0;i<4;i++){
                cp16(dh + i*16, sh + i*8);
                cp16(dl + i*16, sl + i*8);
            }
            cp_commit();
        };

        float acc[2][4];
        #pragma unroll
        for (int f=0;f<2;f++){ acc[f][0]=0.f; acc[f][1]=0.f; acc[f][2]=0.f; acc[f][3]=0.f; }

        issueW(0,0); issueW(1,1);
        for (int kc=0; kc<16; kc++){
            int s = kc&1;
            if (kc==15) cp_wait<0>(); else cp_wait<1>();
            __syncthreads();
            #pragma unroll
            for (int kf=0; kf<2; kf++){
                int kbase = kc*32 + kf*16;
                uint32_t bhr[2], blr[2];
                uint32_t hoff = (uint32_t)(bN*LSH + kbase + bK2)*2;
                bhr[0] = *(const uint32_t*)(sm + L_OFF_HH + hoff);
                bhr[1] = *(const uint32_t*)(sm + L_OFF_HH + hoff + 16);
                blr[0] = *(const uint32_t*)(sm + L_OFF_HL + hoff);
                blr[1] = *(const uint32_t*)(sm + L_OFF_HL + hoff + 16);
                #pragma unroll
                for (int f=0; f<2; f++){
                    int mbase = wid*32 + f*16;
                    uint32_t ah[4], al[4];
                    uint32_t wadr = (uint32_t)((mbase + aRow)*LSW + kf*16 + aCol)*2;
                    ldsm_x4(ah, sbase + (uint32_t)((s*2+0)*L_WSBLK)*2 + wadr);
                    ldsm_x4(al, sbase + (uint32_t)((s*2+1)*L_WSBLK)*2 + wadr);
                    mma16816(acc[f], ah, bhr);
                    mma16816(acc[f], ah, blr);
                    mma16816(acc[f], al, bhr);
                }
            }
            __syncthreads();
            if (kc+2 < 16) issueW(kc+2, s);
        }

        // ---- gates to smem ----
        int rA = lane>>2, cB = 2*(lane&3);
        #pragma unroll
        for (int f=0; f<2; f++){
            int m = wid*32 + f*16 + rA;
            ga[m*9 + cB]       = acc[f][0];
            ga[m*9 + cB + 1]   = acc[f][1];
            ga[(m+8)*9 + cB]   = acc[f][2];
            ga[(m+8)*9 + cB+1] = acc[f][3];
        }
        __syncthreads();

        // ---- elementwise LSTM + h split writeback ----
        const float* Gt = Gih + (size_t)t*Nly*Bsz*G4;
        for (int idx=tid; idx<512; idx+=256){
            int b = idx>>6, r = idx&63;
            size_t gb = (size_t)(n*8+b)*G4 + chunk*64 + r;
            float iv = ga[(      r)*9 + b] + Gt[gb          ];
            float fv = ga[( 64 + r)*9 + b] + Gt[gb +  512   ];
            float gv = ga[(128 + r)*9 + b] + Gt[gb + 1024   ];
            float ov = ga[(192 + r)*9 + b] + Gt[gb + 1536   ];
            float cp = cs[r*9+b];
            float cn = sigm(fv)*cp + sigm(iv)*tanhf(gv);
            cs[r*9+b] = cn;
            float hv = sigm(ov)*tanhf(cn);
            size_t ho = (size_t)t*NBR + (size_t)(n*8+b)*Rsz + chunk*64 + r;
            __nv_bfloat16 hh = __float2bfloat16(hv);
            hall_h[ho] = hh;
            hall_l[ho] = __float2bfloat16(hv - __bfloat162float(hh));
            if (t == Ssz-1)
                hfinal[(size_t)(n*8+b)*Rsz + chunk*64 + r] = hv;
        }
        __threadfence();
        __syncthreads();
        if (tid==0){
            atomicAdd(&g_bar, 1u);
            unsigned target = 128u*(unsigned)(t+1);
            while (atomicAdd(&g_bar, 0u) < target) { }
            __threadfence();
        }
        __syncthreads();
    }

    for (int idx=tid; idx<512; idx+=256){
        int b = idx>>6, r = idx&63;
        cfinal[(size_t)(n*8+b)*Rsz + chunk*64 + r] = cs[r*9+b];
    }
}

// ---------------- attention per token ----------------------------------------
__global__ void __launch_bounds__(256) attn_k()
{
    int m = blockIdx.x, tid = threadIdx.x;
    __shared__ float sq[512];
    __shared__ float sc[8][16];
    __shared__ float sw[8][16];
    sq[tid]     = g_q[(size_t)m*Dsz + tid];
    sq[tid+256] = g_q[(size_t)m*Dsz + tid + 256];
    __syncthreads();
    if (tid < 128){
        int h = tid>>4, nn = tid&15;
        const float* kp = g_k + (size_t)(m*Nly+nn)*Dsz + h*64;
        float s = 0.f;
        #pragma unroll 8
        for (int e=0;e<64;e++) s += sq[h*64+e]*kp[e];
        sc[h][nn] = s*0.125f;
    }
    __syncthreads();
    if (tid < 8){
        float mx = -1e30f;
        for (int nn=0;nn<16;nn++) mx = fmaxf(mx, sc[tid][nn]);
        float e[16], sum = 0.f;
        for (int nn=0;nn<16;nn++){ e[nn]=expf(sc[tid][nn]-mx); sum+=e[nn]; }
        float inv = 1.f/sum;
        for (int nn=0;nn<16;nn++) sw[tid][nn]=e[nn]*inv;
    }
    __syncthreads();
    for (int idx=tid; idx<512; idx+=256){
        int h = idx>>6;
        float s = 0.f;
        #pragma unroll
        for (int nn=0;nn<16;nn++)
            s += sw[h][nn]*g_v[(size_t)(m*Nly+nn)*Dsz + idx];
        g_att[(size_t)m*Dsz + idx] = s;
    }
}

// ---------------- layernorm (in-place on g_mix) ------------------------------
__global__ void __launch_bounds__(256) ln_k(const float* __restrict__ gam,
                                            const float* __restrict__ bet)
{
    int m = blockIdx.x, tid = threadIdx.x;
    __shared__ float sh[8];
    __shared__ float sh2[8];
    float* row = g_mix + (size_t)m*Dsz;
    float v0 = row[tid], v1 = row[tid+256];
    int lane = tid&31, w = tid>>5;

    float s = v0+v1;
    #pragma unroll
    for (int o=16;o>0;o>>=1) s += __shfl_xor_sync(0xffffffffu, s, o);
    if (lane==0) sh[w]=s;
    __syncthreads();
    float tot = sh[0]+sh[1]+sh[2]+sh[3]+sh[4]+sh[5]+sh[6]+sh[7];
    float mu = tot*(1.f/512.f);

    float d0=v0-mu, d1=v1-mu;
    float s2 = d0*d0+d1*d1;
    #pragma unroll
    for (int o=16;o>0;o>>=1) s2 += __shfl_xor_sync(0xffffffffu, s2, o);
    if (lane==0) sh2[w]=s2;
    __syncthreads();
    float tot2 = sh2[0]+sh2[1]+sh2[2]+sh2[3]+sh2[4]+sh2[5]+sh2[6]+sh2[7];
    float inv = rsqrtf(tot2*(1.f/512.f) + 1e-5f);

    row[tid]     = d0*inv*gam[tid]     + bet[tid];
    row[tid+256] = d1*inv*gam[tid+256] + bet[tid+256];
}

// ---------------- final state copy ------------------------------------------
__global__ void __launch_bounds__(256) copyhc_k(const float* __restrict__ hf,
                                                const float* __restrict__ cf,
                                                float* __restrict__ out)
{
    int idx = blockIdx.x*256 + threadIdx.x;
    const size_t L = (size_t)Bsz*Ssz*Vsz;
    out[L + idx]       = hf[idx];
    out[L + NBR + idx] = cf[idx];
}

// =============================================================================
extern "C" void kernel_launch(void* const* d_in, const int* in_sizes, int n_in,
                              void* d_out, int out_size)
{
    const int*   x      = (const int*)  d_in[0];
    const float* h0     = (const float*)d_in[1];
    const float* c0     = (const float*)d_in[2];
    const float* emb    = (const float*)d_in[3];
    const float* W_ih   = (const float*)d_in[4];
    const float* b_ih   = (const float*)d_in[5];
    const float* W_hh   = (const float*)d_in[6];
    const float* b_hh   = (const float*)d_in[7];
    const float* W_np   = (const float*)d_in[8];
    const float* b_np   = (const float*)d_in[9];
    const float* in_w   = (const float*)d_in[10];
    const float* in_b   = (const float*)d_in[11];
    const float* op_w   = (const float*)d_in[12];
    const float* op_b   = (const float*)d_in[13];
    const float* ln_g   = (const float*)d_in[14];
    const float* ln_b   = (const float*)d_in[15];
    const float* head_w = (const float*)d_in[16];
    const float* head_b = (const float*)d_in[17];
    float* out = (float*)d_out;

    cudaFuncSetAttribute(tgemm_k<1>, cudaFuncAttributeMaxDynamicSharedMemorySize, TG_SMEM);
    cudaFuncSetAttribute(tgemm_k<2>, cudaFuncAttributeMaxDynamicSharedMemorySize, TG_SMEM);
    cudaFuncSetAttribute(tgemm_k<3>, cudaFuncAttributeMaxDynamicSharedMemorySize, TG_SMEM);
    cudaFuncSetAttribute(lstm_mma,   cudaFuncAttributeMaxDynamicSharedMemorySize, L_SMEM);

    float *pX,*pGih,*pHall,*pCf,*pQ,*pWnk,*pWnv,*pCk,*pCv,*pK,*pV,*pAtt,*pMix;
    __nv_bfloat16 *pWihH,*pWihL,*pWhhH,*pWhhL,*pHeadH,*pHeadL,*pXH,*pXL,*pHallH,*pHallL;
    __nv_bfloat16 *pWnkH,*pWnkL,*pWnvH,*pWnvL,*pMixH,*pMixL;
    cudaGetSymbolAddress((void**)&pX,    g_X);
    cudaGetSymbolAddress((void**)&pGih,  g_Gih);
    cudaGetSymbolAddress((void**)&pHall, g_hall);
    cudaGetSymbolAddress((void**)&pCf,   g_cf);
    cudaGetSymbolAddress((void**)&pQ,    g_q);
    cudaGetSymbolAddress((void**)&pWnk,  g_Wnk);
    cudaGetSymbolAddress((void**)&pWnv,  g_Wnv);
    cudaGetSymbolAddress((void**)&pCk,   g_ck);
    cudaGetSymbolAddress((void**)&pCv,   g_cv);
    cudaGetSymbolAddress((void**)&pK,    g_k);
    cudaGetSymbolAddress((void**)&pV,    g_v);
    cudaGetSymbolAddress((void**)&pAtt,  g_att);
    cudaGetSymbolAddress((void**)&pMix,  g_mix);
    cudaGetSymbolAddress((void**)&pWihH, bWih_h);  cudaGetSymbolAddress((void**)&pWihL, bWih_l);
    cudaGetSymbolAddress((void**)&pWhhH, bWhh_h);  cudaGetSymbolAddress((void**)&pWhhL, bWhh_l);
    cudaGetSymbolAddress((void**)&pHeadH,bHead_h); cudaGetSymbolAddress((void**)&pHeadL,bHead_l);
    cudaGetSymbolAddress((void**)&pXH,   bX_h);    cudaGetSymbolAddress((void**)&pXL,   bX_l);
    cudaGetSymbolAddress((void**)&pHallH,bHall_h); cudaGetSymbolAddress((void**)&pHallL,bHall_l);
    cudaGetSymbolAddress((void**)&pWnkH, bWnk_h);  cudaGetSymbolAddress((void**)&pWnkL, bWnk_l);
    cudaGetSymbolAddress((void**)&pWnvH, bWnv_h);  cudaGetSymbolAddress((void**)&pWnvL, bWnv_l);
    cudaGetSymbolAddress((void**)&pMixH, bMix_h);  cudaGetSymbolAddress((void**)&pMixL, bMix_l);

    // Phase 0: embedding + weight/input bf16 splits
    embed_k<<<(Mtok*Dsz)/256, 256>>>(x, emb);
    split_k<<<(Mtok*Dsz)/256,256>>>(pX, pXH, pXL, Mtok*Dsz);
    split_k<<<(Nly*G4*Dsz)/256,256>>>(W_ih, pWihH, pWihL, Nly*G4*Dsz);
    split_k<<<(Nly*G4*Dsz)/256,256>>>(W_hh, pWhhH, pWhhL, Nly*G4*Dsz);
    split_k<<<(Vsz*Dsz)/256,256>>>(head_w, pHeadH, pHeadL, Vsz*Dsz);

    // Phase 1: gates_ih (tensor), q (SIMT), Wnk/Wnv (SIMT) + splits
    tgemm_k<1><<<dim3(16,16,16),256,TG_SMEM>>>(pXH,pXL,pWihH,pWihL,pGih,b_ih,b_hh);
    gemm_k<0><<<dim3(4,16),256>>>(pX, in_w, pQ, in_b, nullptr);
    gemm_k<5><<<dim3(4,4,16),256>>>(in_w +   Dsz*Dsz, W_np, pWnk, nullptr, nullptr);
    gemm_k<5><<<dim3(4,4,16),256>>>(in_w + 2*Dsz*Dsz, W_np, pWnv, nullptr, nullptr);
    split_k<<<(Nly*Dsz*Rsz)/256,256>>>(pWnk, pWnkH, pWnkL, Nly*Dsz*Rsz);
    split_k<<<(Nly*Dsz*Rsz)/256,256>>>(pWnv, pWnvH, pWnvL, Nly*Dsz*Rsz);
    ckcv_k<<<(Nly*Dsz)/256, 256>>>(in_w, in_b, b_np);

    // Phase 2: persistent recurrence (HMMA, grid barrier per step)
    zero_bar_k<<<1,1>>>();
    lstm_mma<<<128,256,L_SMEM>>>(pWhhH, pWhhL, h0, c0, pHall, pHallH, pHallL, pGih, pCf);

    // Phase 3: k/v (tensor, directly from bHall), attention, out-proj, LN, head
    tgemm_k<3><<<dim3(4,16,16),256,TG_SMEM>>>(pHallH,pHallL,pWnkH,pWnkL,pK,pCk,nullptr);
    tgemm_k<3><<<dim3(4,16,16),256,TG_SMEM>>>(pHallH,pHallL,pWnvH,pWnvL,pV,pCv,nullptr);
    attn_k<<<Mtok,256>>>();
    gemm_k<4><<<dim3(4,16),256>>>(pAtt, op_w, pMix, op_b, pX);
    ln_k<<<Mtok,256>>>(ln_g, ln_b);
    split_k<<<(Mtok*Dsz)/256,256>>>(pMix, pMixH, pMixL, Mtok*Dsz);
    tgemm_k<2><<<dim3(250,16),256,TG_SMEM>>>(pMixH,pMixL,pHeadH,pHeadL,out,head_b,nullptr);

    // hf / cf
    copyhc_k<<<NBR/256,256>>>(pHall, pCf, out);
}

// round 10
// speedup vs baseline: 1.6174x; 1.0393x over previous
#include <cuda_runtime.h>
#include <cuda_bf16.h>
#include <math.h>
#include <stdint.h>

// Problem dims
#define Bsz 8
#define Ssz 256
#define Vsz 32000
#define Dsz 512
#define Nly 16
#define Rsz 512
#define G4  2048            // 4*R
#define Mtok (Bsz*Ssz)      // 2048 tokens
#define NBR (Nly*Bsz*Rsz)   // 65536

// ---------------- scratch (static device globals; no runtime alloc) ----------
__device__ float g_X   [Mtok*Dsz];
__device__ float g_Gih [(size_t)Ssz*Nly*Bsz*G4];         // [t][n][b][g]
__device__ float g_hall[NBR];                            // final-step h only (hf)
__device__ float g_cf  [NBR];
__device__ float g_q   [Mtok*Dsz];
__device__ float g_Wnk [Nly*Dsz*Rsz];
__device__ float g_Wnv [Nly*Dsz*Rsz];
__device__ float g_ck  [Nly*Dsz];
__device__ float g_cv  [Nly*Dsz];
__device__ float g_k   [(size_t)Mtok*Nly*Dsz];
__device__ float g_v   [(size_t)Mtok*Nly*Dsz];
__device__ float g_att [Mtok*Dsz];
__device__ float g_mix [Mtok*Dsz];
__device__ unsigned g_bar;

// bf16 split buffers (hi + lo)
__device__ __align__(16) __nv_bfloat16 bWih_h [(size_t)Nly*G4*Dsz];
__device__ __align__(16) __nv_bfloat16 bWih_l [(size_t)Nly*G4*Dsz];
__device__ __align__(16) __nv_bfloat16 bWhh_h [(size_t)Nly*G4*Dsz];
__device__ __align__(16) __nv_bfloat16 bWhh_l [(size_t)Nly*G4*Dsz];
__device__ __align__(16) __nv_bfloat16 bHead_h[(size_t)Vsz*Dsz];
__device__ __align__(16) __nv_bfloat16 bHead_l[(size_t)Vsz*Dsz];
__device__ __align__(16) __nv_bfloat16 bX_h   [Mtok*Dsz];
__device__ __align__(16) __nv_bfloat16 bX_l   [Mtok*Dsz];
__device__ __align__(16) __nv_bfloat16 bHall_h[(size_t)Ssz*NBR];
__device__ __align__(16) __nv_bfloat16 bHall_l[(size_t)Ssz*NBR];
__device__ __align__(16) __nv_bfloat16 bWnk_h [Nly*Dsz*Rsz];
__device__ __align__(16) __nv_bfloat16 bWnk_l [Nly*Dsz*Rsz];
__device__ __align__(16) __nv_bfloat16 bWnv_h [Nly*Dsz*Rsz];
__device__ __align__(16) __nv_bfloat16 bWnv_l [Nly*Dsz*Rsz];
__device__ __align__(16) __nv_bfloat16 bMix_h [Mtok*Dsz];
__device__ __align__(16) __nv_bfloat16 bMix_l [Mtok*Dsz];

__device__ __forceinline__ float sigm(float x){ return 1.f/(1.f+expf(-x)); }

// ======================= PTX helpers (compute_103-safe) ======================
__device__ __forceinline__ void cp16(uint32_t sdst, const void* gsrc){
    asm volatile("cp.async.cg.shared.global [%0], [%1], 16;" :: "r"(sdst), "l"(gsrc));
}
__device__ __forceinline__ void cp_commit(){
    asm volatile("cp.async.commit_group;" ::: "memory");
}
template<int N>
__device__ __forceinline__ void cp_wait(){
    asm volatile("cp.async.wait_group %0;" :: "n"(N) : "memory");
}
__device__ __forceinline__ void ldsm_x4(uint32_t* r, uint32_t addr){
    asm volatile("ldmatrix.sync.aligned.m8n8.x4.shared.b16 {%0,%1,%2,%3}, [%4];"
        : "=r"(r[0]),"=r"(r[1]),"=r"(r[2]),"=r"(r[3]) : "r"(addr));
}
__device__ __forceinline__ void mma16816(float* d, const uint32_t* a, const uint32_t* b){
    asm volatile("mma.sync.aligned.m16n8k16.row.col.f32.bf16.bf16.f32 "
        "{%0,%1,%2,%3}, {%4,%5,%6,%7}, {%8,%9}, {%0,%1,%2,%3};"
        : "+f"(d[0]),"+f"(d[1]),"+f"(d[2]),"+f"(d[3])
        : "r"(a[0]),"r"(a[1]),"r"(a[2]),"r"(a[3]), "r"(b[0]),"r"(b[1]));
}

// ======================= mma.sync bf16-split GEMM (unchanged, passing) =======
#define TG_LD   72
#define TG_BLK  (128*TG_LD)
#define TG_SMEM (8*TG_BLK*2)

template<int MODE>
__global__ void __launch_bounds__(256,1) tgemm_k(
    const __nv_bfloat16* __restrict__ Ah, const __nv_bfloat16* __restrict__ Al,
    const __nv_bfloat16* __restrict__ Bh, const __nv_bfloat16* __restrict__ Bl,
    float* __restrict__ C, const float* __restrict__ bias,
    const float* __restrict__ bias2)
{
    extern __shared__ __align__(16) __nv_bfloat16 smb[];
    uint32_t sbase = (uint32_t)__cvta_generic_to_shared(smb);
    int tid = threadIdx.x, wid = tid>>5, lane = tid&31;
    int wm = wid>>2, wn = wid&3;
    int bn = blockIdx.x, bm = blockIdx.y, nz = blockIdx.z;

    const __nv_bfloat16 *BhP = Bh, *BlP = Bl;
    if (MODE==1){ BhP += (size_t)nz*G4 *512; BlP += (size_t)nz*G4 *512; }
    if (MODE==3){ BhP += (size_t)nz*Dsz*512; BlP += (size_t)nz*Dsz*512; }

    int lrow = tid>>1, lk = (tid&1)*32;
    int am = bm*128 + lrow;
    int ag = (MODE==3) ? ((am>>3)*128 + nz*8 + (am&7)) : am;
    const __nv_bfloat16* gAh = Ah  + (size_t)ag*512 + lk;
    const __nv_bfloat16* gAl = Al  + (size_t)ag*512 + lk;
    const __nv_bfloat16* gBh = BhP + (size_t)(bn*128 + lrow)*512 + lk;
    const __nv_bfloat16* gBl = BlP + (size_t)(bn*128 + lrow)*512 + lk;
    uint32_t sRowOff = (uint32_t)(lrow*TG_LD + lk)*2;

    int aRowL = wm*64 + (lane&15);
    int aColL = (lane>>4)*8;
    int bRowL = wn*32 + ((lane>>4)&1)*8 + (lane&7);
    int bColL = ((lane>>3)&1)*8;

    float acc[4][4][4];
    #pragma unroll
    for (int i=0;i<4;i++){
        #pragma unroll
        for (int j=0;j<4;j++){
            acc[i][j][0]=0.f; acc[i][j][1]=0.f; acc[i][j][2]=0.f; acc[i][j][3]=0.f;
        }
    }

    auto issue = [&](int s, int kb){
        uint32_t d0 = sbase + (uint32_t)((s*4+0)*TG_BLK)*2 + sRowOff;
        uint32_t d1 = sbase + (uint32_t)((s*4+1)*TG_BLK)*2 + sRowOff;
        uint32_t d2 = sbase + (uint32_t)((s*4+2)*TG_BLK)*2 + sRowOff;
        uint32_t d3 = sbase + (uint32_t)((s*4+3)*TG_BLK)*2 + sRowOff;
        #pragma unroll
        for (int i=0;i<4;i++){
            cp16(d0 + i*16, gAh + kb + i*8);
            cp16(d1 + i*16, gAl + kb + i*8);
            cp16(d2 + i*16, gBh + kb + i*8);
            cp16(d3 + i*16, gBl + kb + i*8);
        }
        cp_commit();
    };

    issue(0, 0);
    for (int c=0;c<8;c++){
        int s = c&1;
        if (c<7) issue(s^1, (c+1)*64);
        if (c<7) cp_wait<1>(); else cp_wait<0>();
        __syncthreads();

        #pragma unroll
        for (int ks=0; ks<4; ks++){
            int kc = ks*16;
            uint32_t ah[4][4], al[4][4];
            #pragma unroll
            for (int mf=0; mf<4; mf++){
                uint32_t addrh = sbase + (uint32_t)((s*4+0)*TG_BLK + (aRowL+mf*16)*TG_LD + aColL + kc)*2;
                uint32_t addrl = sbase + (uint32_t)((s*4+1)*TG_BLK + (aRowL+mf*16)*TG_LD + aColL + kc)*2;
                ldsm_x4(ah[mf], addrh);
                ldsm_x4(al[mf], addrl);
            }
            uint32_t bh[2][4], bl[2][4];
            #pragma unroll
            for (int nfh=0; nfh<2; nfh++){
                uint32_t addrh = sbase + (uint32_t)((s*4+2)*TG_BLK + (bRowL+nfh*16)*TG_LD + bColL + kc)*2;
                uint32_t addrl = sbase + (uint32_t)((s*4+3)*TG_BLK + (bRowL+nfh*16)*TG_LD + bColL + kc)*2;
                ldsm_x4(bh[nfh], addrh);
                ldsm_x4(bl[nfh], addrl);
            }
            #pragma unroll
            for (int mf=0; mf<4; mf++){
                #pragma unroll
                for (int nf=0; nf<4; nf++){
                    const uint32_t* bhp = &bh[nf>>1][(nf&1)*2];
                    const uint32_t* blp = &bl[nf>>1][(nf&1)*2];
                    mma16816(acc[mf][nf], ah[mf], bhp);
                    mma16816(acc[mf][nf], ah[mf], blp);
                    mma16816(acc[mf][nf], al[mf], bhp);
                }
            }
        }
        __syncthreads();
    }

    int rA = lane>>2, cA = (lane&3)*2;
    #pragma unroll
    for (int mf=0; mf<4; mf++){
        #pragma unroll
        for (int nf=0; nf<4; nf++){
            #pragma unroll
            for (int half=0; half<2; half++){
                int m  = bm*128 + wm*64 + mf*16 + rA + half*8;
                int jc = bn*128 + wn*32 + nf*8 + cA;
                float v0 = acc[mf][nf][half*2+0];
                float v1 = acc[mf][nf][half*2+1];
                if (MODE==1){
                    v0 += bias[nz*G4+jc]   + bias2[nz*G4+jc];
                    v1 += bias[nz*G4+jc+1] + bias2[nz*G4+jc+1];
                    int t=m>>3, b=m&7;
                    float2 w = {v0,v1};
                    *(float2*)&C[(size_t)(t*128+nz*8+b)*G4 + jc] = w;
                } else if (MODE==2){
                    v0 += bias[jc]; v1 += bias[jc+1];
                    int t=m>>3, b=m&7;
                    float2 w = {v0,v1};
                    *(float2*)&C[(size_t)(b*Ssz+t)*Vsz + jc] = w;
                } else {
                    v0 += bias[nz*Dsz+jc]; v1 += bias[nz*Dsz+jc+1];
                    float2 w = {v0,v1};
                    *(float2*)&C[(size_t)(m*Nly+nz)*Dsz + jc] = w;
                }
            }
        }
    }
}

// ---------------- fp32 -> bf16 hi/lo split -----------------------------------
__global__ void __launch_bounds__(256) split_k(const float* __restrict__ src,
                                              __nv_bfloat16* __restrict__ hi,
                                              __nv_bfloat16* __restrict__ lo,
                                              int n)
{
    int i = blockIdx.x*256 + threadIdx.x;
    if (i < n){
        float x = src[i];
        __nv_bfloat16 h = __float2bfloat16(x);
        hi[i] = h;
        lo[i] = __float2bfloat16(x - __bfloat162float(h));
    }
}

// ---------------- SIMT 128x128 GEMM (small modes 0,4,5) ----------------------
template<int MODE>
__global__ void __launch_bounds__(256, 2) gemm_k(
    const float* __restrict__ A, const float* __restrict__ Bw,
    float* __restrict__ C, const float* __restrict__ bias,
    const float* __restrict__ resid)
{
    const int K = 512;
    __shared__ float As[2][8][132];
    __shared__ float Bs[2][8][132];
    int tid = threadIdx.x;
    int bn = blockIdx.x, bm = blockIdx.y, n = blockIdx.z;

    const float* Bp = Bw;
    if (MODE==5) Bp += (size_t)n*Dsz*Rsz;

    int lRow = tid>>1, lK = (tid&1)<<2;
    const float* Aptr = A + (size_t)(bm*128+lRow)*K + lK;
    const float* Bptr;
    int b_k=0, b_j=0;
    if (MODE==5){
        b_k = tid>>5; b_j = (tid&31)<<2;
        Bptr = Bp + (size_t)b_k*Rsz + bn*128 + b_j;
    } else {
        Bptr = Bp + (size_t)(bn*128 + lRow)*K + lK;
    }
    int ty = tid>>4, tx = tid&15;
    float acc[8][8] = {};
    float4 aReg, bReg;

    aReg = *(const float4*)(Aptr);
    bReg = *(const float4*)(Bptr);
    As[0][lK+0][lRow]=aReg.x; As[0][lK+1][lRow]=aReg.y;
    As[0][lK+2][lRow]=aReg.z; As[0][lK+3][lRow]=aReg.w;
    if (MODE==5){ *(float4*)&Bs[0][b_k][b_j] = bReg; }
    else {
        Bs[0][lK+0][lRow]=bReg.x; Bs[0][lK+1][lRow]=bReg.y;
        Bs[0][lK+2][lRow]=bReg.z; Bs[0][lK+3][lRow]=bReg.w;
    }
    __syncthreads();

    int buf = 0;
    for (int kb=8; kb<=K; kb+=8){
        bool more = (kb < K);
        if (more){
            aReg = *(const float4*)(Aptr + kb);
            bReg = (MODE==5) ? *(const float4*)(Bptr + (size_t)kb*Rsz)
                             : *(const float4*)(Bptr + kb);
        }
        #pragma unroll
        for (int k=0;k<8;k++){
            float4 a0 = *(const float4*)&As[buf][k][ty<<2];
            float4 a1 = *(const float4*)&As[buf][k][(ty<<2)+64];
            float4 b0 = *(const float4*)&Bs[buf][k][tx<<2];
            float4 b1 = *(const float4*)&Bs[buf][k][(tx<<2)+64];
            float a[8]={a0.x,a0.y,a0.z,a0.w,a1.x,a1.y,a1.z,a1.w};
            float b[8]={b0.x,b0.y,b0.z,b0.w,b1.x,b1.y,b1.z,b1.w};
            #pragma unroll
            for(int i=0;i<8;i++)
                #pragma unroll
                for(int j=0;j<8;j++) acc[i][j] += a[i]*b[j];
        }
        if (more){
            int nb = buf^1;
            As[nb][lK+0][lRow]=aReg.x; As[nb][lK+1][lRow]=aReg.y;
            As[nb][lK+2][lRow]=aReg.z; As[nb][lK+3][lRow]=aReg.w;
            if (MODE==5){ *(float4*)&Bs[nb][b_k][b_j] = bReg; }
            else {
                Bs[nb][lK+0][lRow]=bReg.x; Bs[nb][lK+1][lRow]=bReg.y;
                Bs[nb][lK+2][lRow]=bReg.z; Bs[nb][lK+3][lRow]=bReg.w;
            }
            __syncthreads();
            buf = nb;
        }
    }

    #pragma unroll
    for(int i=0;i<8;i++){
        int m = bm*128 + (ty<<2) + (i&3) + ((i>>2)<<6);
        #pragma unroll
        for(int j=0;j<8;j++){
            int jc = bn*128 + (tx<<2) + (j&3) + ((j>>2)<<6);
            float v = acc[i][j];
            if (MODE==0){ v += bias[jc]; C[(size_t)m*Dsz+jc]=v; }
            else if (MODE==4){ v += bias[jc] + resid[(size_t)m*Dsz+jc]; C[(size_t)m*Dsz+jc]=v; }
            else { C[(size_t)n*Dsz*Rsz + (size_t)m*Rsz + jc]=v; }
        }
    }
}

// ---------------- embedding gather ------------------------------------------
__global__ void __launch_bounds__(256) embed_k(const int* __restrict__ x,
                                               const float* __restrict__ emb)
{
    int idx = blockIdx.x*256 + threadIdx.x;
    int m = idx>>9, d = idx&511;
    int t = m>>3, b = m&7;
    g_X[idx] = emb[(size_t)x[b*Ssz+t]*Dsz + d];
}

// ---------------- combined k/v biases ----------------------------------------
__global__ void __launch_bounds__(256) ckcv_k(const float* __restrict__ in_w,
                                              const float* __restrict__ in_b,
                                              const float* __restrict__ b_np)
{
    int idx = blockIdx.x*256 + threadIdx.x;
    int n = idx>>9, dc = idx&511;
    const float* Wk = in_w + Dsz*Dsz;
    const float* Wv = in_w + 2*Dsz*Dsz;
    const float* bn = b_np + n*Dsz;
    float sk = in_b[Dsz+dc], sv = in_b[2*Dsz+dc];
    for (int j=0;j<Dsz;j++){
        float bj = bn[j];
        sk += Wk[(size_t)dc*Dsz+j]*bj;
        sv += Wv[(size_t)dc*Dsz+j]*bj;
    }
    g_ck[idx]=sk; g_cv[idx]=sv;
}

// ---------------- persistent LSTM recurrence (HMMA bf16-split) ---------------
#define LSW 40
#define LSH 536
#define L_WSBLK (256*LSW)
#define L_OFF_HH (4*L_WSBLK*2)
#define L_OFF_HL (L_OFF_HH + 8*LSH*2)
#define L_OFF_GA (L_OFF_HL + 8*LSH*2)
#define L_OFF_CS (L_OFF_GA + 256*9*4)
#define L_OFF_GT (L_OFF_CS + 64*9*4)
#define L_SMEM   (L_OFF_GT + 8192)

__global__ void zero_bar_k(){ g_bar = 0u; }

__global__ void __launch_bounds__(256,1) lstm_mma(
    const __nv_bfloat16* __restrict__ Wh, const __nv_bfloat16* __restrict__ Wl,
    const float* __restrict__ h0, const float* __restrict__ c0,
    float* __restrict__ hfinal,
    __nv_bfloat16* __restrict__ hall_h, __nv_bfloat16* __restrict__ hall_l,
    const float* __restrict__ Gih, float* __restrict__ cfinal)
{
    extern __shared__ __align__(16) char sm[];
    uint32_t sbase = (uint32_t)__cvta_generic_to_shared(sm);
    __nv_bfloat16* hh_s = (__nv_bfloat16*)(sm + L_OFF_HH);
    __nv_bfloat16* hl_s = (__nv_bfloat16*)(sm + L_OFF_HL);
    float* ga  = (float*)(sm + L_OFF_GA);   // [256][9]
    float* cs  = (float*)(sm + L_OFF_CS);   // [64][9]
    float* gts = (float*)(sm + L_OFF_GT);   // [8][4][64] prefetched Gih slice

    int tid = threadIdx.x, wid = tid>>5, lane = tid&31;
    int chunk = blockIdx.x & 7, n = blockIdx.x >> 3;

    int m_row = tid;
    int gateT = m_row>>6, rlocT = m_row&63;
    size_t grow = (size_t)(n*G4 + gateT*512 + chunk*64 + rlocT)*512;
    const __nv_bfloat16* gWh = Wh + grow;
    const __nv_bfloat16* gWl = Wl + grow;

    for (int idx=tid; idx<512; idx+=256){
        int b = idx>>6, r = idx&63;
        cs[r*9+b] = c0[(size_t)(n*8+b)*Rsz + chunk*64 + r];
    }

    int aRow = lane&15, aCol = (lane>>4)*8;
    int bN = lane>>2, bK2 = 2*(lane&3);

    volatile unsigned* barp = &g_bar;

    for (int t=0; t<Ssz; t++){
        // ---- load h (prev) into smem hi/lo ----
        if (t==0){
            for (int idx=tid; idx<4096; idx+=256){
                int b = idx>>9, r = idx&511;
                float v = h0[(size_t)(n*8+b)*Rsz + r];
                __nv_bfloat16 h = __float2bfloat16(v);
                hh_s[b*LSH + r] = h;
                hl_s[b*LSH + r] = __float2bfloat16(v - __bfloat162float(h));
            }
        } else {
            const __nv_bfloat16* ph = hall_h + (size_t)(t-1)*NBR + (size_t)(n*8)*Rsz;
            const __nv_bfloat16* pl = hall_l + (size_t)(t-1)*NBR + (size_t)(n*8)*Rsz;
            for (int idx=tid; idx<512; idx+=256){
                int b = idx>>6, r8 = (idx&63)*8;
                *(uint4*)(hh_s + b*LSH + r8) = *(const uint4*)(ph + b*Rsz + r8);
                *(uint4*)(hl_s + b*LSH + r8) = *(const uint4*)(pl + b*Rsz + r8);
            }
        }
        __syncthreads();

        auto issueW = [&](int kc, int s){
            uint32_t dh = sbase + (uint32_t)((s*2+0)*L_WSBLK + m_row*LSW)*2;
            uint32_t dl = sbase + (uint32_t)((s*2+1)*L_WSBLK + m_row*LSW)*2;
            const __nv_bfloat16* sh = gWh + kc*32;
            const __nv_bfloat16* sl = gWl + kc*32;
            #pragma unroll
            for (int i=0;i<4;i++){
                cp16(dh + i*16, sh + i*8);
                cp16(dl + i*16, sl + i*8);
            }
            cp_commit();
        };

        float acc[2][4];
        #pragma unroll
        for (int f=0;f<2;f++){ acc[f][0]=0.f; acc[f][1]=0.f; acc[f][2]=0.f; acc[f][3]=0.f; }

        // Gt prefetch joins group of W stage 0
        {
            const float* GtBase = Gih + (size_t)t*Nly*Bsz*G4 + (size_t)(n*8)*G4 + chunk*64;
            #pragma unroll
            for (int jj=0; jj<2; jj++){
                int j = tid + jj*256;
                int b = j>>6, gate = (j>>4)&3, quad = j&15;
                cp16(sbase + L_OFF_GT + (uint32_t)j*16,
                     GtBase + (size_t)b*G4 + gate*512 + quad*4);
            }
        }
        issueW(0,0); issueW(1,1);
        for (int kc=0; kc<16; kc++){
            int s = kc&1;
            if (kc==15) cp_wait<0>(); else cp_wait<1>();
            __syncthreads();
            #pragma unroll
            for (int kf=0; kf<2; kf++){
                int kbase = kc*32 + kf*16;
                uint32_t bhr[2], blr[2];
                uint32_t hoff = (uint32_t)(bN*LSH + kbase + bK2)*2;
                bhr[0] = *(const uint32_t*)(sm + L_OFF_HH + hoff);
                bhr[1] = *(const uint32_t*)(sm + L_OFF_HH + hoff + 16);
                blr[0] = *(const uint32_t*)(sm + L_OFF_HL + hoff);
                blr[1] = *(const uint32_t*)(sm + L_OFF_HL + hoff + 16);
                #pragma unroll
                for (int f=0; f<2; f++){
                    int mbase = wid*32 + f*16;
                    uint32_t ah[4], al[4];
                    uint32_t wadr = (uint32_t)((mbase + aRow)*LSW + kf*16 + aCol)*2;
                    ldsm_x4(ah, sbase + (uint32_t)((s*2+0)*L_WSBLK)*2 + wadr);
                    ldsm_x4(al, sbase + (uint32_t)((s*2+1)*L_WSBLK)*2 + wadr);
                    mma16816(acc[f], ah, bhr);
                    mma16816(acc[f], ah, blr);
                    mma16816(acc[f], al, bhr);
                }
            }
            __syncthreads();
            if (kc+2 < 16) issueW(kc+2, s);
        }

        // ---- gates to smem ----
        int rA = lane>>2, cB = 2*(lane&3);
        #pragma unroll
        for (int f=0; f<2; f++){
            int m = wid*32 + f*16 + rA;
            ga[m*9 + cB]       = acc[f][0];
            ga[m*9 + cB + 1]   = acc[f][1];
            ga[(m+8)*9 + cB]   = acc[f][2];
            ga[(m+8)*9 + cB+1] = acc[f][3];
        }
        __syncthreads();

        // ---- elementwise LSTM + h split writeback (Gih from smem) ----
        for (int idx=tid; idx<512; idx+=256){
            int b = idx>>6, r = idx&63;
            float iv = ga[(      r)*9 + b] + gts[b*256       + r];
            float fv = ga[( 64 + r)*9 + b] + gts[b*256 +  64 + r];
            float gv = ga[(128 + r)*9 + b] + gts[b*256 + 128 + r];
            float ov = ga[(192 + r)*9 + b] + gts[b*256 + 192 + r];
            float cp = cs[r*9+b];
            float cn = sigm(fv)*cp + sigm(iv)*tanhf(gv);
            cs[r*9+b] = cn;
            float hv = sigm(ov)*tanhf(cn);
            size_t ho = (size_t)t*NBR + (size_t)(n*8+b)*Rsz + chunk*64 + r;
            __nv_bfloat16 hh = __float2bfloat16(hv);
            hall_h[ho] = hh;
            hall_l[ho] = __float2bfloat16(hv - __bfloat162float(hh));
            if (t == Ssz-1)
                hfinal[(size_t)(n*8+b)*Rsz + chunk*64 + r] = hv;
        }
        __threadfence();
        __syncthreads();
        // grid barrier: atomic arrival, volatile-load polling (no atomic poll)
        if (tid==0){
            atomicAdd(&g_bar, 1u);
            unsigned target = 128u*(unsigned)(t+1);
            while (*barp < target) { }
            __threadfence();
        }
        __syncthreads();
    }

    for (int idx=tid; idx<512; idx+=256){
        int b = idx>>6, r = idx&63;
        cfinal[(size_t)(n*8+b)*Rsz + chunk*64 + r] = cs[r*9+b];
    }
}

// ---------------- attention per token ----------------------------------------
__global__ void __launch_bounds__(256) attn_k()
{
    int m = blockIdx.x, tid = threadIdx.x;
    __shared__ float sq[512];
    __shared__ float sc[8][16];
    __shared__ float sw[8][16];
    sq[tid]     = g_q[(size_t)m*Dsz + tid];
    sq[tid+256] = g_q[(size_t)m*Dsz + tid + 256];
    __syncthreads();
    if (tid < 128){
        int h = tid>>4, nn = tid&15;
        const float* kp = g_k + (size_t)(m*Nly+nn)*Dsz + h*64;
        float s = 0.f;
        #pragma unroll 8
        for (int e=0;e<64;e++) s += sq[h*64+e]*kp[e];
        sc[h][nn] = s*0.125f;
    }
    __syncthreads();
    if (tid < 8){
        float mx = -1e30f;
        for (int nn=0;nn<16;nn++) mx = fmaxf(mx, sc[tid][nn]);
        float e[16], sum = 0.f;
        for (int nn=0;nn<16;nn++){ e[nn]=expf(sc[tid][nn]-mx); sum+=e[nn]; }
        float inv = 1.f/sum;
        for (int nn=0;nn<16;nn++) sw[tid][nn]=e[nn]*inv;
    }
    __syncthreads();
    for (int idx=tid; idx<512; idx+=256){
        int h = idx>>6;
        float s = 0.f;
        #pragma unroll
        for (int nn=0;nn<16;nn++)
            s += sw[h][nn]*g_v[(size_t)(m*Nly+nn)*Dsz + idx];
        g_att[(size_t)m*Dsz + idx] = s;
    }
}

// ---------------- layernorm (in-place on g_mix) ------------------------------
__global__ void __launch_bounds__(256) ln_k(const float* __restrict__ gam,
                                            const float* __restrict__ bet)
{
    int m = blockIdx.x, tid = threadIdx.x;
    __shared__ float sh[8];
    __shared__ float sh2[8];
    float* row = g_mix + (size_t)m*Dsz;
    float v0 = row[tid], v1 = row[tid+256];
    int lane = tid&31, w = tid>>5;

    float s = v0+v1;
    #pragma unroll
    for (int o=16;o>0;o>>=1) s += __shfl_xor_sync(0xffffffffu, s, o);
    if (lane==0) sh[w]=s;
    __syncthreads();
    float tot = sh[0]+sh[1]+sh[2]+sh[3]+sh[4]+sh[5]+sh[6]+sh[7];
    float mu = tot*(1.f/512.f);

    float d0=v0-mu, d1=v1-mu;
    float s2 = d0*d0+d1*d1;
    #pragma unroll
    for (int o=16;o>0;o>>=1) s2 += __shfl_xor_sync(0xffffffffu, s2, o);
    if (lane==0) sh2[w]=s2;
    __syncthreads();
    float tot2 = sh2[0]+sh2[1]+sh2[2]+sh2[3]+sh2[4]+sh2[5]+sh2[6]+sh2[7];
    float inv = rsqrtf(tot2*(1.f/512.f) + 1e-5f);

    row[tid]     = d0*inv*gam[tid]     + bet[tid];
    row[tid+256] = d1*inv*gam[tid+256] + bet[tid+256];
}

// ---------------- final state copy ------------------------------------------
__global__ void __launch_bounds__(256) copyhc_k(const float* __restrict__ hf,
                                                const float* __restrict__ cf,
                                                float* __restrict__ out)
{
    int idx = blockIdx.x*256 + threadIdx.x;
    const size_t L = (size_t)Bsz*Ssz*Vsz;
    out[L + idx]       = hf[idx];
    out[L + NBR + idx] = cf[idx];
}

// =============================================================================
extern "C" void kernel_launch(void* const* d_in, const int* in_sizes, int n_in,
                              void* d_out, int out_size)
{
    const int*   x      = (const int*)  d_in[0];
    const float* h0     = (const float*)d_in[1];
    const float* c0     = (const float*)d_in[2];
    const float* emb    = (const float*)d_in[3];
    const float* W_ih   = (const float*)d_in[4];
    const float* b_ih   = (const float*)d_in[5];
    const float* W_hh   = (const float*)d_in[6];
    const float* b_hh   = (const float*)d_in[7];
    const float* W_np   = (const float*)d_in[8];
    const float* b_np   = (const float*)d_in[9];
    const float* in_w   = (const float*)d_in[10];
    const float* in_b   = (const float*)d_in[11];
    const float* op_w   = (const float*)d_in[12];
    const float* op_b   = (const float*)d_in[13];
    const float* ln_g   = (const float*)d_in[14];
    const float* ln_b   = (const float*)d_in[15];
    const float* head_w = (const float*)d_in[16];
    const float* head_b = (const float*)d_in[17];
    float* out = (float*)d_out;

    cudaFuncSetAttribute(tgemm_k<1>, cudaFuncAttributeMaxDynamicSharedMemorySize, TG_SMEM);
    cudaFuncSetAttribute(tgemm_k<2>, cudaFuncAttributeMaxDynamicSharedMemorySize, TG_SMEM);
    cudaFuncSetAttribute(tgemm_k<3>, cudaFuncAttributeMaxDynamicSharedMemorySize, TG_SMEM);
    cudaFuncSetAttribute(lstm_mma,   cudaFuncAttributeMaxDynamicSharedMemorySize, L_SMEM);

    float *pX,*pGih,*pHall,*pCf,*pQ,*pWnk,*pWnv,*pCk,*pCv,*pK,*pV,*pAtt,*pMix;
    __nv_bfloat16 *pWihH,*pWihL,*pWhhH,*pWhhL,*pHeadH,*pHeadL,*pXH,*pXL,*pHallH,*pHallL;
    __nv_bfloat16 *pWnkH,*pWnkL,*pWnvH,*pWnvL,*pMixH,*pMixL;
    cudaGetSymbolAddress((void**)&pX,    g_X);
    cudaGetSymbolAddress((void**)&pGih,  g_Gih);
    cudaGetSymbolAddress((void**)&pHall, g_hall);
    cudaGetSymbolAddress((void**)&pCf,   g_cf);
    cudaGetSymbolAddress((void**)&pQ,    g_q);
    cudaGetSymbolAddress((void**)&pWnk,  g_Wnk);
    cudaGetSymbolAddress((void**)&pWnv,  g_Wnv);
    cudaGetSymbolAddress((void**)&pCk,   g_ck);
    cudaGetSymbolAddress((void**)&pCv,   g_cv);
    cudaGetSymbolAddress((void**)&pK,    g_k);
    cudaGetSymbolAddress((void**)&pV,    g_v);
    cudaGetSymbolAddress((void**)&pAtt,  g_att);
    cudaGetSymbolAddress((void**)&pMix,  g_mix);
    cudaGetSymbolAddress((void**)&pWihH, bWih_h);  cudaGetSymbolAddress((void**)&pWihL, bWih_l);
    cudaGetSymbolAddress((void**)&pWhhH, bWhh_h);  cudaGetSymbolAddress((void**)&pWhhL, bWhh_l);
    cudaGetSymbolAddress((void**)&pHeadH,bHead_h); cudaGetSymbolAddress((void**)&pHeadL,bHead_l);
    cudaGetSymbolAddress((void**)&pXH,   bX_h);    cudaGetSymbolAddress((void**)&pXL,   bX_l);
    cudaGetSymbolAddress((void**)&pHallH,bHall_h); cudaGetSymbolAddress((void**)&pHallL,bHall_l);
    cudaGetSymbolAddress((void**)&pWnkH, bWnk_h);  cudaGetSymbolAddress((void**)&pWnkL, bWnk_l);
    cudaGetSymbolAddress((void**)&pWnvH, bWnv_h);  cudaGetSymbolAddress((void**)&pWnvL, bWnv_l);
    cudaGetSymbolAddress((void**)&pMixH, bMix_h);  cudaGetSymbolAddress((void**)&pMixL, bMix_l);

    // Phase 0/1 reordered: 4th launch (index 3) = tgemm_k<1> for ncu capture
    embed_k<<<(Mtok*Dsz)/256, 256>>>(x, emb);                              // 0
    split_k<<<(Mtok*Dsz)/256,256>>>(pX, pXH, pXL, Mtok*Dsz);               // 1
    split_k<<<(Nly*G4*Dsz)/256,256>>>(W_ih, pWihH, pWihL, Nly*G4*Dsz);     // 2
    tgemm_k<1><<<dim3(16,16,16),256,TG_SMEM>>>(pXH,pXL,pWihH,pWihL,pGih,b_ih,b_hh); // 3 <- profiled
    split_k<<<(Nly*G4*Dsz)/256,256>>>(W_hh, pWhhH, pWhhL, Nly*G4*Dsz);
    split_k<<<(Vsz*Dsz)/256,256>>>(head_w, pHeadH, pHeadL, Vsz*Dsz);
    gemm_k<0><<<dim3(4,16),256>>>(pX, in_w, pQ, in_b, nullptr);
    gemm_k<5><<<dim3(4,4,16),256>>>(in_w +   Dsz*Dsz, W_np, pWnk, nullptr, nullptr);
    gemm_k<5><<<dim3(4,4,16),256>>>(in_w + 2*Dsz*Dsz, W_np, pWnv, nullptr, nullptr);
    split_k<<<(Nly*Dsz*Rsz)/256,256>>>(pWnk, pWnkH, pWnkL, Nly*Dsz*Rsz);
    split_k<<<(Nly*Dsz*Rsz)/256,256>>>(pWnv, pWnvH, pWnvL, Nly*Dsz*Rsz);
    ckcv_k<<<(Nly*Dsz)/256, 256>>>(in_w, in_b, b_np);

    // Phase 2: persistent recurrence (HMMA, grid barrier per step)
    zero_bar_k<<<1,1>>>();
    lstm_mma<<<128,256,L_SMEM>>>(pWhhH, pWhhL, h0, c0, pHall, pHallH, pHallL, pGih, pCf);

    // Phase 3: k/v (tensor, directly from bHall), attention, out-proj, LN, head
    tgemm_k<3><<<dim3(4,16,16),256,TG_SMEM>>>(pHallH,pHallL,pWnkH,pWnkL,pK,pCk,nullptr);
    tgemm_k<3><<<dim3(4,16,16),256,TG_SMEM>>>(pHallH,pHallL,pWnvH,pWnvL,pV,pCv,nullptr);
    attn_k<<<Mtok,256>>>();
    gemm_k<4><<<dim3(4,16),256>>>(pAtt, op_w, pMix, op_b, pX);
    ln_k<<<Mtok,256>>>(ln_g, ln_b);
    split_k<<<(Mtok*Dsz)/256,256>>>(pMix, pMixH, pMixL, Mtok*Dsz);
    tgemm_k<2><<<dim3(250,16),256,TG_SMEM>>>(pMixH,pMixL,pHeadH,pHeadL,out,head_b,nullptr);

    // hf / cf
    copyhc_k<<<NBR/256,256>>>(pHall, pCf, out);
}

// round 11
// speedup vs baseline: 1.6316x; 1.0088x over previous
#include <cuda_runtime.h>
#include <cuda_bf16.h>
#include <math.h>
#include <stdint.h>

// Problem dims
#define Bsz 8
#define Ssz 256
#define Vsz 32000
#define Dsz 512
#define Nly 16
#define Rsz 512
#define G4  2048            // 4*R
#define Mtok (Bsz*Ssz)      // 2048 tokens
#define NBR (Nly*Bsz*Rsz)   // 65536

// ---------------- scratch (static device globals; no runtime alloc) ----------
__device__ float g_X   [Mtok*Dsz];
__device__ float g_Gih [(size_t)Ssz*Nly*Bsz*G4];         // [t][n][b][g]
__device__ float g_hall[NBR];                            // final-step h only (hf)
__device__ float g_cf  [NBR];
__device__ float g_q   [Mtok*Dsz];
__device__ float g_Wnk [Nly*Dsz*Rsz];
__device__ float g_Wnv [Nly*Dsz*Rsz];
__device__ float g_ck  [Nly*Dsz];
__device__ float g_cv  [Nly*Dsz];
__device__ float g_k   [(size_t)Mtok*Nly*Dsz];
__device__ float g_v   [(size_t)Mtok*Nly*Dsz];
__device__ float g_att [Mtok*Dsz];
__device__ float g_mix [Mtok*Dsz];
__device__ unsigned g_bar;

// bf16 split buffers (hi + lo)
__device__ __align__(16) __nv_bfloat16 bWih_h [(size_t)Nly*G4*Dsz];
__device__ __align__(16) __nv_bfloat16 bWih_l [(size_t)Nly*G4*Dsz];
__device__ __align__(16) __nv_bfloat16 bWhh_h [(size_t)Nly*G4*Dsz];
__device__ __align__(16) __nv_bfloat16 bWhh_l [(size_t)Nly*G4*Dsz];
__device__ __align__(16) __nv_bfloat16 bHead_h[(size_t)Vsz*Dsz];
__device__ __align__(16) __nv_bfloat16 bHead_l[(size_t)Vsz*Dsz];
__device__ __align__(16) __nv_bfloat16 bX_h   [Mtok*Dsz];
__device__ __align__(16) __nv_bfloat16 bX_l   [Mtok*Dsz];
__device__ __align__(16) __nv_bfloat16 bHall_h[(size_t)Ssz*NBR];
__device__ __align__(16) __nv_bfloat16 bHall_l[(size_t)Ssz*NBR];
__device__ __align__(16) __nv_bfloat16 bWnk_h [Nly*Dsz*Rsz];
__device__ __align__(16) __nv_bfloat16 bWnk_l [Nly*Dsz*Rsz];
__device__ __align__(16) __nv_bfloat16 bWnv_h [Nly*Dsz*Rsz];
__device__ __align__(16) __nv_bfloat16 bWnv_l [Nly*Dsz*Rsz];
__device__ __align__(16) __nv_bfloat16 bMix_h [Mtok*Dsz];
__device__ __align__(16) __nv_bfloat16 bMix_l [Mtok*Dsz];

__device__ __forceinline__ float sigm(float x){ return 1.f/(1.f+expf(-x)); }

// ======================= PTX helpers (compute_103-safe) ======================
__device__ __forceinline__ void cp16(uint32_t sdst, const void* gsrc){
    asm volatile("cp.async.cg.shared.global [%0], [%1], 16;" :: "r"(sdst), "l"(gsrc));
}
__device__ __forceinline__ void cp_commit(){
    asm volatile("cp.async.commit_group;" ::: "memory");
}
template<int N>
__device__ __forceinline__ void cp_wait(){
    asm volatile("cp.async.wait_group %0;" :: "n"(N) : "memory");
}
__device__ __forceinline__ void ldsm_x4(uint32_t* r, uint32_t addr){
    asm volatile("ldmatrix.sync.aligned.m8n8.x4.shared.b16 {%0,%1,%2,%3}, [%4];"
        : "=r"(r[0]),"=r"(r[1]),"=r"(r[2]),"=r"(r[3]) : "r"(addr));
}
__device__ __forceinline__ void mma16816(float* d, const uint32_t* a, const uint32_t* b){
    asm volatile("mma.sync.aligned.m16n8k16.row.col.f32.bf16.bf16.f32 "
        "{%0,%1,%2,%3}, {%4,%5,%6,%7}, {%8,%9}, {%0,%1,%2,%3};"
        : "+f"(d[0]),"+f"(d[1]),"+f"(d[2]),"+f"(d[3])
        : "r"(a[0]),"r"(a[1]),"r"(a[2]),"r"(a[3]), "r"(b[0]),"r"(b[1]));
}

// ======================= mma.sync bf16-split GEMM (unchanged, passing) =======
#define TG_LD   72
#define TG_BLK  (128*TG_LD)
#define TG_SMEM (8*TG_BLK*2)

template<int MODE>
__global__ void __launch_bounds__(256,1) tgemm_k(
    const __nv_bfloat16* __restrict__ Ah, const __nv_bfloat16* __restrict__ Al,
    const __nv_bfloat16* __restrict__ Bh, const __nv_bfloat16* __restrict__ Bl,
    float* __restrict__ C, const float* __restrict__ bias,
    const float* __restrict__ bias2)
{
    extern __shared__ __align__(16) __nv_bfloat16 smb[];
    uint32_t sbase = (uint32_t)__cvta_generic_to_shared(smb);
    int tid = threadIdx.x, wid = tid>>5, lane = tid&31;
    int wm = wid>>2, wn = wid&3;
    int bn = blockIdx.x, bm = blockIdx.y, nz = blockIdx.z;

    const __nv_bfloat16 *BhP = Bh, *BlP = Bl;
    if (MODE==1){ BhP += (size_t)nz*G4 *512; BlP += (size_t)nz*G4 *512; }
    if (MODE==3){ BhP += (size_t)nz*Dsz*512; BlP += (size_t)nz*Dsz*512; }

    int lrow = tid>>1, lk = (tid&1)*32;
    int am = bm*128 + lrow;
    int ag = (MODE==3) ? ((am>>3)*128 + nz*8 + (am&7)) : am;
    const __nv_bfloat16* gAh = Ah  + (size_t)ag*512 + lk;
    const __nv_bfloat16* gAl = Al  + (size_t)ag*512 + lk;
    const __nv_bfloat16* gBh = BhP + (size_t)(bn*128 + lrow)*512 + lk;
    const __nv_bfloat16* gBl = BlP + (size_t)(bn*128 + lrow)*512 + lk;
    uint32_t sRowOff = (uint32_t)(lrow*TG_LD + lk)*2;

    int aRowL = wm*64 + (lane&15);
    int aColL = (lane>>4)*8;
    int bRowL = wn*32 + ((lane>>4)&1)*8 + (lane&7);
    int bColL = ((lane>>3)&1)*8;

    float acc[4][4][4];
    #pragma unroll
    for (int i=0;i<4;i++){
        #pragma unroll
        for (int j=0;j<4;j++){
            acc[i][j][0]=0.f; acc[i][j][1]=0.f; acc[i][j][2]=0.f; acc[i][j][3]=0.f;
        }
    }

    auto issue = [&](int s, int kb){
        uint32_t d0 = sbase + (uint32_t)((s*4+0)*TG_BLK)*2 + sRowOff;
        uint32_t d1 = sbase + (uint32_t)((s*4+1)*TG_BLK)*2 + sRowOff;
        uint32_t d2 = sbase + (uint32_t)((s*4+2)*TG_BLK)*2 + sRowOff;
        uint32_t d3 = sbase + (uint32_t)((s*4+3)*TG_BLK)*2 + sRowOff;
        #pragma unroll
        for (int i=0;i<4;i++){
            cp16(d0 + i*16, gAh + kb + i*8);
            cp16(d1 + i*16, gAl + kb + i*8);
            cp16(d2 + i*16, gBh + kb + i*8);
            cp16(d3 + i*16, gBl + kb + i*8);
        }
        cp_commit();
    };

    issue(0, 0);
    for (int c=0;c<8;c++){
        int s = c&1;
        if (c<7) issue(s^1, (c+1)*64);
        if (c<7) cp_wait<1>(); else cp_wait<0>();
        __syncthreads();

        #pragma unroll
        for (int ks=0; ks<4; ks++){
            int kc = ks*16;
            uint32_t ah[4][4], al[4][4];
            #pragma unroll
            for (int mf=0; mf<4; mf++){
                uint32_t addrh = sbase + (uint32_t)((s*4+0)*TG_BLK + (aRowL+mf*16)*TG_LD + aColL + kc)*2;
                uint32_t addrl = sbase + (uint32_t)((s*4+1)*TG_BLK + (aRowL+mf*16)*TG_LD + aColL + kc)*2;
                ldsm_x4(ah[mf], addrh);
                ldsm_x4(al[mf], addrl);
            }
            uint32_t bh[2][4], bl[2][4];
            #pragma unroll
            for (int nfh=0; nfh<2; nfh++){
                uint32_t addrh = sbase + (uint32_t)((s*4+2)*TG_BLK + (bRowL+nfh*16)*TG_LD + bColL + kc)*2;
                uint32_t addrl = sbase + (uint32_t)((s*4+3)*TG_BLK + (bRowL+nfh*16)*TG_LD + bColL + kc)*2;
                ldsm_x4(bh[nfh], addrh);
                ldsm_x4(bl[nfh], addrl);
            }
            #pragma unroll
            for (int mf=0; mf<4; mf++){
                #pragma unroll
                for (int nf=0; nf<4; nf++){
                    const uint32_t* bhp = &bh[nf>>1][(nf&1)*2];
                    const uint32_t* blp = &bl[nf>>1][(nf&1)*2];
                    mma16816(acc[mf][nf], ah[mf], bhp);
                    mma16816(acc[mf][nf], ah[mf], blp);
                    mma16816(acc[mf][nf], al[mf], bhp);
                }
            }
        }
        __syncthreads();
    }

    int rA = lane>>2, cA = (lane&3)*2;
    #pragma unroll
    for (int mf=0; mf<4; mf++){
        #pragma unroll
        for (int nf=0; nf<4; nf++){
            #pragma unroll
            for (int half=0; half<2; half++){
                int m  = bm*128 + wm*64 + mf*16 + rA + half*8;
                int jc = bn*128 + wn*32 + nf*8 + cA;
                float v0 = acc[mf][nf][half*2+0];
                float v1 = acc[mf][nf][half*2+1];
                if (MODE==1){
                    v0 += bias[nz*G4+jc]   + bias2[nz*G4+jc];
                    v1 += bias[nz*G4+jc+1] + bias2[nz*G4+jc+1];
                    int t=m>>3, b=m&7;
                    float2 w = {v0,v1};
                    *(float2*)&C[(size_t)(t*128+nz*8+b)*G4 + jc] = w;
                } else if (MODE==2){
                    v0 += bias[jc]; v1 += bias[jc+1];
                    int t=m>>3, b=m&7;
                    float2 w = {v0,v1};
                    *(float2*)&C[(size_t)(b*Ssz+t)*Vsz + jc] = w;
                } else {
                    v0 += bias[nz*Dsz+jc]; v1 += bias[nz*Dsz+jc+1];
                    float2 w = {v0,v1};
                    *(float2*)&C[(size_t)(m*Nly+nz)*Dsz + jc] = w;
                }
            }
        }
    }
}

// ---------------- fp32 -> bf16 hi/lo split -----------------------------------
__global__ void __launch_bounds__(256) split_k(const float* __restrict__ src,
                                              __nv_bfloat16* __restrict__ hi,
                                              __nv_bfloat16* __restrict__ lo,
                                              int n)
{
    int i = blockIdx.x*256 + threadIdx.x;
    if (i < n){
        float x = src[i];
        __nv_bfloat16 h = __float2bfloat16(x);
        hi[i] = h;
        lo[i] = __float2bfloat16(x - __bfloat162float(h));
    }
}

// ---------------- fused: embedding gather + bf16 split -----------------------
__global__ void __launch_bounds__(256) embed_split_k(const int* __restrict__ x,
                                                     const float* __restrict__ emb)
{
    int idx = blockIdx.x*256 + threadIdx.x;
    int m = idx>>9, d = idx&511;
    int t = m>>3, b = m&7;
    float v = emb[(size_t)x[b*Ssz+t]*Dsz + d];
    g_X[idx] = v;
    __nv_bfloat16 h = __float2bfloat16(v);
    bX_h[idx] = h;
    bX_l[idx] = __float2bfloat16(v - __bfloat162float(h));
}

// ---------------- fused: split Wih + Whh + zero grid barrier -----------------
__global__ void __launch_bounds__(256) splitW2_k(const float* __restrict__ s1,
                                                 __nv_bfloat16* __restrict__ h1,
                                                 __nv_bfloat16* __restrict__ l1,
                                                 const float* __restrict__ s2,
                                                 __nv_bfloat16* __restrict__ h2,
                                                 __nv_bfloat16* __restrict__ l2,
                                                 int n)
{
    int i = blockIdx.x*256 + threadIdx.x;
    if (i == 0) g_bar = 0u;
    if (i < n){
        float x = s1[i];
        __nv_bfloat16 h = __float2bfloat16(x);
        h1[i] = h;
        l1[i] = __float2bfloat16(x - __bfloat162float(h));
    } else {
        int j = i - n;
        float x = s2[j];
        __nv_bfloat16 h = __float2bfloat16(x);
        h2[j] = h;
        l2[j] = __float2bfloat16(x - __bfloat162float(h));
    }
}

// ---------------- SIMT 128x128 GEMM (small modes 0,4,5) ----------------------
template<int MODE>
__global__ void __launch_bounds__(256, 2) gemm_k(
    const float* __restrict__ A, const float* __restrict__ Bw,
    float* __restrict__ C, const float* __restrict__ bias,
    const float* __restrict__ resid)
{
    const int K = 512;
    __shared__ float As[2][8][132];
    __shared__ float Bs[2][8][132];
    int tid = threadIdx.x;
    int bn = blockIdx.x, bm = blockIdx.y, n = blockIdx.z;

    const float* Bp = Bw;
    if (MODE==5) Bp += (size_t)n*Dsz*Rsz;

    int lRow = tid>>1, lK = (tid&1)<<2;
    const float* Aptr = A + (size_t)(bm*128+lRow)*K + lK;
    const float* Bptr;
    int b_k=0, b_j=0;
    if (MODE==5){
        b_k = tid>>5; b_j = (tid&31)<<2;
        Bptr = Bp + (size_t)b_k*Rsz + bn*128 + b_j;
    } else {
        Bptr = Bp + (size_t)(bn*128 + lRow)*K + lK;
    }
    int ty = tid>>4, tx = tid&15;
    float acc[8][8] = {};
    float4 aReg, bReg;

    aReg = *(const float4*)(Aptr);
    bReg = *(const float4*)(Bptr);
    As[0][lK+0][lRow]=aReg.x; As[0][lK+1][lRow]=aReg.y;
    As[0][lK+2][lRow]=aReg.z; As[0][lK+3][lRow]=aReg.w;
    if (MODE==5){ *(float4*)&Bs[0][b_k][b_j] = bReg; }
    else {
        Bs[0][lK+0][lRow]=bReg.x; Bs[0][lK+1][lRow]=bReg.y;
        Bs[0][lK+2][lRow]=bReg.z; Bs[0][lK+3][lRow]=bReg.w;
    }
    __syncthreads();

    int buf = 0;
    for (int kb=8; kb<=K; kb+=8){
        bool more = (kb < K);
        if (more){
            aReg = *(const float4*)(Aptr + kb);
            bReg = (MODE==5) ? *(const float4*)(Bptr + (size_t)kb*Rsz)
                             : *(const float4*)(Bptr + kb);
        }
        #pragma unroll
        for (int k=0;k<8;k++){
            float4 a0 = *(const float4*)&As[buf][k][ty<<2];
            float4 a1 = *(const float4*)&As[buf][k][(ty<<2)+64];
            float4 b0 = *(const float4*)&Bs[buf][k][tx<<2];
            float4 b1 = *(const float4*)&Bs[buf][k][(tx<<2)+64];
            float a[8]={a0.x,a0.y,a0.z,a0.w,a1.x,a1.y,a1.z,a1.w};
            float b[8]={b0.x,b0.y,b0.z,b0.w,b1.x,b1.y,b1.z,b1.w};
            #pragma unroll
            for(int i=0;i<8;i++)
                #pragma unroll
                for(int j=0;j<8;j++) acc[i][j] += a[i]*b[j];
        }
        if (more){
            int nb = buf^1;
            As[nb][lK+0][lRow]=aReg.x; As[nb][lK+1][lRow]=aReg.y;
            As[nb][lK+2][lRow]=aReg.z; As[nb][lK+3][lRow]=aReg.w;
            if (MODE==5){ *(float4*)&Bs[nb][b_k][b_j] = bReg; }
            else {
                Bs[nb][lK+0][lRow]=bReg.x; Bs[nb][lK+1][lRow]=bReg.y;
                Bs[nb][lK+2][lRow]=bReg.z; Bs[nb][lK+3][lRow]=bReg.w;
            }
            __syncthreads();
            buf = nb;
        }
    }

    #pragma unroll
    for(int i=0;i<8;i++){
        int m = bm*128 + (ty<<2) + (i&3) + ((i>>2)<<6);
        #pragma unroll
        for(int j=0;j<8;j++){
            int jc = bn*128 + (tx<<2) + (j&3) + ((j>>2)<<6);
            float v = acc[i][j];
            if (MODE==0){ v += bias[jc]; C[(size_t)m*Dsz+jc]=v; }
            else if (MODE==4){ v += bias[jc] + resid[(size_t)m*Dsz+jc]; C[(size_t)m*Dsz+jc]=v; }
            else { C[(size_t)n*Dsz*Rsz + (size_t)m*Rsz + jc]=v; }
        }
    }
}

// ---------------- combined k/v biases ----------------------------------------
__global__ void __launch_bounds__(256) ckcv_k(const float* __restrict__ in_w,
                                              const float* __restrict__ in_b,
                                              const float* __restrict__ b_np)
{
    int idx = blockIdx.x*256 + threadIdx.x;
    int n = idx>>9, dc = idx&511;
    const float* Wk = in_w + Dsz*Dsz;
    const float* Wv = in_w + 2*Dsz*Dsz;
    const float* bn = b_np + n*Dsz;
    float sk = in_b[Dsz+dc], sv = in_b[2*Dsz+dc];
    for (int j=0;j<Dsz;j++){
        float bj = bn[j];
        sk += Wk[(size_t)dc*Dsz+j]*bj;
        sv += Wv[(size_t)dc*Dsz+j]*bj;
    }
    g_ck[idx]=sk; g_cv[idx]=sv;
}

// ---------------- persistent LSTM recurrence (HMMA, 4-stage pipeline) --------
#define LSW 40
#define LSH 536
#define L_WSBLK (256*LSW)
#define L_NSTG 4
#define L_OFF_HH (2*L_NSTG*L_WSBLK*2)
#define L_OFF_HL (L_OFF_HH + 8*LSH*2)
#define L_OFF_GA (L_OFF_HL + 8*LSH*2)
#define L_OFF_CS (L_OFF_GA + 256*9*4)
#define L_OFF_GT (L_OFF_CS + 64*9*4)
#define L_SMEM   (L_OFF_GT + 8192)

__global__ void __launch_bounds__(256,1) lstm_mma(
    const __nv_bfloat16* __restrict__ Wh, const __nv_bfloat16* __restrict__ Wl,
    const float* __restrict__ h0, const float* __restrict__ c0,
    float* __restrict__ hfinal,
    __nv_bfloat16* __restrict__ hall_h, __nv_bfloat16* __restrict__ hall_l,
    const float* __restrict__ Gih, float* __restrict__ cfinal)
{
    extern __shared__ __align__(16) char sm[];
    uint32_t sbase = (uint32_t)__cvta_generic_to_shared(sm);
    __nv_bfloat16* hh_s = (__nv_bfloat16*)(sm + L_OFF_HH);
    __nv_bfloat16* hl_s = (__nv_bfloat16*)(sm + L_OFF_HL);
    float* ga  = (float*)(sm + L_OFF_GA);   // [256][9]
    float* cs  = (float*)(sm + L_OFF_CS);   // [64][9]
    float* gts = (float*)(sm + L_OFF_GT);   // [8][4][64] prefetched Gih slice

    int tid = threadIdx.x, wid = tid>>5, lane = tid&31;
    int chunk = blockIdx.x & 7, n = blockIdx.x >> 3;

    int m_row = tid;
    int gateT = m_row>>6, rlocT = m_row&63;
    size_t grow = (size_t)(n*G4 + gateT*512 + chunk*64 + rlocT)*512;
    const __nv_bfloat16* gWh = Wh + grow;
    const __nv_bfloat16* gWl = Wl + grow;

    for (int idx=tid; idx<512; idx+=256){
        int b = idx>>6, r = idx&63;
        cs[r*9+b] = c0[(size_t)(n*8+b)*Rsz + chunk*64 + r];
    }

    int aRow = lane&15, aCol = (lane>>4)*8;
    int bN = lane>>2, bK2 = 2*(lane&3);

    volatile unsigned* barp = &g_bar;

    // W chunk kc (32 k-elts) -> stage kc&3 (hi part 0, lo part 1)
    auto issueW = [&](int kc, int s){
        uint32_t dh = sbase + (uint32_t)((s*2+0)*L_WSBLK + m_row*LSW)*2;
        uint32_t dl = sbase + (uint32_t)((s*2+1)*L_WSBLK + m_row*LSW)*2;
        const __nv_bfloat16* sh = gWh + kc*32;
        const __nv_bfloat16* sl = gWl + kc*32;
        #pragma unroll
        for (int i=0;i<4;i++){
            cp16(dh + i*16, sh + i*8);
            cp16(dl + i*16, sl + i*8);
        }
        cp_commit();
    };
    // Gt(t) prefetch + W chunk0 as ONE group, then chunks 1,2
    auto issuePrologue = [&](int t){
        const float* GtBase = Gih + (size_t)t*Nly*Bsz*G4 + (size_t)(n*8)*G4 + chunk*64;
        #pragma unroll
        for (int jj=0; jj<2; jj++){
            int j = tid + jj*256;
            int b = j>>6, gate = (j>>4)&3, quad = j&15;
            cp16(sbase + L_OFF_GT + (uint32_t)j*16,
                 GtBase + (size_t)b*G4 + gate*512 + quad*4);
        }
        uint32_t dh = sbase + (uint32_t)(0*L_WSBLK + m_row*LSW)*2;
        uint32_t dl = sbase + (uint32_t)(1*L_WSBLK + m_row*LSW)*2;
        #pragma unroll
        for (int i=0;i<4;i++){
            cp16(dh + i*16, gWh + i*8);
            cp16(dl + i*16, gWl + i*8);
        }
        cp_commit();
        issueW(1,1);
        issueW(2,2);
    };

    issuePrologue(0);

    for (int t=0; t<Ssz; t++){
        // ---- load h (prev) into smem hi/lo (visibility covered by kc=0 sync) ----
        if (t==0){
            for (int idx=tid; idx<4096; idx+=256){
                int b = idx>>9, r = idx&511;
                float v = h0[(size_t)(n*8+b)*Rsz + r];
                __nv_bfloat16 h = __float2bfloat16(v);
                hh_s[b*LSH + r] = h;
                hl_s[b*LSH + r] = __float2bfloat16(v - __bfloat162float(h));
            }
        } else {
            const __nv_bfloat16* ph = hall_h + (size_t)(t-1)*NBR + (size_t)(n*8)*Rsz;
            const __nv_bfloat16* pl = hall_l + (size_t)(t-1)*NBR + (size_t)(n*8)*Rsz;
            for (int idx=tid; idx<512; idx+=256){
                int b = idx>>6, r8 = (idx&63)*8;
                *(uint4*)(hh_s + b*LSH + r8) = *(const uint4*)(ph + b*Rsz + r8);
                *(uint4*)(hl_s + b*LSH + r8) = *(const uint4*)(pl + b*Rsz + r8);
            }
        }

        float acc[2][4];
        #pragma unroll
        for (int f=0;f<2;f++){ acc[f][0]=0.f; acc[f][1]=0.f; acc[f][2]=0.f; acc[f][3]=0.f; }

        // ---- 16-chunk pipelined K loop (chunks 0-2 already in flight) ----
        for (int kc=0; kc<16; kc++){
            int s = kc&3;
            if      (kc<=13) cp_wait<2>();
            else if (kc==14) cp_wait<1>();
            else             cp_wait<0>();
            __syncthreads();                       // data visible; prev compute done
            if (kc+3 < 16) issueW(kc+3, (kc+3)&3);
            #pragma unroll
            for (int kf=0; kf<2; kf++){
                int kbase = kc*32 + kf*16;
                uint32_t bhr[2], blr[2];
                uint32_t hoff = (uint32_t)(bN*LSH + kbase + bK2)*2;
                bhr[0] = *(const uint32_t*)(sm + L_OFF_HH + hoff);
                bhr[1] = *(const uint32_t*)(sm + L_OFF_HH + hoff + 16);
                blr[0] = *(const uint32_t*)(sm + L_OFF_HL + hoff);
                blr[1] = *(const uint32_t*)(sm + L_OFF_HL + hoff + 16);
                #pragma unroll
                for (int f=0; f<2; f++){
                    int mbase = wid*32 + f*16;
                    uint32_t ah[4], al[4];
                    uint32_t wadr = (uint32_t)((mbase + aRow)*LSW + kf*16 + aCol)*2;
                    ldsm_x4(ah, sbase + (uint32_t)((s*2+0)*L_WSBLK)*2 + wadr);
                    ldsm_x4(al, sbase + (uint32_t)((s*2+1)*L_WSBLK)*2 + wadr);
                    mma16816(acc[f], ah, bhr);
                    mma16816(acc[f], ah, blr);
                    mma16816(acc[f], al, bhr);
                }
            }
        }

        // ---- gates to smem (warp-exclusive rows) ----
        int rA = lane>>2, cB = 2*(lane&3);
        #pragma unroll
        for (int f=0; f<2; f++){
            int m = wid*32 + f*16 + rA;
            ga[m*9 + cB]       = acc[f][0];
            ga[m*9 + cB + 1]   = acc[f][1];
            ga[(m+8)*9 + cB]   = acc[f][2];
            ga[(m+8)*9 + cB+1] = acc[f][3];
        }
        __syncthreads();

        // ---- elementwise LSTM + h split writeback (Gih from smem) ----
        for (int idx=tid; idx<512; idx+=256){
            int b = idx>>6, r = idx&63;
            float iv = ga[(      r)*9 + b] + gts[b*256       + r];
            float fv = ga[( 64 + r)*9 + b] + gts[b*256 +  64 + r];
            float gv = ga[(128 + r)*9 + b] + gts[b*256 + 128 + r];
            float ov = ga[(192 + r)*9 + b] + gts[b*256 + 192 + r];
            float cp = cs[r*9+b];
            float cn = sigm(fv)*cp + sigm(iv)*tanhf(gv);
            cs[r*9+b] = cn;
            float hv = sigm(ov)*tanhf(cn);
            size_t ho = (size_t)t*NBR + (size_t)(n*8+b)*Rsz + chunk*64 + r;
            __nv_bfloat16 hh = __float2bfloat16(hv);
            hall_h[ho] = hh;
            hall_l[ho] = __float2bfloat16(hv - __bfloat162float(hh));
            if (t == Ssz-1)
                hfinal[(size_t)(n*8+b)*Rsz + chunk*64 + r] = hv;
        }
        __syncthreads();                 // gts fully consumed before re-issue

        if (t+1 < Ssz){
            // prefetch next step's Gt + W chunks 0-2 WHILE waiting on barrier
            issuePrologue(t+1);
            __threadfence();
            if (tid==0){
                atomicAdd(&g_bar, 1u);
                unsigned target = 128u*(unsigned)(t+1);
                while (*barp < target) { }
                __threadfence();
            }
            __syncthreads();
        }
    }

    for (int idx=tid; idx<512; idx+=256){
        int b = idx>>6, r = idx&63;
        cfinal[(size_t)(n*8+b)*Rsz + chunk*64 + r] = cs[r*9+b];
    }
}

// ---------------- attention per token ----------------------------------------
__global__ void __launch_bounds__(256) attn_k()
{
    int m = blockIdx.x, tid = threadIdx.x;
    __shared__ float sq[512];
    __shared__ float sc[8][16];
    __shared__ float sw[8][16];
    sq[tid]     = g_q[(size_t)m*Dsz + tid];
    sq[tid+256] = g_q[(size_t)m*Dsz + tid + 256];
    __syncthreads();
    if (tid < 128){
        int h = tid>>4, nn = tid&15;
        const float* kp = g_k + (size_t)(m*Nly+nn)*Dsz + h*64;
        float s = 0.f;
        #pragma unroll 8
        for (int e=0;e<64;e++) s += sq[h*64+e]*kp[e];
        sc[h][nn] = s*0.125f;
    }
    __syncthreads();
    if (tid < 8){
        float mx = -1e30f;
        for (int nn=0;nn<16;nn++) mx = fmaxf(mx, sc[tid][nn]);
        float e[16], sum = 0.f;
        for (int nn=0;nn<16;nn++){ e[nn]=expf(sc[tid][nn]-mx); sum+=e[nn]; }
        float inv = 1.f/sum;
        for (int nn=0;nn<16;nn++) sw[tid][nn]=e[nn]*inv;
    }
    __syncthreads();
    for (int idx=tid; idx<512; idx+=256){
        int h = idx>>6;
        float s = 0.f;
        #pragma unroll
        for (int nn=0;nn<16;nn++)
            s += sw[h][nn]*g_v[(size_t)(m*Nly+nn)*Dsz + idx];
        g_att[(size_t)m*Dsz + idx] = s;
    }
}

// ---------------- layernorm (in-place on g_mix) ------------------------------
__global__ void __launch_bounds__(256) ln_k(const float* __restrict__ gam,
                                            const float* __restrict__ bet)
{
    int m = blockIdx.x, tid = threadIdx.x;
    __shared__ float sh[8];
    __shared__ float sh2[8];
    float* row = g_mix + (size_t)m*Dsz;
    float v0 = row[tid], v1 = row[tid+256];
    int lane = tid&31, w = tid>>5;

    float s = v0+v1;
    #pragma unroll
    for (int o=16;o>0;o>>=1) s += __shfl_xor_sync(0xffffffffu, s, o);
    if (lane==0) sh[w]=s;
    __syncthreads();
    float tot = sh[0]+sh[1]+sh[2]+sh[3]+sh[4]+sh[5]+sh[6]+sh[7];
    float mu = tot*(1.f/512.f);

    float d0=v0-mu, d1=v1-mu;
    float s2 = d0*d0+d1*d1;
    #pragma unroll
    for (int o=16;o>0;o>>=1) s2 += __shfl_xor_sync(0xffffffffu, s2, o);
    if (lane==0) sh2[w]=s2;
    __syncthreads();
    float tot2 = sh2[0]+sh2[1]+sh2[2]+sh2[3]+sh2[4]+sh2[5]+sh2[6]+sh2[7];
    float inv = rsqrtf(tot2*(1.f/512.f) + 1e-5f);

    row[tid]     = d0*inv*gam[tid]     + bet[tid];
    row[tid+256] = d1*inv*gam[tid+256] + bet[tid+256];
}

// ---------------- final state copy ------------------------------------------
__global__ void __launch_bounds__(256) copyhc_k(const float* __restrict__ hf,
                                                const float* __restrict__ cf,
                                                float* __restrict__ out)
{
    int idx = blockIdx.x*256 + threadIdx.x;
    const size_t L = (size_t)Bsz*Ssz*Vsz;
    out[L + idx]       = hf[idx];
    out[L + NBR + idx] = cf[idx];
}

// =============================================================================
extern "C" void kernel_launch(void* const* d_in, const int* in_sizes, int n_in,
                              void* d_out, int out_size)
{
    const int*   x      = (const int*)  d_in[0];
    const float* h0     = (const float*)d_in[1];
    const float* c0     = (const float*)d_in[2];
    const float* emb    = (const float*)d_in[3];
    const float* W_ih   = (const float*)d_in[4];
    const float* b_ih   = (const float*)d_in[5];
    const float* W_hh   = (const float*)d_in[6];
    const float* b_hh   = (const float*)d_in[7];
    const float* W_np   = (const float*)d_in[8];
    const float* b_np   = (const float*)d_in[9];
    const float* in_w   = (const float*)d_in[10];
    const float* in_b   = (const float*)d_in[11];
    const float* op_w   = (const float*)d_in[12];
    const float* op_b   = (const float*)d_in[13];
    const float* ln_g   = (const float*)d_in[14];
    const float* ln_b   = (const float*)d_in[15];
    const float* head_w = (const float*)d_in[16];
    const float* head_b = (const float*)d_in[17];
    float* out = (float*)d_out;

    cudaFuncSetAttribute(tgemm_k<1>, cudaFuncAttributeMaxDynamicSharedMemorySize, TG_SMEM);
    cudaFuncSetAttribute(tgemm_k<2>, cudaFuncAttributeMaxDynamicSharedMemorySize, TG_SMEM);
    cudaFuncSetAttribute(tgemm_k<3>, cudaFuncAttributeMaxDynamicSharedMemorySize, TG_SMEM);
    cudaFuncSetAttribute(lstm_mma,   cudaFuncAttributeMaxDynamicSharedMemorySize, L_SMEM);

    float *pX,*pGih,*pHall,*pCf,*pQ,*pWnk,*pWnv,*pCk,*pCv,*pK,*pV,*pAtt,*pMix;
    __nv_bfloat16 *pWihH,*pWihL,*pWhhH,*pWhhL,*pHeadH,*pHeadL,*pXH,*pXL,*pHallH,*pHallL;
    __nv_bfloat16 *pWnkH,*pWnkL,*pWnvH,*pWnvL,*pMixH,*pMixL;
    cudaGetSymbolAddress((void**)&pX,    g_X);
    cudaGetSymbolAddress((void**)&pGih,  g_Gih);
    cudaGetSymbolAddress((void**)&pHall, g_hall);
    cudaGetSymbolAddress((void**)&pCf,   g_cf);
    cudaGetSymbolAddress((void**)&pQ,    g_q);
    cudaGetSymbolAddress((void**)&pWnk,  g_Wnk);
    cudaGetSymbolAddress((void**)&pWnv,  g_Wnv);
    cudaGetSymbolAddress((void**)&pCk,   g_ck);
    cudaGetSymbolAddress((void**)&pCv,   g_cv);
    cudaGetSymbolAddress((void**)&pK,    g_k);
    cudaGetSymbolAddress((void**)&pV,    g_v);
    cudaGetSymbolAddress((void**)&pAtt,  g_att);
    cudaGetSymbolAddress((void**)&pMix,  g_mix);
    cudaGetSymbolAddress((void**)&pWihH, bWih_h);  cudaGetSymbolAddress((void**)&pWihL, bWih_l);
    cudaGetSymbolAddress((void**)&pWhhH, bWhh_h);  cudaGetSymbolAddress((void**)&pWhhL, bWhh_l);
    cudaGetSymbolAddress((void**)&pHeadH,bHead_h); cudaGetSymbolAddress((void**)&pHeadL,bHead_l);
    cudaGetSymbolAddress((void**)&pXH,   bX_h);    cudaGetSymbolAddress((void**)&pXL,   bX_l);
    cudaGetSymbolAddress((void**)&pHallH,bHall_h); cudaGetSymbolAddress((void**)&pHallL,bHall_l);
    cudaGetSymbolAddress((void**)&pWnkH, bWnk_h);  cudaGetSymbolAddress((void**)&pWnkL, bWnk_l);
    cudaGetSymbolAddress((void**)&pWnvH, bWnv_h);  cudaGetSymbolAddress((void**)&pWnvL, bWnv_l);
    cudaGetSymbolAddress((void**)&pMixH, bMix_h);  cudaGetSymbolAddress((void**)&pMixL, bMix_l);

    // Launch order: index 3 = lstm_mma (ncu captures 4th launch)
    embed_split_k<<<(Mtok*Dsz)/256, 256>>>(x, emb);                              // 0
    splitW2_k<<<2*(Nly*G4*Dsz)/256,256>>>(W_ih,pWihH,pWihL, W_hh,pWhhH,pWhhL,
                                          Nly*G4*Dsz);                           // 1 (+bar=0)
    tgemm_k<1><<<dim3(16,16,16),256,TG_SMEM>>>(pXH,pXL,pWihH,pWihL,pGih,b_ih,b_hh); // 2
    lstm_mma<<<128,256,L_SMEM>>>(pWhhH, pWhhL, h0, c0, pHall, pHallH, pHallL, pGih, pCf); // 3 <- profiled

    // Phase 1 remainder + Phase 3
    split_k<<<(Vsz*Dsz)/256,256>>>(head_w, pHeadH, pHeadL, Vsz*Dsz);
    gemm_k<0><<<dim3(4,16),256>>>(pX, in_w, pQ, in_b, nullptr);
    gemm_k<5><<<dim3(4,4,16),256>>>(in_w +   Dsz*Dsz, W_np, pWnk, nullptr, nullptr);
    gemm_k<5><<<dim3(4,4,16),256>>>(in_w + 2*Dsz*Dsz, W_np, pWnv, nullptr, nullptr);
    split_k<<<(Nly*Dsz*Rsz)/256,256>>>(pWnk, pWnkH, pWnkL, Nly*Dsz*Rsz);
    split_k<<<(Nly*Dsz*Rsz)/256,256>>>(pWnv, pWnvH, pWnvL, Nly*Dsz*Rsz);
    ckcv_k<<<(Nly*Dsz)/256, 256>>>(in_w, in_b, b_np);
    tgemm_k<3><<<dim3(4,16,16),256,TG_SMEM>>>(pHallH,pHallL,pWnkH,pWnkL,pK,pCk,nullptr);
    tgemm_k<3><<<dim3(4,16,16),256,TG_SMEM>>>(pHallH,pHallL,pWnvH,pWnvL,pV,pCv,nullptr);
    attn_k<<<Mtok,256>>>();
    gemm_k<4><<<dim3(4,16),256>>>(pAtt, op_w, pMix, op_b, pX);
    ln_k<<<Mtok,256>>>(ln_g, ln_b);
    split_k<<<(Mtok*Dsz)/256,256>>>(pMix, pMixH, pMixL, Mtok*Dsz);
    tgemm_k<2><<<dim3(250,16),256,TG_SMEM>>>(pMixH,pMixL,pHeadH,pHeadL,out,head_b,nullptr);

    // hf / cf
    copyhc_k<<<NBR/256,256>>>(pHall, pCf, out);
}

// round 12
// speedup vs baseline: 2.3516x; 1.4413x over previous
#include <cuda_runtime.h>
#include <cuda_bf16.h>
#include <cuda_fp16.h>
#include <math.h>
#include <stdint.h>

// Problem dims
#define Bsz 8
#define Ssz 256
#define Vsz 32000
#define Dsz 512
#define Nly 16
#define Rsz 512
#define G4  2048            // 4*R
#define Mtok (Bsz*Ssz)      // 2048 tokens
#define NBR (Nly*Bsz*Rsz)   // 65536

// ---------------- scratch (static device globals; no runtime alloc) ----------
__device__ float g_X   [Mtok*Dsz];
__device__ float g_Gih [(size_t)Ssz*Nly*Bsz*G4];         // [t][n][b][g]
__device__ float g_hall[NBR];                            // final-step h only (hf)
__device__ float g_cf  [NBR];
__device__ float g_q   [Mtok*Dsz];
__device__ float g_Wnk [Nly*Dsz*Rsz];
__device__ float g_Wnv [Nly*Dsz*Rsz];
__device__ float g_ck  [Nly*Dsz];
__device__ float g_cv  [Nly*Dsz];
__device__ float g_k   [(size_t)Mtok*Nly*Dsz];
__device__ float g_v   [(size_t)Mtok*Nly*Dsz];
__device__ float g_att [Mtok*Dsz];
__device__ float g_mix [Mtok*Dsz];
__device__ unsigned g_bar;

// bf16 split buffers (hi + lo)
__device__ __align__(16) __nv_bfloat16 bWih_h [(size_t)Nly*G4*Dsz];
__device__ __align__(16) __nv_bfloat16 bWih_l [(size_t)Nly*G4*Dsz];
__device__ __align__(16) __half        hWhh   [(size_t)Nly*G4*Dsz];   // fp16 single
__device__ __align__(16) __nv_bfloat16 bHead_h[(size_t)Vsz*Dsz];
__device__ __align__(16) __nv_bfloat16 bHead_l[(size_t)Vsz*Dsz];
__device__ __align__(16) __nv_bfloat16 bX_h   [Mtok*Dsz];
__device__ __align__(16) __nv_bfloat16 bX_l   [Mtok*Dsz];
__device__ __align__(16) __nv_bfloat16 bHall_h[(size_t)Ssz*NBR];
__device__ __align__(16) __nv_bfloat16 bHall_l[(size_t)Ssz*NBR];
__device__ __align__(16) __nv_bfloat16 bWnk_h [Nly*Dsz*Rsz];
__device__ __align__(16) __nv_bfloat16 bWnk_l [Nly*Dsz*Rsz];
__device__ __align__(16) __nv_bfloat16 bWnv_h [Nly*Dsz*Rsz];
__device__ __align__(16) __nv_bfloat16 bWnv_l [Nly*Dsz*Rsz];
__device__ __align__(16) __nv_bfloat16 bMix_h [Mtok*Dsz];
__device__ __align__(16) __nv_bfloat16 bMix_l [Mtok*Dsz];

__device__ __forceinline__ float sigm(float x){ return 1.f/(1.f+expf(-x)); }

// ======================= PTX helpers (compute_103-safe) ======================
__device__ __forceinline__ void cp16(uint32_t sdst, const void* gsrc){
    asm volatile("cp.async.cg.shared.global [%0], [%1], 16;" :: "r"(sdst), "l"(gsrc));
}
__device__ __forceinline__ void cp_commit(){
    asm volatile("cp.async.commit_group;" ::: "memory");
}
template<int N>
__device__ __forceinline__ void cp_wait(){
    asm volatile("cp.async.wait_group %0;" :: "n"(N) : "memory");
}
__device__ __forceinline__ void ldsm_x4(uint32_t* r, uint32_t addr){
    asm volatile("ldmatrix.sync.aligned.m8n8.x4.shared.b16 {%0,%1,%2,%3}, [%4];"
        : "=r"(r[0]),"=r"(r[1]),"=r"(r[2]),"=r"(r[3]) : "r"(addr));
}
__device__ __forceinline__ void mma16816(float* d, const uint32_t* a, const uint32_t* b){
    asm volatile("mma.sync.aligned.m16n8k16.row.col.f32.bf16.bf16.f32 "
        "{%0,%1,%2,%3}, {%4,%5,%6,%7}, {%8,%9}, {%0,%1,%2,%3};"
        : "+f"(d[0]),"+f"(d[1]),"+f"(d[2]),"+f"(d[3])
        : "r"(a[0]),"r"(a[1]),"r"(a[2]),"r"(a[3]), "r"(b[0]),"r"(b[1]));
}
__device__ __forceinline__ void mma16816h(float* d, const uint32_t* a, const uint32_t* b){
    asm volatile("mma.sync.aligned.m16n8k16.row.col.f32.f16.f16.f32 "
        "{%0,%1,%2,%3}, {%4,%5,%6,%7}, {%8,%9}, {%0,%1,%2,%3};"
        : "+f"(d[0]),"+f"(d[1]),"+f"(d[2]),"+f"(d[3])
        : "r"(a[0]),"r"(a[1]),"r"(a[2]),"r"(a[3]), "r"(b[0]),"r"(b[1]));
}

// ======================= mma.sync bf16-split GEMM (unchanged, passing) =======
#define TG_LD   72
#define TG_BLK  (128*TG_LD)
#define TG_SMEM (8*TG_BLK*2)

template<int MODE>
__global__ void __launch_bounds__(256,1) tgemm_k(
    const __nv_bfloat16* __restrict__ Ah, const __nv_bfloat16* __restrict__ Al,
    const __nv_bfloat16* __restrict__ Bh, const __nv_bfloat16* __restrict__ Bl,
    float* __restrict__ C, const float* __restrict__ bias,
    const float* __restrict__ bias2)
{
    extern __shared__ __align__(16) __nv_bfloat16 smb[];
    uint32_t sbase = (uint32_t)__cvta_generic_to_shared(smb);
    int tid = threadIdx.x, wid = tid>>5, lane = tid&31;
    int wm = wid>>2, wn = wid&3;
    int bn = blockIdx.x, bm = blockIdx.y, nz = blockIdx.z;

    const __nv_bfloat16 *BhP = Bh, *BlP = Bl;
    if (MODE==1){ BhP += (size_t)nz*G4 *512; BlP += (size_t)nz*G4 *512; }
    if (MODE==3){ BhP += (size_t)nz*Dsz*512; BlP += (size_t)nz*Dsz*512; }

    int lrow = tid>>1, lk = (tid&1)*32;
    int am = bm*128 + lrow;
    int ag = (MODE==3) ? ((am>>3)*128 + nz*8 + (am&7)) : am;
    const __nv_bfloat16* gAh = Ah  + (size_t)ag*512 + lk;
    const __nv_bfloat16* gAl = Al  + (size_t)ag*512 + lk;
    const __nv_bfloat16* gBh = BhP + (size_t)(bn*128 + lrow)*512 + lk;
    const __nv_bfloat16* gBl = BlP + (size_t)(bn*128 + lrow)*512 + lk;
    uint32_t sRowOff = (uint32_t)(lrow*TG_LD + lk)*2;

    int aRowL = wm*64 + (lane&15);
    int aColL = (lane>>4)*8;
    int bRowL = wn*32 + ((lane>>4)&1)*8 + (lane&7);
    int bColL = ((lane>>3)&1)*8;

    float acc[4][4][4];
    #pragma unroll
    for (int i=0;i<4;i++){
        #pragma unroll
        for (int j=0;j<4;j++){
            acc[i][j][0]=0.f; acc[i][j][1]=0.f; acc[i][j][2]=0.f; acc[i][j][3]=0.f;
        }
    }

    auto issue = [&](int s, int kb){
        uint32_t d0 = sbase + (uint32_t)((s*4+0)*TG_BLK)*2 + sRowOff;
        uint32_t d1 = sbase + (uint32_t)((s*4+1)*TG_BLK)*2 + sRowOff;
        uint32_t d2 = sbase + (uint32_t)((s*4+2)*TG_BLK)*2 + sRowOff;
        uint32_t d3 = sbase + (uint32_t)((s*4+3)*TG_BLK)*2 + sRowOff;
        #pragma unroll
        for (int i=0;i<4;i++){
            cp16(d0 + i*16, gAh + kb + i*8);
            cp16(d1 + i*16, gAl + kb + i*8);
            cp16(d2 + i*16, gBh + kb + i*8);
            cp16(d3 + i*16, gBl + kb + i*8);
        }
        cp_commit();
    };

    issue(0, 0);
    for (int c=0;c<8;c++){
        int s = c&1;
        if (c<7) issue(s^1, (c+1)*64);
        if (c<7) cp_wait<1>(); else cp_wait<0>();
        __syncthreads();

        #pragma unroll
        for (int ks=0; ks<4; ks++){
            int kc = ks*16;
            uint32_t ah[4][4], al[4][4];
            #pragma unroll
            for (int mf=0; mf<4; mf++){
                uint32_t addrh = sbase + (uint32_t)((s*4+0)*TG_BLK + (aRowL+mf*16)*TG_LD + aColL + kc)*2;
                uint32_t addrl = sbase + (uint32_t)((s*4+1)*TG_BLK + (aRowL+mf*16)*TG_LD + aColL + kc)*2;
                ldsm_x4(ah[mf], addrh);
                ldsm_x4(al[mf], addrl);
            }
            uint32_t bh[2][4], bl[2][4];
            #pragma unroll
            for (int nfh=0; nfh<2; nfh++){
                uint32_t addrh = sbase + (uint32_t)((s*4+2)*TG_BLK + (bRowL+nfh*16)*TG_LD + bColL + kc)*2;
                uint32_t addrl = sbase + (uint32_t)((s*4+3)*TG_BLK + (bRowL+nfh*16)*TG_LD + bColL + kc)*2;
                ldsm_x4(bh[nfh], addrh);
                ldsm_x4(bl[nfh], addrl);
            }
            #pragma unroll
            for (int mf=0; mf<4; mf++){
                #pragma unroll
                for (int nf=0; nf<4; nf++){
                    const uint32_t* bhp = &bh[nf>>1][(nf&1)*2];
                    const uint32_t* blp = &bl[nf>>1][(nf&1)*2];
                    mma16816(acc[mf][nf], ah[mf], bhp);
                    mma16816(acc[mf][nf], ah[mf], blp);
                    mma16816(acc[mf][nf], al[mf], bhp);
                }
            }
        }
        __syncthreads();
    }

    int rA = lane>>2, cA = (lane&3)*2;
    #pragma unroll
    for (int mf=0; mf<4; mf++){
        #pragma unroll
        for (int nf=0; nf<4; nf++){
            #pragma unroll
            for (int half=0; half<2; half++){
                int m  = bm*128 + wm*64 + mf*16 + rA + half*8;
                int jc = bn*128 + wn*32 + nf*8 + cA;
                float v0 = acc[mf][nf][half*2+0];
                float v1 = acc[mf][nf][half*2+1];
                if (MODE==1){
                    v0 += bias[nz*G4+jc]   + bias2[nz*G4+jc];
                    v1 += bias[nz*G4+jc+1] + bias2[nz*G4+jc+1];
                    int t=m>>3, b=m&7;
                    float2 w = {v0,v1};
                    *(float2*)&C[(size_t)(t*128+nz*8+b)*G4 + jc] = w;
                } else if (MODE==2){
                    v0 += bias[jc]; v1 += bias[jc+1];
                    int t=m>>3, b=m&7;
                    float2 w = {v0,v1};
                    *(float2*)&C[(size_t)(b*Ssz+t)*Vsz + jc] = w;
                } else {
                    v0 += bias[nz*Dsz+jc]; v1 += bias[nz*Dsz+jc+1];
                    float2 w = {v0,v1};
                    *(float2*)&C[(size_t)(m*Nly+nz)*Dsz + jc] = w;
                }
            }
        }
    }
}

// ---------------- fp32 -> bf16 hi/lo split -----------------------------------
__global__ void __launch_bounds__(256) split_k(const float* __restrict__ src,
                                              __nv_bfloat16* __restrict__ hi,
                                              __nv_bfloat16* __restrict__ lo,
                                              int n)
{
    int i = blockIdx.x*256 + threadIdx.x;
    if (i < n){
        float x = src[i];
        __nv_bfloat16 h = __float2bfloat16(x);
        hi[i] = h;
        lo[i] = __float2bfloat16(x - __bfloat162float(h));
    }
}

// ---------------- fused: embedding gather + bf16 split -----------------------
__global__ void __launch_bounds__(256) embed_split_k(const int* __restrict__ x,
                                                     const float* __restrict__ emb)
{
    int idx = blockIdx.x*256 + threadIdx.x;
    int m = idx>>9, d = idx&511;
    int t = m>>3, b = m&7;
    float v = emb[(size_t)x[b*Ssz+t]*Dsz + d];
    g_X[idx] = v;
    __nv_bfloat16 h = __float2bfloat16(v);
    bX_h[idx] = h;
    bX_l[idx] = __float2bfloat16(v - __bfloat162float(h));
}

// ---------------- fused: split Wih (bf16 pair) + convert Whh (fp16) + bar=0 --
__global__ void __launch_bounds__(256) splitW2_k(const float* __restrict__ s1,
                                                 __nv_bfloat16* __restrict__ h1,
                                                 __nv_bfloat16* __restrict__ l1,
                                                 const float* __restrict__ s2,
                                                 __half* __restrict__ h2,
                                                 int n)
{
    int i = blockIdx.x*256 + threadIdx.x;
    if (i == 0) g_bar = 0u;
    if (i < n){
        float x = s1[i];
        __nv_bfloat16 h = __float2bfloat16(x);
        h1[i] = h;
        l1[i] = __float2bfloat16(x - __bfloat162float(h));
    } else {
        int j = i - n;
        h2[j] = __float2half(s2[j]);
    }
}

// ---------------- SIMT 128x128 GEMM (small modes 0,4,5) ----------------------
template<int MODE>
__global__ void __launch_bounds__(256, 2) gemm_k(
    const float* __restrict__ A, const float* __restrict__ Bw,
    float* __restrict__ C, const float* __restrict__ bias,
    const float* __restrict__ resid)
{
    const int K = 512;
    __shared__ float As[2][8][132];
    __shared__ float Bs[2][8][132];
    int tid = threadIdx.x;
    int bn = blockIdx.x, bm = blockIdx.y, n = blockIdx.z;

    const float* Bp = Bw;
    if (MODE==5) Bp += (size_t)n*Dsz*Rsz;

    int lRow = tid>>1, lK = (tid&1)<<2;
    const float* Aptr = A + (size_t)(bm*128+lRow)*K + lK;
    const float* Bptr;
    int b_k=0, b_j=0;
    if (MODE==5){
        b_k = tid>>5; b_j = (tid&31)<<2;
        Bptr = Bp + (size_t)b_k*Rsz + bn*128 + b_j;
    } else {
        Bptr = Bp + (size_t)(bn*128 + lRow)*K + lK;
    }
    int ty = tid>>4, tx = tid&15;
    float acc[8][8] = {};
    float4 aReg, bReg;

    aReg = *(const float4*)(Aptr);
    bReg = *(const float4*)(Bptr);
    As[0][lK+0][lRow]=aReg.x; As[0][lK+1][lRow]=aReg.y;
    As[0][lK+2][lRow]=aReg.z; As[0][lK+3][lRow]=aReg.w;
    if (MODE==5){ *(float4*)&Bs[0][b_k][b_j] = bReg; }
    else {
        Bs[0][lK+0][lRow]=bReg.x; Bs[0][lK+1][lRow]=bReg.y;
        Bs[0][lK+2][lRow]=bReg.z; Bs[0][lK+3][lRow]=bReg.w;
    }
    __syncthreads();

    int buf = 0;
    for (int kb=8; kb<=K; kb+=8){
        bool more = (kb < K);
        if (more){
            aReg = *(const float4*)(Aptr + kb);
            bReg = (MODE==5) ? *(const float4*)(Bptr + (size_t)kb*Rsz)
                             : *(const float4*)(Bptr + kb);
        }
        #pragma unroll
        for (int k=0;k<8;k++){
            float4 a0 = *(const float4*)&As[buf][k][ty<<2];
            float4 a1 = *(const float4*)&As[buf][k][(ty<<2)+64];
            float4 b0 = *(const float4*)&Bs[buf][k][tx<<2];
            float4 b1 = *(const float4*)&Bs[buf][k][(tx<<2)+64];
            float a[8]={a0.x,a0.y,a0.z,a0.w,a1.x,a1.y,a1.z,a1.w};
            float b[8]={b0.x,b0.y,b0.z,b0.w,b1.x,b1.y,b1.z,b1.w};
            #pragma unroll
            for(int i=0;i<8;i++)
                #pragma unroll
                for(int j=0;j<8;j++) acc[i][j] += a[i]*b[j];
        }
        if (more){
            int nb = buf^1;
            As[nb][lK+0][lRow]=aReg.x; As[nb][lK+1][lRow]=aReg.y;
            As[nb][lK+2][lRow]=aReg.z; As[nb][lK+3][lRow]=aReg.w;
            if (MODE==5){ *(float4*)&Bs[nb][b_k][b_j] = bReg; }
            else {
                Bs[nb][lK+0][lRow]=bReg.x; Bs[nb][lK+1][lRow]=bReg.y;
                Bs[nb][lK+2][lRow]=bReg.z; Bs[nb][lK+3][lRow]=bReg.w;
            }
            __syncthreads();
            buf = nb;
        }
    }

    #pragma unroll
    for(int i=0;i<8;i++){
        int m = bm*128 + (ty<<2) + (i&3) + ((i>>2)<<6);
        #pragma unroll
        for(int j=0;j<8;j++){
            int jc = bn*128 + (tx<<2) + (j&3) + ((j>>2)<<6);
            float v = acc[i][j];
            if (MODE==0){ v += bias[jc]; C[(size_t)m*Dsz+jc]=v; }
            else if (MODE==4){ v += bias[jc] + resid[(size_t)m*Dsz+jc]; C[(size_t)m*Dsz+jc]=v; }
            else { C[(size_t)n*Dsz*Rsz + (size_t)m*Rsz + jc]=v; }
        }
    }
}

// ---------------- combined k/v biases ----------------------------------------
__global__ void __launch_bounds__(256) ckcv_k(const float* __restrict__ in_w,
                                              const float* __restrict__ in_b,
                                              const float* __restrict__ b_np)
{
    int idx = blockIdx.x*256 + threadIdx.x;
    int n = idx>>9, dc = idx&511;
    const float* Wk = in_w + Dsz*Dsz;
    const float* Wv = in_w + 2*Dsz*Dsz;
    const float* bn = b_np + n*Dsz;
    float sk = in_b[Dsz+dc], sv = in_b[2*Dsz+dc];
    for (int j=0;j<Dsz;j++){
        float bj = bn[j];
        sk += Wk[(size_t)dc*Dsz+j]*bj;
        sv += Wv[(size_t)dc*Dsz+j]*bj;
    }
    g_ck[idx]=sk; g_cv[idx]=sv;
}

// ---------------- persistent LSTM recurrence (fp16 W, 2-product, 4-stage) ----
#define LSW 40
#define LSH 536
#define L_WSBLK (256*LSW)                  // halfs per W stage
#define L_NSTG 4
#define L_OFF_HH (L_NSTG*L_WSBLK*2)        // after 4 W stages (fp16)
#define L_OFF_HL (L_OFF_HH + 8*LSH*2)
#define L_OFF_GA (L_OFF_HL + 8*LSH*2)
#define L_OFF_CS (L_OFF_GA + 256*9*4)
#define L_OFF_GT (L_OFF_CS + 64*9*4)
#define L_SMEM   (L_OFF_GT + 8192)

__global__ void __launch_bounds__(256,1) lstm_mma(
    const __half* __restrict__ W,
    const float* __restrict__ h0, const float* __restrict__ c0,
    float* __restrict__ hfinal,
    __nv_bfloat16* __restrict__ hall_h, __nv_bfloat16* __restrict__ hall_l,
    const float* __restrict__ Gih, float* __restrict__ cfinal)
{
    extern __shared__ __align__(16) char sm[];
    uint32_t sbase = (uint32_t)__cvta_generic_to_shared(sm);
    __half* hh_s = (__half*)(sm + L_OFF_HH);
    __half* hl_s = (__half*)(sm + L_OFF_HL);
    float* ga  = (float*)(sm + L_OFF_GA);   // [256][9]
    float* cs  = (float*)(sm + L_OFF_CS);   // [64][9]
    float* gts = (float*)(sm + L_OFF_GT);   // [8][4][64] prefetched Gih slice

    int tid = threadIdx.x, wid = tid>>5, lane = tid&31;
    int chunk = blockIdx.x & 7, n = blockIdx.x >> 3;

    int m_row = tid;
    int gateT = m_row>>6, rlocT = m_row&63;
    size_t grow = (size_t)(n*G4 + gateT*512 + chunk*64 + rlocT)*512;
    const __half* gW = W + grow;

    for (int idx=tid; idx<512; idx+=256){
        int b = idx>>6, r = idx&63;
        cs[r*9+b] = c0[(size_t)(n*8+b)*Rsz + chunk*64 + r];
    }

    int aRow = lane&15, aCol = (lane>>4)*8;
    int bN = lane>>2, bK2 = 2*(lane&3);

    volatile unsigned* barp = &g_bar;

    // W chunk kc (32 k-elts = 64B/row) -> stage s
    auto issueW = [&](int kc, int s){
        uint32_t dw = sbase + (uint32_t)(s*L_WSBLK + m_row*LSW)*2;
        const __half* sw = gW + kc*32;
        #pragma unroll
        for (int i=0;i<4;i++) cp16(dw + i*16, sw + i*8);
        cp_commit();
    };
    // Gt(t) prefetch + W chunk0 as ONE group, then chunks 1,2
    auto issuePrologue = [&](int t){
        const float* GtBase = Gih + (size_t)t*Nly*Bsz*G4 + (size_t)(n*8)*G4 + chunk*64;
        #pragma unroll
        for (int jj=0; jj<2; jj++){
            int j = tid + jj*256;
            int b = j>>6, gate = (j>>4)&3, quad = j&15;
            cp16(sbase + L_OFF_GT + (uint32_t)j*16,
                 GtBase + (size_t)b*G4 + gate*512 + quad*4);
        }
        uint32_t dw = sbase + (uint32_t)(0*L_WSBLK + m_row*LSW)*2;
        #pragma unroll
        for (int i=0;i<4;i++) cp16(dw + i*16, gW + i*8);
        cp_commit();
        issueW(1,1);
        issueW(2,2);
    };

    issuePrologue(0);

    for (int t=0; t<Ssz; t++){
        // ---- load h (prev), convert to fp16 hi/lo in smem ----
        if (t==0){
            for (int idx=tid; idx<4096; idx+=256){
                int b = idx>>9, r = idx&511;
                float v = h0[(size_t)(n*8+b)*Rsz + r];
                __half hh = __float2half(v);
                hh_s[b*LSH + r] = hh;
                hl_s[b*LSH + r] = __float2half(v - __half2float(hh));
            }
        } else {
            const __nv_bfloat16* ph = hall_h + (size_t)(t-1)*NBR + (size_t)(n*8)*Rsz;
            const __nv_bfloat16* pl = hall_l + (size_t)(t-1)*NBR + (size_t)(n*8)*Rsz;
            for (int idx=tid; idx<4096; idx+=256){
                int b = idx>>9, r = idx&511;
                float v = __bfloat162float(ph[(size_t)b*Rsz + r])
                        + __bfloat162float(pl[(size_t)b*Rsz + r]);
                __half hh = __float2half(v);
                hh_s[b*LSH + r] = hh;
                hl_s[b*LSH + r] = __float2half(v - __half2float(hh));
            }
        }

        float acc[2][4];
        #pragma unroll
        for (int f=0;f<2;f++){ acc[f][0]=0.f; acc[f][1]=0.f; acc[f][2]=0.f; acc[f][3]=0.f; }

        // ---- 16-chunk pipelined K loop (chunks 0-2 already in flight) ----
        for (int kc=0; kc<16; kc++){
            int s = kc&3;
            if      (kc<=13) cp_wait<2>();
            else if (kc==14) cp_wait<1>();
            else             cp_wait<0>();
            __syncthreads();                       // data visible; prev compute done
            if (kc+3 < 16) issueW(kc+3, (kc+3)&3);
            #pragma unroll
            for (int kf=0; kf<2; kf++){
                int kbase = kc*32 + kf*16;
                uint32_t bhr[2], blr[2];
                uint32_t hoff = (uint32_t)(bN*LSH + kbase + bK2)*2;
                bhr[0] = *(const uint32_t*)(sm + L_OFF_HH + hoff);
                bhr[1] = *(const uint32_t*)(sm + L_OFF_HH + hoff + 16);
                blr[0] = *(const uint32_t*)(sm + L_OFF_HL + hoff);
                blr[1] = *(const uint32_t*)(sm + L_OFF_HL + hoff + 16);
                #pragma unroll
                for (int f=0; f<2; f++){
                    int mbase = wid*32 + f*16;
                    uint32_t aw[4];
                    uint32_t wadr = (uint32_t)((mbase + aRow)*LSW + kf*16 + aCol)*2;
                    ldsm_x4(aw, sbase + (uint32_t)(s*L_WSBLK)*2 + wadr);
                    mma16816h(acc[f], aw, bhr);
                    mma16816h(acc[f], aw, blr);
                }
            }
        }

        // ---- gates to smem (warp-exclusive rows) ----
        int rA = lane>>2, cB = 2*(lane&3);
        #pragma unroll
        for (int f=0; f<2; f++){
            int m = wid*32 + f*16 + rA;
            ga[m*9 + cB]       = acc[f][0];
            ga[m*9 + cB + 1]   = acc[f][1];
            ga[(m+8)*9 + cB]   = acc[f][2];
            ga[(m+8)*9 + cB+1] = acc[f][3];
        }
        __syncthreads();

        // ---- elementwise LSTM + h split writeback (Gih from smem) ----
        for (int idx=tid; idx<512; idx+=256){
            int b = idx>>6, r = idx&63;
            float iv = ga[(      r)*9 + b] + gts[b*256       + r];
            float fv = ga[( 64 + r)*9 + b] + gts[b*256 +  64 + r];
            float gv = ga[(128 + r)*9 + b] + gts[b*256 + 128 + r];
            float ov = ga[(192 + r)*9 + b] + gts[b*256 + 192 + r];
            float cp = cs[r*9+b];
            float cn = sigm(fv)*cp + sigm(iv)*tanhf(gv);
            cs[r*9+b] = cn;
            float hv = sigm(ov)*tanhf(cn);
            size_t ho = (size_t)t*NBR + (size_t)(n*8+b)*Rsz + chunk*64 + r;
            __nv_bfloat16 hh = __float2bfloat16(hv);
            hall_h[ho] = hh;
            hall_l[ho] = __float2bfloat16(hv - __bfloat162float(hh));
            if (t == Ssz-1)
                hfinal[(size_t)(n*8+b)*Rsz + chunk*64 + r] = hv;
        }
        __syncthreads();                 // gts fully consumed before re-issue

        if (t+1 < Ssz){
            issuePrologue(t+1);          // prefetch while waiting on barrier
            __threadfence();
            if (tid==0){
                atomicAdd(&g_bar, 1u);
                unsigned target = 128u*(unsigned)(t+1);
                while (*barp < target) { }
                __threadfence();
            }
            __syncthreads();
        }
    }

    for (int idx=tid; idx<512; idx+=256){
        int b = idx>>6, r = idx&63;
        cfinal[(size_t)(n*8+b)*Rsz + chunk*64 + r] = cs[r*9+b];
    }
}

// ---------------- attention per token ----------------------------------------
__global__ void __launch_bounds__(256) attn_k()
{
    int m = blockIdx.x, tid = threadIdx.x;
    __shared__ float sq[512];
    __shared__ float sc[8][16];
    __shared__ float sw[8][16];
    sq[tid]     = g_q[(size_t)m*Dsz + tid];
    sq[tid+256] = g_q[(size_t)m*Dsz + tid + 256];
    __syncthreads();
    if (tid < 128){
        int h = tid>>4, nn = tid&15;
        const float* kp = g_k + (size_t)(m*Nly+nn)*Dsz + h*64;
        float s = 0.f;
        #pragma unroll 8
        for (int e=0;e<64;e++) s += sq[h*64+e]*kp[e];
        sc[h][nn] = s*0.125f;
    }
    __syncthreads();
    if (tid < 8){
        float mx = -1e30f;
        for (int nn=0;nn<16;nn++) mx = fmaxf(mx, sc[tid][nn]);
        float e[16], sum = 0.f;
        for (int nn=0;nn<16;nn++){ e[nn]=expf(sc[tid][nn]-mx); sum+=e[nn]; }
        float inv = 1.f/sum;
        for (int nn=0;nn<16;nn++) sw[tid][nn]=e[nn]*inv;
    }
    __syncthreads();
    for (int idx=tid; idx<512; idx+=256){
        int h = idx>>6;
        float s = 0.f;
        #pragma unroll
        for (int nn=0;nn<16;nn++)
            s += sw[h][nn]*g_v[(size_t)(m*Nly+nn)*Dsz + idx];
        g_att[(size_t)m*Dsz + idx] = s;
    }
}

// ---------------- layernorm (in-place on g_mix) ------------------------------
__global__ void __launch_bounds__(256) ln_k(const float* __restrict__ gam,
                                            const float* __restrict__ bet)
{
    int m = blockIdx.x, tid = threadIdx.x;
    __shared__ float sh[8];
    __shared__ float sh2[8];
    float* row = g_mix + (size_t)m*Dsz;
    float v0 = row[tid], v1 = row[tid+256];
    int lane = tid&31, w = tid>>5;

    float s = v0+v1;
    #pragma unroll
    for (int o=16;o>0;o>>=1) s += __shfl_xor_sync(0xffffffffu, s, o);
    if (lane==0) sh[w]=s;
    __syncthreads();
    float tot = sh[0]+sh[1]+sh[2]+sh[3]+sh[4]+sh[5]+sh[6]+sh[7];
    float mu = tot*(1.f/512.f);

    float d0=v0-mu, d1=v1-mu;
    float s2 = d0*d0+d1*d1;
    #pragma unroll
    for (int o=16;o>0;o>>=1) s2 += __shfl_xor_sync(0xffffffffu, s2, o);
    if (lane==0) sh2[w]=s2;
    __syncthreads();
    float tot2 = sh2[0]+sh2[1]+sh2[2]+sh2[3]+sh2[4]+sh2[5]+sh2[6]+sh2[7];
    float inv = rsqrtf(tot2*(1.f/512.f) + 1e-5f);

    row[tid]     = d0*inv*gam[tid]     + bet[tid];
    row[tid+256] = d1*inv*gam[tid+256] + bet[tid+256];
}

// ---------------- final state copy ------------------------------------------
__global__ void __launch_bounds__(256) copyhc_k(const float* __restrict__ hf,
                                                const float* __restrict__ cf,
                                                float* __restrict__ out)
{
    int idx = blockIdx.x*256 + threadIdx.x;
    const size_t L = (size_t)Bsz*Ssz*Vsz;
    out[L + idx]       = hf[idx];
    out[L + NBR + idx] = cf[idx];
}

// =============================================================================
extern "C" void kernel_launch(void* const* d_in, const int* in_sizes, int n_in,
                              void* d_out, int out_size)
{
    const int*   x      = (const int*)  d_in[0];
    const float* h0     = (const float*)d_in[1];
    const float* c0     = (const float*)d_in[2];
    const float* emb    = (const float*)d_in[3];
    const float* W_ih   = (const float*)d_in[4];
    const float* b_ih   = (const float*)d_in[5];
    const float* W_hh   = (const float*)d_in[6];
    const float* b_hh   = (const float*)d_in[7];
    const float* W_np   = (const float*)d_in[8];
    const float* b_np   = (const float*)d_in[9];
    const float* in_w   = (const float*)d_in[10];
    const float* in_b   = (const float*)d_in[11];
    const float* op_w   = (const float*)d_in[12];
    const float* op_b   = (const float*)d_in[13];
    const float* ln_g   = (const float*)d_in[14];
    const float* ln_b   = (const float*)d_in[15];
    const float* head_w = (const float*)d_in[16];
    const float* head_b = (const float*)d_in[17];
    float* out = (float*)d_out;

    cudaFuncSetAttribute(tgemm_k<1>, cudaFuncAttributeMaxDynamicSharedMemorySize, TG_SMEM);
    cudaFuncSetAttribute(tgemm_k<2>, cudaFuncAttributeMaxDynamicSharedMemorySize, TG_SMEM);
    cudaFuncSetAttribute(tgemm_k<3>, cudaFuncAttributeMaxDynamicSharedMemorySize, TG_SMEM);
    cudaFuncSetAttribute(lstm_mma,   cudaFuncAttributeMaxDynamicSharedMemorySize, L_SMEM);

    float *pX,*pGih,*pHall,*pCf,*pQ,*pWnk,*pWnv,*pCk,*pCv,*pK,*pV,*pAtt,*pMix;
    __nv_bfloat16 *pWihH,*pWihL,*pHeadH,*pHeadL,*pXH,*pXL,*pHallH,*pHallL;
    __nv_bfloat16 *pWnkH,*pWnkL,*pWnvH,*pWnvL,*pMixH,*pMixL;
    __half *pWhh;
    cudaGetSymbolAddress((void**)&pX,    g_X);
    cudaGetSymbolAddress((void**)&pGih,  g_Gih);
    cudaGetSymbolAddress((void**)&pHall, g_hall);
    cudaGetSymbolAddress((void**)&pCf,   g_cf);
    cudaGetSymbolAddress((void**)&pQ,    g_q);
    cudaGetSymbolAddress((void**)&pWnk,  g_Wnk);
    cudaGetSymbolAddress((void**)&pWnv,  g_Wnv);
    cudaGetSymbolAddress((void**)&pCk,   g_ck);
    cudaGetSymbolAddress((void**)&pCv,   g_cv);
    cudaGetSymbolAddress((void**)&pK,    g_k);
    cudaGetSymbolAddress((void**)&pV,    g_v);
    cudaGetSymbolAddress((void**)&pAtt,  g_att);
    cudaGetSymbolAddress((void**)&pMix,  g_mix);
    cudaGetSymbolAddress((void**)&pWihH, bWih_h);  cudaGetSymbolAddress((void**)&pWihL, bWih_l);
    cudaGetSymbolAddress((void**)&pWhh,  hWhh);
    cudaGetSymbolAddress((void**)&pHeadH,bHead_h); cudaGetSymbolAddress((void**)&pHeadL,bHead_l);
    cudaGetSymbolAddress((void**)&pXH,   bX_h);    cudaGetSymbolAddress((void**)&pXL,   bX_l);
    cudaGetSymbolAddress((void**)&pHallH,bHall_h); cudaGetSymbolAddress((void**)&pHallL,bHall_l);
    cudaGetSymbolAddress((void**)&pWnkH, bWnk_h);  cudaGetSymbolAddress((void**)&pWnkL, bWnk_l);
    cudaGetSymbolAddress((void**)&pWnvH, bWnv_h);  cudaGetSymbolAddress((void**)&pWnvL, bWnv_l);
    cudaGetSymbolAddress((void**)&pMixH, bMix_h);  cudaGetSymbolAddress((void**)&pMixL, bMix_l);

    // Launch order: index 3 = lstm_mma (ncu captures 4th launch)
    embed_split_k<<<(Mtok*Dsz)/256, 256>>>(x, emb);                              // 0
    splitW2_k<<<2*(Nly*G4*Dsz)/256,256>>>(W_ih,pWihH,pWihL, W_hh,pWhh,
                                          Nly*G4*Dsz);                           // 1 (+bar=0)
    tgemm_k<1><<<dim3(16,16,16),256,TG_SMEM>>>(pXH,pXL,pWihH,pWihL,pGih,b_ih,b_hh); // 2
    lstm_mma<<<128,256,L_SMEM>>>(pWhh, h0, c0, pHall, pHallH, pHallL, pGih, pCf);   // 3 <- profiled

    // Phase 1 remainder + Phase 3
    split_k<<<(Vsz*Dsz)/256,256>>>(head_w, pHeadH, pHeadL, Vsz*Dsz);
    gemm_k<0><<<dim3(4,16),256>>>(pX, in_w, pQ, in_b, nullptr);
    gemm_k<5><<<dim3(4,4,16),256>>>(in_w +   Dsz*Dsz, W_np, pWnk, nullptr, nullptr);
    gemm_k<5><<<dim3(4,4,16),256>>>(in_w + 2*Dsz*Dsz, W_np, pWnv, nullptr, nullptr);
    split_k<<<(Nly*Dsz*Rsz)/256,256>>>(pWnk, pWnkH, pWnkL, Nly*Dsz*Rsz);
    split_k<<<(Nly*Dsz*Rsz)/256,256>>>(pWnv, pWnvH, pWnvL, Nly*Dsz*Rsz);
    ckcv_k<<<(Nly*Dsz)/256, 256>>>(in_w, in_b, b_np);
    tgemm_k<3><<<dim3(4,16,16),256,TG_SMEM>>>(pHallH,pHallL,pWnkH,pWnkL,pK,pCk,nullptr);
    tgemm_k<3><<<dim3(4,16,16),256,TG_SMEM>>>(pHallH,pHallL,pWnvH,pWnvL,pV,pCv,nullptr);
    attn_k<<<Mtok,256>>>();
    gemm_k<4><<<dim3(4,16),256>>>(pAtt, op_w, pMix, op_b, pX);
    ln_k<<<Mtok,256>>>(ln_g, ln_b);
    split_k<<<(Mtok*Dsz)/256,256>>>(pMix, pMixH, pMixL, Mtok*Dsz);
    tgemm_k<2><<<dim3(250,16),256,TG_SMEM>>>(pMixH,pMixL,pHeadH,pHeadL,out,head_b,nullptr);

    // hf / cf
    copyhc_k<<<NBR/256,256>>>(pHall, pCf, out);
}

// round 13
// speedup vs baseline: 2.7520x; 1.1702x over previous
#include <cuda_runtime.h>
#include <cuda_bf16.h>
#include <cuda_fp16.h>
#include <math.h>
#include <stdint.h>

// Problem dims
#define Bsz 8
#define Ssz 256
#define Vsz 32000
#define Dsz 512
#define Nly 16
#define Rsz 512
#define G4  2048            // 4*R
#define Mtok (Bsz*Ssz)      // 2048 tokens
#define NBR (Nly*Bsz*Rsz)   // 65536

// ---------------- scratch (static device globals; no runtime alloc) ----------
__device__ float g_X   [Mtok*Dsz];
__device__ float g_Gih [(size_t)Ssz*Nly*Bsz*G4];         // [t][n][b][g]
__device__ float g_hall[NBR];                            // final-step h only (hf)
__device__ float g_cf  [NBR];
__device__ float g_q   [Mtok*Dsz];
__device__ float g_Wnk [Nly*Dsz*Rsz];
__device__ float g_Wnv [Nly*Dsz*Rsz];
__device__ float g_ck  [Nly*Dsz];
__device__ float g_cv  [Nly*Dsz];
__device__ float g_k   [(size_t)Mtok*Nly*Dsz];
__device__ float g_v   [(size_t)Mtok*Nly*Dsz];
__device__ float g_att [Mtok*Dsz];
__device__ float g_mix [Mtok*Dsz];
__device__ unsigned g_bars[Nly];

// fp16 buffers
__device__ __align__(16) __half hWih   [(size_t)Nly*G4*Dsz];   // single
__device__ __align__(16) __half hWhh   [(size_t)Nly*G4*Dsz];   // single
__device__ __align__(16) __half hHead  [(size_t)Vsz*Dsz];      // single
__device__ __align__(16) __half hX_h   [Mtok*Dsz];
__device__ __align__(16) __half hX_l   [Mtok*Dsz];
__device__ __align__(16) __half hHall_h[(size_t)Ssz*NBR];
__device__ __align__(16) __half hHall_l[(size_t)Ssz*NBR];
__device__ __align__(16) __half hWnk   [Nly*Dsz*Rsz];          // single
__device__ __align__(16) __half hWnv   [Nly*Dsz*Rsz];          // single
__device__ __align__(16) __half hMix_h [Mtok*Dsz];
__device__ __align__(16) __half hMix_l [Mtok*Dsz];

__device__ __forceinline__ float sigm(float x){ return 1.f/(1.f+expf(-x)); }

// ======================= PTX helpers (compute_103-safe) ======================
__device__ __forceinline__ void cp16(uint32_t sdst, const void* gsrc){
    asm volatile("cp.async.cg.shared.global [%0], [%1], 16;" :: "r"(sdst), "l"(gsrc));
}
__device__ __forceinline__ void cp_commit(){
    asm volatile("cp.async.commit_group;" ::: "memory");
}
template<int N>
__device__ __forceinline__ void cp_wait(){
    asm volatile("cp.async.wait_group %0;" :: "n"(N) : "memory");
}
__device__ __forceinline__ void ldsm_x4(uint32_t* r, uint32_t addr){
    asm volatile("ldmatrix.sync.aligned.m8n8.x4.shared.b16 {%0,%1,%2,%3}, [%4];"
        : "=r"(r[0]),"=r"(r[1]),"=r"(r[2]),"=r"(r[3]) : "r"(addr));
}
__device__ __forceinline__ void mma16816h(float* d, const uint32_t* a, const uint32_t* b){
    asm volatile("mma.sync.aligned.m16n8k16.row.col.f32.f16.f16.f32 "
        "{%0,%1,%2,%3}, {%4,%5,%6,%7}, {%8,%9}, {%0,%1,%2,%3};"
        : "+f"(d[0]),"+f"(d[1]),"+f"(d[2]),"+f"(d[3])
        : "r"(a[0]),"r"(a[1]),"r"(a[2]),"r"(a[3]), "r"(b[0]),"r"(b[1]));
}

// ======================= mma.sync fp16 2-product GEMM ========================
// C(128x128 tile) = (Ah+Al)[Mx512] @ B^T[Nx512] in fp32 (2 MMAs per K16)
// MODE 1: Gih ; MODE 2: head logits ; MODE 3: k/v (A row remap)
#define TG_LD   72
#define TG_BLK  (128*TG_LD)
#define TG_SMEM (2*3*TG_BLK*2)     // 2 stages x {Ah,Al,B}

template<int MODE>
__global__ void __launch_bounds__(256,1) tgemm_k(
    const __half* __restrict__ Ah, const __half* __restrict__ Al,
    const __half* __restrict__ B,
    float* __restrict__ C, const float* __restrict__ bias,
    const float* __restrict__ bias2)
{
    extern __shared__ __align__(16) __half smb[];
    uint32_t sbase = (uint32_t)__cvta_generic_to_shared(smb);
    int tid = threadIdx.x, wid = tid>>5, lane = tid&31;
    int wm = wid>>2, wn = wid&3;
    int bn = blockIdx.x, bm = blockIdx.y, nz = blockIdx.z;

    const __half *BP = B;
    if (MODE==1) BP += (size_t)nz*G4 *512;
    if (MODE==3) BP += (size_t)nz*Dsz*512;

    int lrow = tid>>1, lk = (tid&1)*32;
    int am = bm*128 + lrow;
    int ag = (MODE==3) ? ((am>>3)*128 + nz*8 + (am&7)) : am;
    const __half* gAh = Ah + (size_t)ag*512 + lk;
    const __half* gAl = Al + (size_t)ag*512 + lk;
    const __half* gB  = BP + (size_t)(bn*128 + lrow)*512 + lk;
    uint32_t sRowOff = (uint32_t)(lrow*TG_LD + lk)*2;

    int aRowL = wm*64 + (lane&15);
    int aColL = (lane>>4)*8;
    int bRowL = wn*32 + ((lane>>4)&1)*8 + (lane&7);
    int bColL = ((lane>>3)&1)*8;

    float acc[4][4][4];
    #pragma unroll
    for (int i=0;i<4;i++){
        #pragma unroll
        for (int j=0;j<4;j++){
            acc[i][j][0]=0.f; acc[i][j][1]=0.f; acc[i][j][2]=0.f; acc[i][j][3]=0.f;
        }
    }

    auto issue = [&](int s, int kb){
        uint32_t d0 = sbase + (uint32_t)((s*3+0)*TG_BLK)*2 + sRowOff;
        uint32_t d1 = sbase + (uint32_t)((s*3+1)*TG_BLK)*2 + sRowOff;
        uint32_t d2 = sbase + (uint32_t)((s*3+2)*TG_BLK)*2 + sRowOff;
        #pragma unroll
        for (int i=0;i<4;i++){
            cp16(d0 + i*16, gAh + kb + i*8);
            cp16(d1 + i*16, gAl + kb + i*8);
            cp16(d2 + i*16, gB  + kb + i*8);
        }
        cp_commit();
    };

    issue(0, 0);
    for (int c=0;c<8;c++){
        int s = c&1;
        if (c<7) issue(s^1, (c+1)*64);
        if (c<7) cp_wait<1>(); else cp_wait<0>();
        __syncthreads();

        #pragma unroll
        for (int ks=0; ks<4; ks++){
            int kc = ks*16;
            uint32_t ah[4][4], al[4][4];
            #pragma unroll
            for (int mf=0; mf<4; mf++){
                uint32_t addrh = sbase + (uint32_t)((s*3+0)*TG_BLK + (aRowL+mf*16)*TG_LD + aColL + kc)*2;
                uint32_t addrl = sbase + (uint32_t)((s*3+1)*TG_BLK + (aRowL+mf*16)*TG_LD + aColL + kc)*2;
                ldsm_x4(ah[mf], addrh);
                ldsm_x4(al[mf], addrl);
            }
            uint32_t bb[2][4];
            #pragma unroll
            for (int nfh=0; nfh<2; nfh++){
                uint32_t addrb = sbase + (uint32_t)((s*3+2)*TG_BLK + (bRowL+nfh*16)*TG_LD + bColL + kc)*2;
                ldsm_x4(bb[nfh], addrb);
            }
            #pragma unroll
            for (int mf=0; mf<4; mf++){
                #pragma unroll
                for (int nf=0; nf<4; nf++){
                    const uint32_t* bp = &bb[nf>>1][(nf&1)*2];
                    mma16816h(acc[mf][nf], ah[mf], bp);
                    mma16816h(acc[mf][nf], al[mf], bp);
                }
            }
        }
        __syncthreads();
    }

    int rA = lane>>2, cA = (lane&3)*2;
    #pragma unroll
    for (int mf=0; mf<4; mf++){
        #pragma unroll
        for (int nf=0; nf<4; nf++){
            #pragma unroll
            for (int half=0; half<2; half++){
                int m  = bm*128 + wm*64 + mf*16 + rA + half*8;
                int jc = bn*128 + wn*32 + nf*8 + cA;
                float v0 = acc[mf][nf][half*2+0];
                float v1 = acc[mf][nf][half*2+1];
                if (MODE==1){
                    v0 += bias[nz*G4+jc]   + bias2[nz*G4+jc];
                    v1 += bias[nz*G4+jc+1] + bias2[nz*G4+jc+1];
                    int t=m>>3, b=m&7;
                    float2 w = {v0,v1};
                    *(float2*)&C[(size_t)(t*128+nz*8+b)*G4 + jc] = w;
                } else if (MODE==2){
                    v0 += bias[jc]; v1 += bias[jc+1];
                    int t=m>>3, b=m&7;
                    float2 w = {v0,v1};
                    *(float2*)&C[(size_t)(b*Ssz+t)*Vsz + jc] = w;
                } else {
                    v0 += bias[nz*Dsz+jc]; v1 += bias[nz*Dsz+jc+1];
                    float2 w = {v0,v1};
                    *(float2*)&C[(size_t)(m*Nly+nz)*Dsz + jc] = w;
                }
            }
        }
    }
}

// ---------------- fp32 -> fp16 hi/lo split ------------------------------------
__global__ void __launch_bounds__(256) splitH_k(const float* __restrict__ src,
                                                __half* __restrict__ hi,
                                                __half* __restrict__ lo,
                                                int n)
{
    int i = blockIdx.x*256 + threadIdx.x;
    if (i < n){
        float x = src[i];
        __half h = __float2half(x);
        hi[i] = h;
        lo[i] = __float2half(x - __half2float(h));
    }
}

// ---------------- fp32 -> fp16 single convert ---------------------------------
__global__ void __launch_bounds__(256) cvtH_k(const float* __restrict__ src,
                                              __half* __restrict__ dst, int n)
{
    int i = blockIdx.x*256 + threadIdx.x;
    if (i < n) dst[i] = __float2half(src[i]);
}

// ---------------- fused: embedding gather + fp16 split ------------------------
__global__ void __launch_bounds__(256) embed_split_k(const int* __restrict__ x,
                                                     const float* __restrict__ emb)
{
    int idx = blockIdx.x*256 + threadIdx.x;
    int m = idx>>9, d = idx&511;
    int t = m>>3, b = m&7;
    float v = emb[(size_t)x[b*Ssz+t]*Dsz + d];
    g_X[idx] = v;
    __half h = __float2half(v);
    hX_h[idx] = h;
    hX_l[idx] = __float2half(v - __half2float(h));
}

// ---------------- fused: Wih + Whh -> fp16 + zero layer barriers --------------
__global__ void __launch_bounds__(256) cvtW2_k(const float* __restrict__ s1,
                                               __half* __restrict__ d1,
                                               const float* __restrict__ s2,
                                               __half* __restrict__ d2,
                                               int n)
{
    int i = blockIdx.x*256 + threadIdx.x;
    if (i < Nly) g_bars[i] = 0u;
    if (i < n) d1[i] = __float2half(s1[i]);
    else       d2[i - n] = __float2half(s2[i - n]);
}

// ---------------- SIMT 128x128 GEMM (small modes 0,4,5) ----------------------
template<int MODE>
__global__ void __launch_bounds__(256, 2) gemm_k(
    const float* __restrict__ A, const float* __restrict__ Bw,
    float* __restrict__ C, const float* __restrict__ bias,
    const float* __restrict__ resid)
{
    const int K = 512;
    __shared__ float As[2][8][132];
    __shared__ float Bs[2][8][132];
    int tid = threadIdx.x;
    int bn = blockIdx.x, bm = blockIdx.y, n = blockIdx.z;

    const float* Bp = Bw;
    if (MODE==5) Bp += (size_t)n*Dsz*Rsz;

    int lRow = tid>>1, lK = (tid&1)<<2;
    const float* Aptr = A + (size_t)(bm*128+lRow)*K + lK;
    const float* Bptr;
    int b_k=0, b_j=0;
    if (MODE==5){
        b_k = tid>>5; b_j = (tid&31)<<2;
        Bptr = Bp + (size_t)b_k*Rsz + bn*128 + b_j;
    } else {
        Bptr = Bp + (size_t)(bn*128 + lRow)*K + lK;
    }
    int ty = tid>>4, tx = tid&15;
    float acc[8][8] = {};
    float4 aReg, bReg;

    aReg = *(const float4*)(Aptr);
    bReg = *(const float4*)(Bptr);
    As[0][lK+0][lRow]=aReg.x; As[0][lK+1][lRow]=aReg.y;
    As[0][lK+2][lRow]=aReg.z; As[0][lK+3][lRow]=aReg.w;
    if (MODE==5){ *(float4*)&Bs[0][b_k][b_j] = bReg; }
    else {
        Bs[0][lK+0][lRow]=bReg.x; Bs[0][lK+1][lRow]=bReg.y;
        Bs[0][lK+2][lRow]=bReg.z; Bs[0][lK+3][lRow]=bReg.w;
    }
    __syncthreads();

    int buf = 0;
    for (int kb=8; kb<=K; kb+=8){
        bool more = (kb < K);
        if (more){
            aReg = *(const float4*)(Aptr + kb);
            bReg = (MODE==5) ? *(const float4*)(Bptr + (size_t)kb*Rsz)
                             : *(const float4*)(Bptr + kb);
        }
        #pragma unroll
        for (int k=0;k<8;k++){
            float4 a0 = *(const float4*)&As[buf][k][ty<<2];
            float4 a1 = *(const float4*)&As[buf][k][(ty<<2)+64];
            float4 b0 = *(const float4*)&Bs[buf][k][tx<<2];
            float4 b1 = *(const float4*)&Bs[buf][k][(tx<<2)+64];
            float a[8]={a0.x,a0.y,a0.z,a0.w,a1.x,a1.y,a1.z,a1.w};
            float b[8]={b0.x,b0.y,b0.z,b0.w,b1.x,b1.y,b1.z,b1.w};
            #pragma unroll
            for(int i=0;i<8;i++)
                #pragma unroll
                for(int j=0;j<8;j++) acc[i][j] += a[i]*b[j];
        }
        if (more){
            int nb = buf^1;
            As[nb][lK+0][lRow]=aReg.x; As[nb][lK+1][lRow]=aReg.y;
            As[nb][lK+2][lRow]=aReg.z; As[nb][lK+3][lRow]=aReg.w;
            if (MODE==5){ *(float4*)&Bs[nb][b_k][b_j] = bReg; }
            else {
                Bs[nb][lK+0][lRow]=bReg.x; Bs[nb][lK+1][lRow]=bReg.y;
                Bs[nb][lK+2][lRow]=bReg.z; Bs[nb][lK+3][lRow]=bReg.w;
            }
            __syncthreads();
            buf = nb;
        }
    }

    #pragma unroll
    for(int i=0;i<8;i++){
        int m = bm*128 + (ty<<2) + (i&3) + ((i>>2)<<6);
        #pragma unroll
        for(int j=0;j<8;j++){
            int jc = bn*128 + (tx<<2) + (j&3) + ((j>>2)<<6);
            float v = acc[i][j];
            if (MODE==0){ v += bias[jc]; C[(size_t)m*Dsz+jc]=v; }
            else if (MODE==4){ v += bias[jc] + resid[(size_t)m*Dsz+jc]; C[(size_t)m*Dsz+jc]=v; }
            else { C[(size_t)n*Dsz*Rsz + (size_t)m*Rsz + jc]=v; }
        }
    }
}

// ---------------- combined k/v biases ----------------------------------------
__global__ void __launch_bounds__(256) ckcv_k(const float* __restrict__ in_w,
                                              const float* __restrict__ in_b,
                                              const float* __restrict__ b_np)
{
    int idx = blockIdx.x*256 + threadIdx.x;
    int n = idx>>9, dc = idx&511;
    const float* Wk = in_w + Dsz*Dsz;
    const float* Wv = in_w + 2*Dsz*Dsz;
    const float* bn = b_np + n*Dsz;
    float sk = in_b[Dsz+dc], sv = in_b[2*Dsz+dc];
    for (int j=0;j<Dsz;j++){
        float bj = bn[j];
        sk += Wk[(size_t)dc*Dsz+j]*bj;
        sv += Wv[(size_t)dc*Dsz+j]*bj;
    }
    g_ck[idx]=sk; g_cv[idx]=sv;
}

// ---------------- persistent LSTM recurrence (fp16 W, per-layer barrier) -----
#define LSW 40
#define LSH 536
#define L_WSBLK (256*LSW)
#define L_NSTG 4
#define L_OFF_HH (L_NSTG*L_WSBLK*2)
#define L_OFF_HL (L_OFF_HH + 8*LSH*2)
#define L_OFF_GA (L_OFF_HL + 8*LSH*2)
#define L_OFF_CS (L_OFF_GA + 256*9*4)
#define L_OFF_GT (L_OFF_CS + 64*9*4)
#define L_SMEM   (L_OFF_GT + 8192)

__global__ void __launch_bounds__(256,1) lstm_mma(
    const __half* __restrict__ W,
    const float* __restrict__ h0, const float* __restrict__ c0,
    float* __restrict__ hfinal,
    __half* __restrict__ hall_h, __half* __restrict__ hall_l,
    const float* __restrict__ Gih, float* __restrict__ cfinal)
{
    extern __shared__ __align__(16) char sm[];
    uint32_t sbase = (uint32_t)__cvta_generic_to_shared(sm);
    __half* hh_s = (__half*)(sm + L_OFF_HH);
    __half* hl_s = (__half*)(sm + L_OFF_HL);
    float* ga  = (float*)(sm + L_OFF_GA);   // [256][9]
    float* cs  = (float*)(sm + L_OFF_CS);   // [64][9]
    float* gts = (float*)(sm + L_OFF_GT);   // [8][4][64] prefetched Gih slice

    int tid = threadIdx.x, wid = tid>>5, lane = tid&31;
    int chunk = blockIdx.x & 7, n = blockIdx.x >> 3;

    int m_row = tid;
    int gateT = m_row>>6, rlocT = m_row&63;
    size_t grow = (size_t)(n*G4 + gateT*512 + chunk*64 + rlocT)*512;
    const __half* gW = W + grow;

    for (int idx=tid; idx<512; idx+=256){
        int b = idx>>6, r = idx&63;
        cs[r*9+b] = c0[(size_t)(n*8+b)*Rsz + chunk*64 + r];
    }

    int aRow = lane&15, aCol = (lane>>4)*8;
    int bN = lane>>2, bK2 = 2*(lane&3);

    volatile unsigned* barp = &g_bars[n];

    auto issueW = [&](int kc, int s){
        uint32_t dw = sbase + (uint32_t)(s*L_WSBLK + m_row*LSW)*2;
        const __half* sw = gW + kc*32;
        #pragma unroll
        for (int i=0;i<4;i++) cp16(dw + i*16, sw + i*8);
        cp_commit();
    };
    auto issuePrologue = [&](int t){
        const float* GtBase = Gih + (size_t)t*Nly*Bsz*G4 + (size_t)(n*8)*G4 + chunk*64;
        #pragma unroll
        for (int jj=0; jj<2; jj++){
            int j = tid + jj*256;
            int b = j>>6, gate = (j>>4)&3, quad = j&15;
            cp16(sbase + L_OFF_GT + (uint32_t)j*16,
                 GtBase + (size_t)b*G4 + gate*512 + quad*4);
        }
        uint32_t dw = sbase + (uint32_t)(0*L_WSBLK + m_row*LSW)*2;
        #pragma unroll
        for (int i=0;i<4;i++) cp16(dw + i*16, gW + i*8);
        cp_commit();
        issueW(1,1);
        issueW(2,2);
    };

    issuePrologue(0);

    for (int t=0; t<Ssz; t++){
        // ---- load h (prev) into smem fp16 hi/lo ----
        if (t==0){
            for (int idx=tid; idx<4096; idx+=256){
                int b = idx>>9, r = idx&511;
                float v = h0[(size_t)(n*8+b)*Rsz + r];
                __half hh = __float2half(v);
                hh_s[b*LSH + r] = hh;
                hl_s[b*LSH + r] = __float2half(v - __half2float(hh));
            }
        } else {
            const __half* ph = hall_h + (size_t)(t-1)*NBR + (size_t)(n*8)*Rsz;
            const __half* pl = hall_l + (size_t)(t-1)*NBR + (size_t)(n*8)*Rsz;
            for (int idx=tid; idx<512; idx+=256){
                int b = idx>>6, r8 = (idx&63)*8;
                *(uint4*)(hh_s + b*LSH + r8) = *(const uint4*)(ph + b*Rsz + r8);
                *(uint4*)(hl_s + b*LSH + r8) = *(const uint4*)(pl + b*Rsz + r8);
            }
        }

        float acc[2][4];
        #pragma unroll
        for (int f=0;f<2;f++){ acc[f][0]=0.f; acc[f][1]=0.f; acc[f][2]=0.f; acc[f][3]=0.f; }

        for (int kc=0; kc<16; kc++){
            int s = kc&3;
            if      (kc<=13) cp_wait<2>();
            else if (kc==14) cp_wait<1>();
            else             cp_wait<0>();
            __syncthreads();
            if (kc+3 < 16) issueW(kc+3, (kc+3)&3);
            #pragma unroll
            for (int kf=0; kf<2; kf++){
                int kbase = kc*32 + kf*16;
                uint32_t bhr[2], blr[2];
                uint32_t hoff = (uint32_t)(bN*LSH + kbase + bK2)*2;
                bhr[0] = *(const uint32_t*)(sm + L_OFF_HH + hoff);
                bhr[1] = *(const uint32_t*)(sm + L_OFF_HH + hoff + 16);
                blr[0] = *(const uint32_t*)(sm + L_OFF_HL + hoff);
                blr[1] = *(const uint32_t*)(sm + L_OFF_HL + hoff + 16);
                #pragma unroll
                for (int f=0; f<2; f++){
                    int mbase = wid*32 + f*16;
                    uint32_t aw[4];
                    uint32_t wadr = (uint32_t)((mbase + aRow)*LSW + kf*16 + aCol)*2;
                    ldsm_x4(aw, sbase + (uint32_t)(s*L_WSBLK)*2 + wadr);
                    mma16816h(acc[f], aw, bhr);
                    mma16816h(acc[f], aw, blr);
                }
            }
        }

        int rA = lane>>2, cB = 2*(lane&3);
        #pragma unroll
        for (int f=0; f<2; f++){
            int m = wid*32 + f*16 + rA;
            ga[m*9 + cB]       = acc[f][0];
            ga[m*9 + cB + 1]   = acc[f][1];
            ga[(m+8)*9 + cB]   = acc[f][2];
            ga[(m+8)*9 + cB+1] = acc[f][3];
        }
        __syncthreads();

        for (int idx=tid; idx<512; idx+=256){
            int b = idx>>6, r = idx&63;
            float iv = ga[(      r)*9 + b] + gts[b*256       + r];
            float fv = ga[( 64 + r)*9 + b] + gts[b*256 +  64 + r];
            float gv = ga[(128 + r)*9 + b] + gts[b*256 + 128 + r];
            float ov = ga[(192 + r)*9 + b] + gts[b*256 + 192 + r];
            float cp = cs[r*9+b];
            float cn = sigm(fv)*cp + sigm(iv)*tanhf(gv);
            cs[r*9+b] = cn;
            float hv = sigm(ov)*tanhf(cn);
            size_t ho = (size_t)t*NBR + (size_t)(n*8+b)*Rsz + chunk*64 + r;
            __half hh = __float2half(hv);
            hall_h[ho] = hh;
            hall_l[ho] = __float2half(hv - __half2float(hh));
            if (t == Ssz-1)
                hfinal[(size_t)(n*8+b)*Rsz + chunk*64 + r] = hv;
        }
        __syncthreads();

        if (t+1 < Ssz){
            issuePrologue(t+1);
            __threadfence();
            if (tid==0){
                atomicAdd(&g_bars[n], 1u);
                unsigned target = 8u*(unsigned)(t+1);
                while (*barp < target) { }
                __threadfence();
            }
            __syncthreads();
        }
    }

    for (int idx=tid; idx<512; idx+=256){
        int b = idx>>6, r = idx&63;
        cfinal[(size_t)(n*8+b)*Rsz + chunk*64 + r] = cs[r*9+b];
    }
}

// ---------------- attention per token ----------------------------------------
__global__ void __launch_bounds__(256) attn_k()
{
    int m = blockIdx.x, tid = threadIdx.x;
    __shared__ float sq[512];
    __shared__ float sc[8][16];
    __shared__ float sw[8][16];
    sq[tid]     = g_q[(size_t)m*Dsz + tid];
    sq[tid+256] = g_q[(size_t)m*Dsz + tid + 256];
    __syncthreads();
    if (tid < 128){
        int h = tid>>4, nn = tid&15;
        const float* kp = g_k + (size_t)(m*Nly+nn)*Dsz + h*64;
        float s = 0.f;
        #pragma unroll 8
        for (int e=0;e<64;e++) s += sq[h*64+e]*kp[e];
        sc[h][nn] = s*0.125f;
    }
    __syncthreads();
    if (tid < 8){
        float mx = -1e30f;
        for (int nn=0;nn<16;nn++) mx = fmaxf(mx, sc[tid][nn]);
        float e[16], sum = 0.f;
        for (int nn=0;nn<16;nn++){ e[nn]=expf(sc[tid][nn]-mx); sum+=e[nn]; }
        float inv = 1.f/sum;
        for (int nn=0;nn<16;nn++) sw[tid][nn]=e[nn]*inv;
    }
    __syncthreads();
    for (int idx=tid; idx<512; idx+=256){
        int h = idx>>6;
        float s = 0.f;
        #pragma unroll
        for (int nn=0;nn<16;nn++)
            s += sw[h][nn]*g_v[(size_t)(m*Nly+nn)*Dsz + idx];
        g_att[(size_t)m*Dsz + idx] = s;
    }
}

// ---------------- layernorm (in-place on g_mix) ------------------------------
__global__ void __launch_bounds__(256) ln_k(const float* __restrict__ gam,
                                            const float* __restrict__ bet)
{
    int m = blockIdx.x, tid = threadIdx.x;
    __shared__ float sh[8];
    __shared__ float sh2[8];
    float* row = g_mix + (size_t)m*Dsz;
    float v0 = row[tid], v1 = row[tid+256];
    int lane = tid&31, w = tid>>5;

    float s = v0+v1;
    #pragma unroll
    for (int o=16;o>0;o>>=1) s += __shfl_xor_sync(0xffffffffu, s, o);
    if (lane==0) sh[w]=s;
    __syncthreads();
    float tot = sh[0]+sh[1]+sh[2]+sh[3]+sh[4]+sh[5]+sh[6]+sh[7];
    float mu = tot*(1.f/512.f);

    float d0=v0-mu, d1=v1-mu;
    float s2 = d0*d0+d1*d1;
    #pragma unroll
    for (int o=16;o>0;o>>=1) s2 += __shfl_xor_sync(0xffffffffu, s2, o);
    if (lane==0) sh2[w]=s2;
    __syncthreads();
    float tot2 = sh2[0]+sh2[1]+sh2[2]+sh2[3]+sh2[4]+sh2[5]+sh2[6]+sh2[7];
    float inv = rsqrtf(tot2*(1.f/512.f) + 1e-5f);

    row[tid]     = d0*inv*gam[tid]     + bet[tid];
    row[tid+256] = d1*inv*gam[tid+256] + bet[tid+256];
}

// ---------------- final state copy ------------------------------------------
__global__ void __launch_bounds__(256) copyhc_k(const float* __restrict__ hf,
                                                const float* __restrict__ cf,
                                                float* __restrict__ out)
{
    int idx = blockIdx.x*256 + threadIdx.x;
    const size_t L = (size_t)Bsz*Ssz*Vsz;
    out[L + idx]       = hf[idx];
    out[L + NBR + idx] = cf[idx];
}

// =============================================================================
extern "C" void kernel_launch(void* const* d_in, const int* in_sizes, int n_in,
                              void* d_out, int out_size)
{
    const int*   x      = (const int*)  d_in[0];
    const float* h0     = (const float*)d_in[1];
    const float* c0     = (const float*)d_in[2];
    const float* emb    = (const float*)d_in[3];
    const float* W_ih   = (const float*)d_in[4];
    const float* b_ih   = (const float*)d_in[5];
    const float* W_hh   = (const float*)d_in[6];
    const float* b_hh   = (const float*)d_in[7];
    const float* W_np   = (const float*)d_in[8];
    const float* b_np   = (const float*)d_in[9];
    const float* in_w   = (const float*)d_in[10];
    const float* in_b   = (const float*)d_in[11];
    const float* op_w   = (const float*)d_in[12];
    const float* op_b   = (const float*)d_in[13];
    const float* ln_g   = (const float*)d_in[14];
    const float* ln_b   = (const float*)d_in[15];
    const float* head_w = (const float*)d_in[16];
    const float* head_b = (const float*)d_in[17];
    float* out = (float*)d_out;

    cudaFuncSetAttribute(tgemm_k<1>, cudaFuncAttributeMaxDynamicSharedMemorySize, TG_SMEM);
    cudaFuncSetAttribute(tgemm_k<2>, cudaFuncAttributeMaxDynamicSharedMemorySize, TG_SMEM);
    cudaFuncSetAttribute(tgemm_k<3>, cudaFuncAttributeMaxDynamicSharedMemorySize, TG_SMEM);
    cudaFuncSetAttribute(lstm_mma,   cudaFuncAttributeMaxDynamicSharedMemorySize, L_SMEM);

    float *pX,*pGih,*pHall,*pCf,*pQ,*pWnk,*pWnv,*pCk,*pCv,*pK,*pV,*pAtt,*pMix;
    __half *pWih,*pWhh,*pHead,*pXH,*pXL,*pHallH,*pHallL,*pWnkH,*pWnvH,*pMixH,*pMixL;
    cudaGetSymbolAddress((void**)&pX,    g_X);
    cudaGetSymbolAddress((void**)&pGih,  g_Gih);
    cudaGetSymbolAddress((void**)&pHall, g_hall);
    cudaGetSymbolAddress((void**)&pCf,   g_cf);
    cudaGetSymbolAddress((void**)&pQ,    g_q);
    cudaGetSymbolAddress((void**)&pWnk,  g_Wnk);
    cudaGetSymbolAddress((void**)&pWnv,  g_Wnv);
    cudaGetSymbolAddress((void**)&pCk,   g_ck);
    cudaGetSymbolAddress((void**)&pCv,   g_cv);
    cudaGetSymbolAddress((void**)&pK,    g_k);
    cudaGetSymbolAddress((void**)&pV,    g_v);
    cudaGetSymbolAddress((void**)&pAtt,  g_att);
    cudaGetSymbolAddress((void**)&pMix,  g_mix);
    cudaGetSymbolAddress((void**)&pWih,  hWih);
    cudaGetSymbolAddress((void**)&pWhh,  hWhh);
    cudaGetSymbolAddress((void**)&pHead, hHead);
    cudaGetSymbolAddress((void**)&pXH,   hX_h);    cudaGetSymbolAddress((void**)&pXL, hX_l);
    cudaGetSymbolAddress((void**)&pHallH,hHall_h); cudaGetSymbolAddress((void**)&pHallL,hHall_l);
    cudaGetSymbolAddress((void**)&pWnkH, hWnk);
    cudaGetSymbolAddress((void**)&pWnvH, hWnv);
    cudaGetSymbolAddress((void**)&pMixH, hMix_h);  cudaGetSymbolAddress((void**)&pMixL, hMix_l);

    // Launch order: index 3 = lstm_mma
    embed_split_k<<<(Mtok*Dsz)/256, 256>>>(x, emb);                              // 0
    cvtW2_k<<<2*(Nly*G4*Dsz)/256,256>>>(W_ih,pWih, W_hh,pWhh, Nly*G4*Dsz);       // 1 (+bars=0)
    tgemm_k<1><<<dim3(16,16,16),256,TG_SMEM>>>(pXH,pXL,pWih,pGih,b_ih,b_hh);     // 2
    lstm_mma<<<128,256,L_SMEM>>>(pWhh, h0, c0, pHall, pHallH, pHallL, pGih, pCf);// 3

    // Phase 1 remainder + Phase 3
    cvtH_k<<<(Vsz*Dsz)/256,256>>>(head_w, pHead, Vsz*Dsz);
    gemm_k<0><<<dim3(4,16),256>>>(pX, in_w, pQ, in_b, nullptr);
    gemm_k<5><<<dim3(4,4,16),256>>>(in_w +   Dsz*Dsz, W_np, pWnk, nullptr, nullptr);
    gemm_k<5><<<dim3(4,4,16),256>>>(in_w + 2*Dsz*Dsz, W_np, pWnv, nullptr, nullptr);
    cvtH_k<<<(Nly*Dsz*Rsz)/256,256>>>(pWnk, pWnkH, Nly*Dsz*Rsz);
    cvtH_k<<<(Nly*Dsz*Rsz)/256,256>>>(pWnv, pWnvH, Nly*Dsz*Rsz);
    ckcv_k<<<(Nly*Dsz)/256, 256>>>(in_w, in_b, b_np);
    tgemm_k<3><<<dim3(4,16,16),256,TG_SMEM>>>(pHallH,pHallL,pWnkH,pK,pCk,nullptr);
    tgemm_k<3><<<dim3(4,16,16),256,TG_SMEM>>>(pHallH,pHallL,pWnvH,pV,pCv,nullptr);
    attn_k<<<Mtok,256>>>();
    gemm_k<4><<<dim3(4,16),256>>>(pAtt, op_w, pMix, op_b, pX);
    ln_k<<<Mtok,256>>>(ln_g, ln_b);
    splitH_k<<<(Mtok*Dsz)/256,256>>>(pMix, pMixH, pMixL, Mtok*Dsz);
    tgemm_k<2><<<dim3(250,16),256,TG_SMEM>>>(pMixH,pMixL,pHead,out,head_b,nullptr);

    // hf / cf
    copyhc_k<<<NBR/256,256>>>(pHall, pCf, out);
}

// round 14
// speedup vs baseline: 3.4874x; 1.2673x over previous
#include <cuda_runtime.h>
#include <cuda_bf16.h>
#include <cuda_fp16.h>
#include <math.h>
#include <stdint.h>

// Problem dims
#define Bsz 8
#define Ssz 256
#define Vsz 32000
#define Dsz 512
#define Nly 16
#define Rsz 512
#define G4  2048            // 4*R
#define Mtok (Bsz*Ssz)      // 2048 tokens
#define NBR (Nly*Bsz*Rsz)   // 65536

// ---------------- scratch (static device globals; no runtime alloc) ----------
__device__ float g_X   [Mtok*Dsz];
__device__ float g_Gih [(size_t)Ssz*Nly*Bsz*G4];         // [t][n][b][g]
__device__ float g_hall[NBR];                            // final-step h only (hf)
__device__ float g_cf  [NBR];
__device__ float g_q   [Mtok*Dsz];
__device__ float g_Wnk [Nly*Dsz*Rsz];
__device__ float g_Wnv [Nly*Dsz*Rsz];
__device__ float g_ck  [Nly*Dsz];
__device__ float g_cv  [Nly*Dsz];
__device__ float g_k   [(size_t)Mtok*Nly*Dsz];
__device__ float g_v   [(size_t)Mtok*Nly*Dsz];
__device__ float g_att [Mtok*Dsz];
__device__ float g_mix [Mtok*Dsz];
__device__ unsigned g_bars[Nly];

// fp16 buffers
__device__ __align__(16) __half hWih   [(size_t)Nly*G4*Dsz];   // single
__device__ __align__(16) __half hWhh   [(size_t)Nly*G4*Dsz];   // single
__device__ __align__(16) __half hHead  [(size_t)Vsz*Dsz];      // single
__device__ __align__(16) __half hX_h   [Mtok*Dsz];
__device__ __align__(16) __half hX_l   [Mtok*Dsz];
__device__ __align__(16) __half hHall_h[(size_t)Ssz*NBR];
__device__ __align__(16) __half hHall_l[(size_t)Ssz*NBR];
__device__ __align__(16) __half hWnk   [Nly*Dsz*Rsz];          // single
__device__ __align__(16) __half hWnv   [Nly*Dsz*Rsz];          // single
__device__ __align__(16) __half hMix_h [Mtok*Dsz];
__device__ __align__(16) __half hMix_l [Mtok*Dsz];

__device__ __forceinline__ float sigm(float x){ return 1.f/(1.f+__expf(-x)); }

// ======================= PTX helpers (compute_103-safe) ======================
__device__ __forceinline__ void cp16(uint32_t sdst, const void* gsrc){
    asm volatile("cp.async.cg.shared.global [%0], [%1], 16;" :: "r"(sdst), "l"(gsrc));
}
__device__ __forceinline__ void cp_commit(){
    asm volatile("cp.async.commit_group;" ::: "memory");
}
template<int N>
__device__ __forceinline__ void cp_wait(){
    asm volatile("cp.async.wait_group %0;" :: "n"(N) : "memory");
}
__device__ __forceinline__ void ldsm_x4(uint32_t* r, uint32_t addr){
    asm volatile("ldmatrix.sync.aligned.m8n8.x4.shared.b16 {%0,%1,%2,%3}, [%4];"
        : "=r"(r[0]),"=r"(r[1]),"=r"(r[2]),"=r"(r[3]) : "r"(addr));
}
__device__ __forceinline__ void mma16816h(float* d, const uint32_t* a, const uint32_t* b){
    asm volatile("mma.sync.aligned.m16n8k16.row.col.f32.f16.f16.f32 "
        "{%0,%1,%2,%3}, {%4,%5,%6,%7}, {%8,%9}, {%0,%1,%2,%3};"
        : "+f"(d[0]),"+f"(d[1]),"+f"(d[2]),"+f"(d[3])
        : "r"(a[0]),"r"(a[1]),"r"(a[2]),"r"(a[3]), "r"(b[0]),"r"(b[1]));
}

// ======================= mma.sync fp16 2-product GEMM ========================
#define TG_LD   72
#define TG_BLK  (128*TG_LD)
#define TG_SMEM (2*3*TG_BLK*2)     // 2 stages x {Ah,Al,B}

template<int MODE>
__global__ void __launch_bounds__(256,1) tgemm_k(
    const __half* __restrict__ Ah, const __half* __restrict__ Al,
    const __half* __restrict__ B,
    float* __restrict__ C, const float* __restrict__ bias,
    const float* __restrict__ bias2)
{
    extern __shared__ __align__(16) __half smb[];
    uint32_t sbase = (uint32_t)__cvta_generic_to_shared(smb);
    int tid = threadIdx.x, wid = tid>>5, lane = tid&31;
    int wm = wid>>2, wn = wid&3;
    int bn = blockIdx.x, bm = blockIdx.y, nz = blockIdx.z;

    const __half *BP = B;
    if (MODE==1) BP += (size_t)nz*G4 *512;
    if (MODE==3) BP += (size_t)nz*Dsz*512;

    int lrow = tid>>1, lk = (tid&1)*32;
    int am = bm*128 + lrow;
    int ag = (MODE==3) ? ((am>>3)*128 + nz*8 + (am&7)) : am;
    const __half* gAh = Ah + (size_t)ag*512 + lk;
    const __half* gAl = Al + (size_t)ag*512 + lk;
    const __half* gB  = BP + (size_t)(bn*128 + lrow)*512 + lk;
    uint32_t sRowOff = (uint32_t)(lrow*TG_LD + lk)*2;

    int aRowL = wm*64 + (lane&15);
    int aColL = (lane>>4)*8;
    int bRowL = wn*32 + ((lane>>4)&1)*8 + (lane&7);
    int bColL = ((lane>>3)&1)*8;

    float acc[4][4][4];
    #pragma unroll
    for (int i=0;i<4;i++){
        #pragma unroll
        for (int j=0;j<4;j++){
            acc[i][j][0]=0.f; acc[i][j][1]=0.f; acc[i][j][2]=0.f; acc[i][j][3]=0.f;
        }
    }

    auto issue = [&](int s, int kb){
        uint32_t d0 = sbase + (uint32_t)((s*3+0)*TG_BLK)*2 + sRowOff;
        uint32_t d1 = sbase + (uint32_t)((s*3+1)*TG_BLK)*2 + sRowOff;
        uint32_t d2 = sbase + (uint32_t)((s*3+2)*TG_BLK)*2 + sRowOff;
        #pragma unroll
        for (int i=0;i<4;i++){
            cp16(d0 + i*16, gAh + kb + i*8);
            cp16(d1 + i*16, gAl + kb + i*8);
            cp16(d2 + i*16, gB  + kb + i*8);
        }
        cp_commit();
    };

    issue(0, 0);
    for (int c=0;c<8;c++){
        int s = c&1;
        if (c<7) issue(s^1, (c+1)*64);
        if (c<7) cp_wait<1>(); else cp_wait<0>();
        __syncthreads();

        #pragma unroll
        for (int ks=0; ks<4; ks++){
            int kc = ks*16;
            uint32_t ah[4][4], al[4][4];
            #pragma unroll
            for (int mf=0; mf<4; mf++){
                uint32_t addrh = sbase + (uint32_t)((s*3+0)*TG_BLK + (aRowL+mf*16)*TG_LD + aColL + kc)*2;
                uint32_t addrl = sbase + (uint32_t)((s*3+1)*TG_BLK + (aRowL+mf*16)*TG_LD + aColL + kc)*2;
                ldsm_x4(ah[mf], addrh);
                ldsm_x4(al[mf], addrl);
            }
            uint32_t bb[2][4];
            #pragma unroll
            for (int nfh=0; nfh<2; nfh++){
                uint32_t addrb = sbase + (uint32_t)((s*3+2)*TG_BLK + (bRowL+nfh*16)*TG_LD + bColL + kc)*2;
                ldsm_x4(bb[nfh], addrb);
            }
            #pragma unroll
            for (int mf=0; mf<4; mf++){
                #pragma unroll
                for (int nf=0; nf<4; nf++){
                    const uint32_t* bp = &bb[nf>>1][(nf&1)*2];
                    mma16816h(acc[mf][nf], ah[mf], bp);
                    mma16816h(acc[mf][nf], al[mf], bp);
                }
            }
        }
        __syncthreads();
    }

    int rA = lane>>2, cA = (lane&3)*2;
    #pragma unroll
    for (int mf=0; mf<4; mf++){
        #pragma unroll
        for (int nf=0; nf<4; nf++){
            #pragma unroll
            for (int half=0; half<2; half++){
                int m  = bm*128 + wm*64 + mf*16 + rA + half*8;
                int jc = bn*128 + wn*32 + nf*8 + cA;
                float v0 = acc[mf][nf][half*2+0];
                float v1 = acc[mf][nf][half*2+1];
                if (MODE==1){
                    v0 += bias[nz*G4+jc]   + bias2[nz*G4+jc];
                    v1 += bias[nz*G4+jc+1] + bias2[nz*G4+jc+1];
                    int t=m>>3, b=m&7;
                    float2 w = {v0,v1};
                    *(float2*)&C[(size_t)(t*128+nz*8+b)*G4 + jc] = w;
                } else if (MODE==2){
                    v0 += bias[jc]; v1 += bias[jc+1];
                    int t=m>>3, b=m&7;
                    float2 w = {v0,v1};
                    *(float2*)&C[(size_t)(b*Ssz+t)*Vsz + jc] = w;
                } else {
                    v0 += bias[nz*Dsz+jc]; v1 += bias[nz*Dsz+jc+1];
                    float2 w = {v0,v1};
                    *(float2*)&C[(size_t)(m*Nly+nz)*Dsz + jc] = w;
                }
            }
        }
    }
}

// ---------------- fp32 -> fp16 hi/lo split ------------------------------------
__global__ void __launch_bounds__(256) splitH_k(const float* __restrict__ src,
                                                __half* __restrict__ hi,
                                                __half* __restrict__ lo,
                                                int n)
{
    int i = blockIdx.x*256 + threadIdx.x;
    if (i < n){
        float x = src[i];
        __half h = __float2half(x);
        hi[i] = h;
        lo[i] = __float2half(x - __half2float(h));
    }
}

// ---------------- fp32 -> fp16 single convert ---------------------------------
__global__ void __launch_bounds__(256) cvtH_k(const float* __restrict__ src,
                                              __half* __restrict__ dst, int n)
{
    int i = blockIdx.x*256 + threadIdx.x;
    if (i < n) dst[i] = __float2half(src[i]);
}

// ---------------- fused: embedding gather + fp16 split ------------------------
__global__ void __launch_bounds__(256) embed_split_k(const int* __restrict__ x,
                                                     const float* __restrict__ emb)
{
    int idx = blockIdx.x*256 + threadIdx.x;
    int m = idx>>9, d = idx&511;
    int t = m>>3, b = m&7;
    float v = emb[(size_t)x[b*Ssz+t]*Dsz + d];
    g_X[idx] = v;
    __half h = __float2half(v);
    hX_h[idx] = h;
    hX_l[idx] = __float2half(v - __half2float(h));
}

// ---------------- fused: Wih + Whh -> fp16 + zero layer barriers --------------
__global__ void __launch_bounds__(256) cvtW2_k(const float* __restrict__ s1,
                                               __half* __restrict__ d1,
                                               const float* __restrict__ s2,
                                               __half* __restrict__ d2,
                                               int n)
{
    int i = blockIdx.x*256 + threadIdx.x;
    if (i < Nly) g_bars[i] = 0u;
    if (i < n) d1[i] = __float2half(s1[i]);
    else       d2[i - n] = __float2half(s2[i - n]);
}

// ---------------- SIMT 128x128 GEMM (small modes 0,4,5) ----------------------
template<int MODE>
__global__ void __launch_bounds__(256, 2) gemm_k(
    const float* __restrict__ A, const float* __restrict__ Bw,
    float* __restrict__ C, const float* __restrict__ bias,
    const float* __restrict__ resid)
{
    const int K = 512;
    __shared__ float As[2][8][132];
    __shared__ float Bs[2][8][132];
    int tid = threadIdx.x;
    int bn = blockIdx.x, bm = blockIdx.y, n = blockIdx.z;

    const float* Bp = Bw;
    if (MODE==5) Bp += (size_t)n*Dsz*Rsz;

    int lRow = tid>>1, lK = (tid&1)<<2;
    const float* Aptr = A + (size_t)(bm*128+lRow)*K + lK;
    const float* Bptr;
    int b_k=0, b_j=0;
    if (MODE==5){
        b_k = tid>>5; b_j = (tid&31)<<2;
        Bptr = Bp + (size_t)b_k*Rsz + bn*128 + b_j;
    } else {
        Bptr = Bp + (size_t)(bn*128 + lRow)*K + lK;
    }
    int ty = tid>>4, tx = tid&15;
    float acc[8][8] = {};
    float4 aReg, bReg;

    aReg = *(const float4*)(Aptr);
    bReg = *(const float4*)(Bptr);
    As[0][lK+0][lRow]=aReg.x; As[0][lK+1][lRow]=aReg.y;
    As[0][lK+2][lRow]=aReg.z; As[0][lK+3][lRow]=aReg.w;
    if (MODE==5){ *(float4*)&Bs[0][b_k][b_j] = bReg; }
    else {
        Bs[0][lK+0][lRow]=bReg.x; Bs[0][lK+1][lRow]=bReg.y;
        Bs[0][lK+2][lRow]=bReg.z; Bs[0][lK+3][lRow]=bReg.w;
    }
    __syncthreads();

    int buf = 0;
    for (int kb=8; kb<=K; kb+=8){
        bool more = (kb < K);
        if (more){
            aReg = *(const float4*)(Aptr + kb);
            bReg = (MODE==5) ? *(const float4*)(Bptr + (size_t)kb*Rsz)
                             : *(const float4*)(Bptr + kb);
        }
        #pragma unroll
        for (int k=0;k<8;k++){
            float4 a0 = *(const float4*)&As[buf][k][ty<<2];
            float4 a1 = *(const float4*)&As[buf][k][(ty<<2)+64];
            float4 b0 = *(const float4*)&Bs[buf][k][tx<<2];
            float4 b1 = *(const float4*)&Bs[buf][k][(tx<<2)+64];
            float a[8]={a0.x,a0.y,a0.z,a0.w,a1.x,a1.y,a1.z,a1.w};
            float b[8]={b0.x,b0.y,b0.z,b0.w,b1.x,b1.y,b1.z,b1.w};
            #pragma unroll
            for(int i=0;i<8;i++)
                #pragma unroll
                for(int j=0;j<8;j++) acc[i][j] += a[i]*b[j];
        }
        if (more){
            int nb = buf^1;
            As[nb][lK+0][lRow]=aReg.x; As[nb][lK+1][lRow]=aReg.y;
            As[nb][lK+2][lRow]=aReg.z; As[nb][lK+3][lRow]=aReg.w;
            if (MODE==5){ *(float4*)&Bs[nb][b_k][b_j] = bReg; }
            else {
                Bs[nb][lK+0][lRow]=bReg.x; Bs[nb][lK+1][lRow]=bReg.y;
                Bs[nb][lK+2][lRow]=bReg.z; Bs[nb][lK+3][lRow]=bReg.w;
            }
            __syncthreads();
            buf = nb;
        }
    }

    #pragma unroll
    for(int i=0;i<8;i++){
        int m = bm*128 + (ty<<2) + (i&3) + ((i>>2)<<6);
        #pragma unroll
        for(int j=0;j<8;j++){
            int jc = bn*128 + (tx<<2) + (j&3) + ((j>>2)<<6);
            float v = acc[i][j];
            if (MODE==0){ v += bias[jc]; C[(size_t)m*Dsz+jc]=v; }
            else if (MODE==4){ v += bias[jc] + resid[(size_t)m*Dsz+jc]; C[(size_t)m*Dsz+jc]=v; }
            else { C[(size_t)n*Dsz*Rsz + (size_t)m*Rsz + jc]=v; }
        }
    }
}

// ---------------- combined k/v biases ----------------------------------------
__global__ void __launch_bounds__(256) ckcv_k(const float* __restrict__ in_w,
                                              const float* __restrict__ in_b,
                                              const float* __restrict__ b_np)
{
    int idx = blockIdx.x*256 + threadIdx.x;
    int n = idx>>9, dc = idx&511;
    const float* Wk = in_w + Dsz*Dsz;
    const float* Wv = in_w + 2*Dsz*Dsz;
    const float* bn = b_np + n*Dsz;
    float sk = in_b[Dsz+dc], sv = in_b[2*Dsz+dc];
    for (int j=0;j<Dsz;j++){
        float bj = bn[j];
        sk += Wk[(size_t)dc*Dsz+j]*bj;
        sv += Wv[(size_t)dc*Dsz+j]*bj;
    }
    g_ck[idx]=sk; g_cv[idx]=sv;
}

// ---------------- persistent LSTM: resident-W half + warp specialization -----
#define LSWR 520                            // resident row stride (halfs)
#define L_OFF_WRES 0
#define L_SZ_WRES  (128*LSWR*2)             // 133120
#define LSW  40
#define L_WSBLK2 (128*LSW)                  // streamed stage halfs = 5120
#define L_OFF_WS   L_SZ_WRES
#define L_SZ_WS    (4*L_WSBLK2*2)           // 40960
#define LSH 536
#define L_OFF_HH (L_OFF_WS + L_SZ_WS)       // 174080
#define L_OFF_HL (L_OFF_HH + 8*LSH*2)       // 182656
#define L_OFF_GA (L_OFF_HL + 8*LSH*2)       // 191232
#define L_OFF_CS (L_OFF_GA + 256*9*4)       // 200448
#define L_OFF_GT (L_OFF_CS + 64*9*4)        // 202752
#define L_SMEM   (L_OFF_GT + 8192)          // 210944

__global__ void __launch_bounds__(256,1) lstm_mma(
    const __half* __restrict__ W,
    const float* __restrict__ h0, const float* __restrict__ c0,
    float* __restrict__ hfinal,
    __half* __restrict__ hall_h, __half* __restrict__ hall_l,
    const float* __restrict__ Gih, float* __restrict__ cfinal)
{
    extern __shared__ __align__(16) char sm[];
    uint32_t sbase = (uint32_t)__cvta_generic_to_shared(sm);
    __half* hh_s = (__half*)(sm + L_OFF_HH);
    __half* hl_s = (__half*)(sm + L_OFF_HL);
    float* ga  = (float*)(sm + L_OFF_GA);   // [256][9]
    float* cs  = (float*)(sm + L_OFF_CS);   // [64][9]
    float* gts = (float*)(sm + L_OFF_GT);   // [8][4][64]

    int tid = threadIdx.x, wid = tid>>5, lane = tid&31;
    int chunk = blockIdx.x & 7, n = blockIdx.x >> 3;

    const __half* Wbase = W + (size_t)n*G4*512;

    for (int idx=tid; idx<512; idx+=256){
        int b = idx>>6, r = idx&63;
        cs[r*9+b] = c0[(size_t)(n*8+b)*Rsz + chunk*64 + r];
    }

    int aRow = lane&15, aCol = (lane>>4)*8;
    int bN = lane>>2, bK2 = 2*(lane&3);

    volatile unsigned* barp = &g_bars[n];

    // streamed-warp thread j (0..127) handles global row 128+j
    int j = tid - 128;
    const __half* gWs = nullptr;
    if (tid >= 128){
        int m = 128 + j;
        gWs = Wbase + (size_t)((m>>6)*512 + chunk*64 + (m&63))*512;
    }
    auto issueS = [&](int kc, int s){
        uint32_t dw = sbase + L_OFF_WS + (uint32_t)(s*L_WSBLK2 + j*LSW)*2;
        const __half* sw = gWs + kc*32;
        #pragma unroll
        for (int i=0;i<4;i++) cp16(dw + i*16, sw + i*8);
        cp_commit();
    };
    auto issueGt = [&](int t){
        const float* GtBase = Gih + (size_t)t*Nly*Bsz*G4 + (size_t)(n*8)*G4 + chunk*64;
        #pragma unroll
        for (int jj=0; jj<4; jj++){
            int idx = tid + jj*128;            // 0..511
            int b = idx>>6, gate = (idx>>4)&3, quad = idx&15;
            cp16(sbase + L_OFF_GT + (uint32_t)idx*16,
                 GtBase + (size_t)b*G4 + gate*512 + quad*4);
        }
        cp_commit();
    };

    // ---- one-time: resident W rows 0..127 into smem ----
    {
        int row = tid>>1, half = tid&1;
        const __half* gsrc = Wbase + (size_t)((row>>6)*512 + chunk*64 + (row&63))*512 + half*256;
        uint32_t dst = sbase + L_OFF_WRES + (uint32_t)(row*LSWR + half*256)*2;
        #pragma unroll
        for (int i=0;i<32;i++) cp16(dst + i*16, gsrc + i*8);
        cp_commit();
    }
    if (tid < 128){ issueGt(0); cp_wait<1>(); }
    else { issueS(0,0); issueS(1,1); issueS(2,2); cp_wait<3>(); }
    __syncthreads();   // resident W + everything ordered

    for (int t=0; t<Ssz; t++){
        // ---- load h (prev) into smem fp16 hi/lo ----
        if (t==0){
            for (int idx=tid; idx<4096; idx+=256){
                int b = idx>>9, r = idx&511;
                float v = h0[(size_t)(n*8+b)*Rsz + r];
                __half hh = __float2half(v);
                hh_s[b*LSH + r] = hh;
                hl_s[b*LSH + r] = __float2half(v - __half2float(hh));
            }
        } else {
            const __half* ph = hall_h + (size_t)(t-1)*NBR + (size_t)(n*8)*Rsz;
            const __half* pl = hall_l + (size_t)(t-1)*NBR + (size_t)(n*8)*Rsz;
            for (int idx=tid; idx<512; idx+=256){
                int b = idx>>6, r8 = (idx&63)*8;
                *(uint4*)(hh_s + b*LSH + r8) = *(const uint4*)(ph + b*Rsz + r8);
                *(uint4*)(hl_s + b*LSH + r8) = *(const uint4*)(pl + b*Rsz + r8);
            }
        }
        __syncthreads();   // h visible to all

        float acc[2][4];
        #pragma unroll
        for (int f=0;f<2;f++){ acc[f][0]=0.f; acc[f][1]=0.f; acc[f][2]=0.f; acc[f][3]=0.f; }

        if (tid < 128){
            // ===== resident warps 0-3: rows wid*32..wid*32+31, no syncs =====
            for (int kc=0; kc<16; kc++){
                #pragma unroll
                for (int kf=0; kf<2; kf++){
                    int kbase = kc*32 + kf*16;
                    uint32_t bhr[2], blr[2];
                    uint32_t hoff = (uint32_t)(bN*LSH + kbase + bK2)*2;
                    bhr[0] = *(const uint32_t*)(sm + L_OFF_HH + hoff);
                    bhr[1] = *(const uint32_t*)(sm + L_OFF_HH + hoff + 16);
                    blr[0] = *(const uint32_t*)(sm + L_OFF_HL + hoff);
                    blr[1] = *(const uint32_t*)(sm + L_OFF_HL + hoff + 16);
                    #pragma unroll
                    for (int f=0; f<2; f++){
                        uint32_t aw[4];
                        uint32_t wadr = sbase + L_OFF_WRES +
                            (uint32_t)((wid*32 + f*16 + aRow)*LSWR + kbase + aCol)*2;
                        ldsm_x4(aw, wadr);
                        mma16816h(acc[f], aw, bhr);
                        mma16816h(acc[f], aw, blr);
                    }
                }
            }
            cp_wait<0>();   // Gt(t) group done (for elementwise)
        } else {
            // ===== streamed warps 4-7: rows 128..255, private pipeline =====
            int wl = wid - 4;   // 0..3
            for (int kc=0; kc<16; kc++){
                int s = kc&3;
                if      (kc<=13) cp_wait<2>();
                else if (kc==14) cp_wait<1>();
                else             cp_wait<0>();
                asm volatile("bar.sync 1, 128;" ::: "memory");
                if (kc+3 < 16) issueS(kc+3, (kc+3)&3);
                #pragma unroll
                for (int kf=0; kf<2; kf++){
                    int kbase = kc*32 + kf*16;
                    uint32_t bhr[2], blr[2];
                    uint32_t hoff = (uint32_t)(bN*LSH + kbase + bK2)*2;
                    bhr[0] = *(const uint32_t*)(sm + L_OFF_HH + hoff);
                    bhr[1] = *(const uint32_t*)(sm + L_OFF_HH + hoff + 16);
                    blr[0] = *(const uint32_t*)(sm + L_OFF_HL + hoff);
                    blr[1] = *(const uint32_t*)(sm + L_OFF_HL + hoff + 16);
                    #pragma unroll
                    for (int f=0; f<2; f++){
                        uint32_t aw[4];
                        uint32_t wadr = sbase + L_OFF_WS +
                            (uint32_t)(s*L_WSBLK2 + (wl*32 + f*16 + aRow)*LSW + kf*16 + aCol)*2;
                        ldsm_x4(aw, wadr);
                        mma16816h(acc[f], aw, bhr);
                        mma16816h(acc[f], aw, blr);
                    }
                }
            }
        }

        // ---- gates to smem (warp-exclusive rows; m = wid*32 + ...) ----
        int rA = lane>>2, cB = 2*(lane&3);
        #pragma unroll
        for (int f=0; f<2; f++){
            int m = wid*32 + f*16 + rA;
            ga[m*9 + cB]       = acc[f][0];
            ga[m*9 + cB + 1]   = acc[f][1];
            ga[(m+8)*9 + cB]   = acc[f][2];
            ga[(m+8)*9 + cB+1] = acc[f][3];
        }
        __syncthreads();

        // ---- elementwise LSTM + h split writeback ----
        for (int idx=tid; idx<512; idx+=256){
            int b = idx>>6, r = idx&63;
            float iv = ga[(      r)*9 + b] + gts[b*256       + r];
            float fv = ga[( 64 + r)*9 + b] + gts[b*256 +  64 + r];
            float gv = ga[(128 + r)*9 + b] + gts[b*256 + 128 + r];
            float ov = ga[(192 + r)*9 + b] + gts[b*256 + 192 + r];
            float cp = cs[r*9+b];
            float cn = sigm(fv)*cp + sigm(iv)*tanhf(gv);
            cs[r*9+b] = cn;
            float hv = sigm(ov)*tanhf(cn);
            size_t ho = (size_t)t*NBR + (size_t)(n*8+b)*Rsz + chunk*64 + r;
            __half hh = __float2half(hv);
            hall_h[ho] = hh;
            hall_l[ho] = __float2half(hv - __half2float(hh));
            if (t == Ssz-1)
                hfinal[(size_t)(n*8+b)*Rsz + chunk*64 + r] = hv;
        }
        __syncthreads();

        if (t+1 < Ssz){
            if (tid < 128) issueGt(t+1);
            else { issueS(0,0); issueS(1,1); issueS(2,2); }
            __threadfence();
            if (tid==0){
                atomicAdd(&g_bars[n], 1u);
                unsigned target = 8u*(unsigned)(t+1);
                while (*barp < target) { }
                __threadfence();
            }
            __syncthreads();
        }
    }

    for (int idx=tid; idx<512; idx+=256){
        int b = idx>>6, r = idx&63;
        cfinal[(size_t)(n*8+b)*Rsz + chunk*64 + r] = cs[r*9+b];
    }
}

// ---------------- attention per token ----------------------------------------
__global__ void __launch_bounds__(256) attn_k()
{
    int m = blockIdx.x, tid = threadIdx.x;
    __shared__ float sq[512];
    __shared__ float sc[8][16];
    __shared__ float sw[8][16];
    sq[tid]     = g_q[(size_t)m*Dsz + tid];
    sq[tid+256] = g_q[(size_t)m*Dsz + tid + 256];
    __syncthreads();
    if (tid < 128){
        int h = tid>>4, nn = tid&15;
        const float* kp = g_k + (size_t)(m*Nly+nn)*Dsz + h*64;
        float s = 0.f;
        #pragma unroll 8
        for (int e=0;e<64;e++) s += sq[h*64+e]*kp[e];
        sc[h][nn] = s*0.125f;
    }
    __syncthreads();
    if (tid < 8){
        float mx = -1e30f;
        for (int nn=0;nn<16;nn++) mx = fmaxf(mx, sc[tid][nn]);
        float e[16], sum = 0.f;
        for (int nn=0;nn<16;nn++){ e[nn]=expf(sc[tid][nn]-mx); sum+=e[nn]; }
        float inv = 1.f/sum;
        for (int nn=0;nn<16;nn++) sw[tid][nn]=e[nn]*inv;
    }
    __syncthreads();
    for (int idx=tid; idx<512; idx+=256){
        int h = idx>>6;
        float s = 0.f;
        #pragma unroll
        for (int nn=0;nn<16;nn++)
            s += sw[h][nn]*g_v[(size_t)(m*Nly+nn)*Dsz + idx];
        g_att[(size_t)m*Dsz + idx] = s;
    }
}

// ---------------- layernorm (in-place on g_mix) ------------------------------
__global__ void __launch_bounds__(256) ln_k(const float* __restrict__ gam,
                                            const float* __restrict__ bet)
{
    int m = blockIdx.x, tid = threadIdx.x;
    __shared__ float sh[8];
    __shared__ float sh2[8];
    float* row = g_mix + (size_t)m*Dsz;
    float v0 = row[tid], v1 = row[tid+256];
    int lane = tid&31, w = tid>>5;

    float s = v0+v1;
    #pragma unroll
    for (int o=16;o>0;o>>=1) s += __shfl_xor_sync(0xffffffffu, s, o);
    if (lane==0) sh[w]=s;
    __syncthreads();
    float tot = sh[0]+sh[1]+sh[2]+sh[3]+sh[4]+sh[5]+sh[6]+sh[7];
    float mu = tot*(1.f/512.f);

    float d0=v0-mu, d1=v1-mu;
    float s2 = d0*d0+d1*d1;
    #pragma unroll
    for (int o=16;o>0;o>>=1) s2 += __shfl_xor_sync(0xffffffffu, s2, o);
    if (lane==0) sh2[w]=s2;
    __syncthreads();
    float tot2 = sh2[0]+sh2[1]+sh2[2]+sh2[3]+sh2[4]+sh2[5]+sh2[6]+sh2[7];
    float inv = rsqrtf(tot2*(1.f/512.f) + 1e-5f);

    row[tid]     = d0*inv*gam[tid]     + bet[tid];
    row[tid+256] = d1*inv*gam[tid+256] + bet[tid+256];
}

// ---------------- final state copy ------------------------------------------
__global__ void __launch_bounds__(256) copyhc_k(const float* __restrict__ hf,
                                                const float* __restrict__ cf,
                                                float* __restrict__ out)
{
    int idx = blockIdx.x*256 + threadIdx.x;
    const size_t L = (size_t)Bsz*Ssz*Vsz;
    out[L + idx]       = hf[idx];
    out[L + NBR + idx] = cf[idx];
}

// =============================================================================
extern "C" void kernel_launch(void* const* d_in, const int* in_sizes, int n_in,
                              void* d_out, int out_size)
{
    const int*   x      = (const int*)  d_in[0];
    const float* h0     = (const float*)d_in[1];
    const float* c0     = (const float*)d_in[2];
    const float* emb    = (const float*)d_in[3];
    const float* W_ih   = (const float*)d_in[4];
    const float* b_ih   = (const float*)d_in[5];
    const float* W_hh   = (const float*)d_in[6];
    const float* b_hh   = (const float*)d_in[7];
    const float* W_np   = (const float*)d_in[8];
    const float* b_np   = (const float*)d_in[9];
    const float* in_w   = (const float*)d_in[10];
    const float* in_b   = (const float*)d_in[11];
    const float* op_w   = (const float*)d_in[12];
    const float* op_b   = (const float*)d_in[13];
    const float* ln_g   = (const float*)d_in[14];
    const float* ln_b   = (const float*)d_in[15];
    const float* head_w = (const float*)d_in[16];
    const float* head_b = (const float*)d_in[17];
    float* out = (float*)d_out;

    cudaFuncSetAttribute(tgemm_k<1>, cudaFuncAttributeMaxDynamicSharedMemorySize, TG_SMEM);
    cudaFuncSetAttribute(tgemm_k<2>, cudaFuncAttributeMaxDynamicSharedMemorySize, TG_SMEM);
    cudaFuncSetAttribute(tgemm_k<3>, cudaFuncAttributeMaxDynamicSharedMemorySize, TG_SMEM);
    cudaFuncSetAttribute(lstm_mma,   cudaFuncAttributeMaxDynamicSharedMemorySize, L_SMEM);

    float *pX,*pGih,*pHall,*pCf,*pQ,*pWnk,*pWnv,*pCk,*pCv,*pK,*pV,*pAtt,*pMix;
    __half *pWih,*pWhh,*pHead,*pXH,*pXL,*pHallH,*pHallL,*pWnkH,*pWnvH,*pMixH,*pMixL;
    cudaGetSymbolAddress((void**)&pX,    g_X);
    cudaGetSymbolAddress((void**)&pGih,  g_Gih);
    cudaGetSymbolAddress((void**)&pHall, g_hall);
    cudaGetSymbolAddress((void**)&pCf,   g_cf);
    cudaGetSymbolAddress((void**)&pQ,    g_q);
    cudaGetSymbolAddress((void**)&pWnk,  g_Wnk);
    cudaGetSymbolAddress((void**)&pWnv,  g_Wnv);
    cudaGetSymbolAddress((void**)&pCk,   g_ck);
    cudaGetSymbolAddress((void**)&pCv,   g_cv);
    cudaGetSymbolAddress((void**)&pK,    g_k);
    cudaGetSymbolAddress((void**)&pV,    g_v);
    cudaGetSymbolAddress((void**)&pAtt,  g_att);
    cudaGetSymbolAddress((void**)&pMix,  g_mix);
    cudaGetSymbolAddress((void**)&pWih,  hWih);
    cudaGetSymbolAddress((void**)&pWhh,  hWhh);
    cudaGetSymbolAddress((void**)&pHead, hHead);
    cudaGetSymbolAddress((void**)&pXH,   hX_h);    cudaGetSymbolAddress((void**)&pXL, hX_l);
    cudaGetSymbolAddress((void**)&pHallH,hHall_h); cudaGetSymbolAddress((void**)&pHallL,hHall_l);
    cudaGetSymbolAddress((void**)&pWnkH, hWnk);
    cudaGetSymbolAddress((void**)&pWnvH, hWnv);
    cudaGetSymbolAddress((void**)&pMixH, hMix_h);  cudaGetSymbolAddress((void**)&pMixL, hMix_l);

    // Launch order: index 3 = tgemm_k<1> (ncu captures 4th launch)
    embed_split_k<<<(Mtok*Dsz)/256, 256>>>(x, emb);                              // 0
    cvtW2_k<<<2*(Nly*G4*Dsz)/256,256>>>(W_ih,pWih, W_hh,pWhh, Nly*G4*Dsz);       // 1 (+bars=0)
    cvtH_k<<<(Vsz*Dsz)/256,256>>>(head_w, pHead, Vsz*Dsz);                       // 2
    tgemm_k<1><<<dim3(16,16,16),256,TG_SMEM>>>(pXH,pXL,pWih,pGih,b_ih,b_hh);     // 3 <- profiled
    lstm_mma<<<128,256,L_SMEM>>>(pWhh, h0, c0, pHall, pHallH, pHallL, pGih, pCf);// 4

    // Phase 1 remainder + Phase 3
    gemm_k<0><<<dim3(4,16),256>>>(pX, in_w, pQ, in_b, nullptr);
    gemm_k<5><<<dim3(4,4,16),256>>>(in_w +   Dsz*Dsz, W_np, pWnk, nullptr, nullptr);
    gemm_k<5><<<dim3(4,4,16),256>>>(in_w + 2*Dsz*Dsz, W_np, pWnv, nullptr, nullptr);
    cvtH_k<<<(Nly*Dsz*Rsz)/256,256>>>(pWnk, pWnkH, Nly*Dsz*Rsz);
    cvtH_k<<<(Nly*Dsz*Rsz)/256,256>>>(pWnv, pWnvH, Nly*Dsz*Rsz);
    ckcv_k<<<(Nly*Dsz)/256, 256>>>(in_w, in_b, b_np);
    tgemm_k<3><<<dim3(4,16,16),256,TG_SMEM>>>(pHallH,pHallL,pWnkH,pK,pCk,nullptr);
    tgemm_k<3><<<dim3(4,16,16),256,TG_SMEM>>>(pHallH,pHallL,pWnvH,pV,pCv,nullptr);
    attn_k<<<Mtok,256>>>();
    gemm_k<4><<<dim3(4,16),256>>>(pAtt, op_w, pMix, op_b, pX);
    ln_k<<<Mtok,256>>>(ln_g, ln_b);
    splitH_k<<<(Mtok*Dsz)/256,256>>>(pMix, pMixH, pMixL, Mtok*Dsz);
    tgemm_k<2><<<dim3(250,16),256,TG_SMEM>>>(pMixH,pMixL,pHead,out,head_b,nullptr);

    // hf / cf
    copyhc_k<<<NBR/256,256>>>(pHall, pCf, out);
}

// round 15
// speedup vs baseline: 3.6654x; 1.0510x over previous
#include <cuda_runtime.h>
#include <cuda_bf16.h>
#include <cuda_fp16.h>
#include <math.h>
#include <stdint.h>

// Problem dims
#define Bsz 8
#define Ssz 256
#define Vsz 32000
#define Dsz 512
#define Nly 16
#define Rsz 512
#define G4  2048            // 4*R
#define Mtok (Bsz*Ssz)      // 2048 tokens
#define NBR (Nly*Bsz*Rsz)   // 65536

// ---------------- scratch (static device globals; no runtime alloc) ----------
__device__ float g_X   [Mtok*Dsz];
__device__ float g_Gih [(size_t)Ssz*Nly*Bsz*G4];         // [t][n][b][g]
__device__ float g_hall[NBR];                            // final-step h only (hf)
__device__ float g_cf  [NBR];
__device__ float g_q   [Mtok*Dsz];
__device__ float g_ck  [Nly*Dsz];
__device__ float g_cv  [Nly*Dsz];
__device__ float g_k   [(size_t)Mtok*Nly*Dsz];
__device__ float g_v   [(size_t)Mtok*Nly*Dsz];
__device__ float g_att [Mtok*Dsz];
__device__ float g_mix [Mtok*Dsz];
__device__ unsigned g_bars[Nly];

// fp16 buffers
__device__ __align__(16) __half hWih   [(size_t)Nly*G4*Dsz];   // single
__device__ __align__(16) __half hWhh   [(size_t)Nly*G4*Dsz];   // single
__device__ __align__(16) __half hHead  [(size_t)Vsz*Dsz];      // single
__device__ __align__(16) __half hX_h   [Mtok*Dsz];
__device__ __align__(16) __half hX_l   [Mtok*Dsz];
__device__ __align__(16) __half hHall_h[(size_t)Ssz*NBR];
__device__ __align__(16) __half hHall_l[(size_t)Ssz*NBR];
__device__ __align__(16) __half hWnk   [Nly*Dsz*Rsz];          // single
__device__ __align__(16) __half hWnv   [Nly*Dsz*Rsz];          // single
__device__ __align__(16) __half hMix_h [Mtok*Dsz];
__device__ __align__(16) __half hMix_l [Mtok*Dsz];

__device__ __forceinline__ float sigm(float x){ return 1.f/(1.f+__expf(-x)); }

// ======================= PTX helpers (compute_103-safe) ======================
__device__ __forceinline__ void cp16(uint32_t sdst, const void* gsrc){
    asm volatile("cp.async.cg.shared.global [%0], [%1], 16;" :: "r"(sdst), "l"(gsrc));
}
__device__ __forceinline__ void cp_commit(){
    asm volatile("cp.async.commit_group;" ::: "memory");
}
template<int N>
__device__ __forceinline__ void cp_wait(){
    asm volatile("cp.async.wait_group %0;" :: "n"(N) : "memory");
}
__device__ __forceinline__ void ldsm_x4(uint32_t* r, uint32_t addr){
    asm volatile("ldmatrix.sync.aligned.m8n8.x4.shared.b16 {%0,%1,%2,%3}, [%4];"
        : "=r"(r[0]),"=r"(r[1]),"=r"(r[2]),"=r"(r[3]) : "r"(addr));
}
__device__ __forceinline__ void mma16816h(float* d, const uint32_t* a, const uint32_t* b){
    asm volatile("mma.sync.aligned.m16n8k16.row.col.f32.f16.f16.f32 "
        "{%0,%1,%2,%3}, {%4,%5,%6,%7}, {%8,%9}, {%0,%1,%2,%3};"
        : "+f"(d[0]),"+f"(d[1]),"+f"(d[2]),"+f"(d[3])
        : "r"(a[0]),"r"(a[1]),"r"(a[2]),"r"(a[3]), "r"(b[0]),"r"(b[1]));
}
__device__ __forceinline__ void bar_arrive_release(unsigned* p){
    asm volatile("red.release.gpu.global.add.u32 [%0], 1;" :: "l"(p) : "memory");
}
__device__ __forceinline__ unsigned ld_acquire(const unsigned* p){
    unsigned v;
    asm volatile("ld.acquire.gpu.global.u32 %0, [%1];" : "=r"(v) : "l"(p) : "memory");
    return v;
}

// ======================= mma.sync fp16 2-product GEMM ========================
// single barrier per K-chunk: wait<0>; sync; issue(c+1); compute(c)
#define TG_LD   72
#define TG_BLK  (128*TG_LD)
#define TG_SMEM (2*3*TG_BLK*2)     // 2 stages x {Ah,Al,B}

template<int MODE>
__global__ void __launch_bounds__(256,1) tgemm_k(
    const __half* __restrict__ Ah, const __half* __restrict__ Al,
    const __half* __restrict__ B,
    float* __restrict__ C, const float* __restrict__ bias,
    const float* __restrict__ bias2)
{
    extern __shared__ __align__(16) __half smb[];
    uint32_t sbase = (uint32_t)__cvta_generic_to_shared(smb);
    int tid = threadIdx.x, wid = tid>>5, lane = tid&31;
    int wm = wid>>2, wn = wid&3;
    int bn = blockIdx.x, bm = blockIdx.y, nz = blockIdx.z;

    const __half *BP = B;
    if (MODE==1) BP += (size_t)nz*G4 *512;
    if (MODE==3) BP += (size_t)nz*Dsz*512;

    int lrow = tid>>1, lk = (tid&1)*32;
    int am = bm*128 + lrow;
    int ag = (MODE==3) ? ((am>>3)*128 + nz*8 + (am&7)) : am;
    const __half* gAh = Ah + (size_t)ag*512 + lk;
    const __half* gAl = Al + (size_t)ag*512 + lk;
    const __half* gB  = BP + (size_t)(bn*128 + lrow)*512 + lk;
    uint32_t sRowOff = (uint32_t)(lrow*TG_LD + lk)*2;

    int aRowL = wm*64 + (lane&15);
    int aColL = (lane>>4)*8;
    int bRowL = wn*32 + ((lane>>4)&1)*8 + (lane&7);
    int bColL = ((lane>>3)&1)*8;

    float acc[4][4][4];
    #pragma unroll
    for (int i=0;i<4;i++){
        #pragma unroll
        for (int j=0;j<4;j++){
            acc[i][j][0]=0.f; acc[i][j][1]=0.f; acc[i][j][2]=0.f; acc[i][j][3]=0.f;
        }
    }

    auto issue = [&](int s, int kb){
        uint32_t d0 = sbase + (uint32_t)((s*3+0)*TG_BLK)*2 + sRowOff;
        uint32_t d1 = sbase + (uint32_t)((s*3+1)*TG_BLK)*2 + sRowOff;
        uint32_t d2 = sbase + (uint32_t)((s*3+2)*TG_BLK)*2 + sRowOff;
        #pragma unroll
        for (int i=0;i<4;i++){
            cp16(d0 + i*16, gAh + kb + i*8);
            cp16(d1 + i*16, gAl + kb + i*8);
            cp16(d2 + i*16, gB  + kb + i*8);
        }
        cp_commit();
    };

    issue(0, 0);
    for (int c=0;c<8;c++){
        int s = c&1;
        cp_wait<0>();
        __syncthreads();      // chunk c visible AND prev reads of stage s^1 done
        if (c<7) issue(s^1, (c+1)*64);

        #pragma unroll
        for (int ks=0; ks<4; ks++){
            int kc = ks*16;
            uint32_t ah[4][4], al[4][4];
            #pragma unroll
            for (int mf=0; mf<4; mf++){
                uint32_t addrh = sbase + (uint32_t)((s*3+0)*TG_BLK + (aRowL+mf*16)*TG_LD + aColL + kc)*2;
                uint32_t addrl = sbase + (uint32_t)((s*3+1)*TG_BLK + (aRowL+mf*16)*TG_LD + aColL + kc)*2;
                ldsm_x4(ah[mf], addrh);
                ldsm_x4(al[mf], addrl);
            }
            uint32_t bb[2][4];
            #pragma unroll
            for (int nfh=0; nfh<2; nfh++){
                uint32_t addrb = sbase + (uint32_t)((s*3+2)*TG_BLK + (bRowL+nfh*16)*TG_LD + bColL + kc)*2;
                ldsm_x4(bb[nfh], addrb);
            }
            #pragma unroll
            for (int mf=0; mf<4; mf++){
                #pragma unroll
                for (int nf=0; nf<4; nf++){
                    const uint32_t* bp = &bb[nf>>1][(nf&1)*2];
                    mma16816h(acc[mf][nf], ah[mf], bp);
                    mma16816h(acc[mf][nf], al[mf], bp);
                }
            }
        }
    }

    int rA = lane>>2, cA = (lane&3)*2;
    #pragma unroll
    for (int mf=0; mf<4; mf++){
        #pragma unroll
        for (int nf=0; nf<4; nf++){
            #pragma unroll
            for (int half=0; half<2; half++){
                int m  = bm*128 + wm*64 + mf*16 + rA + half*8;
                int jc = bn*128 + wn*32 + nf*8 + cA;
                float v0 = acc[mf][nf][half*2+0];
                float v1 = acc[mf][nf][half*2+1];
                if (MODE==1){
                    v0 += bias[nz*G4+jc]   + bias2[nz*G4+jc];
                    v1 += bias[nz*G4+jc+1] + bias2[nz*G4+jc+1];
                    int t=m>>3, b=m&7;
                    float2 w = {v0,v1};
                    *(float2*)&C[(size_t)(t*128+nz*8+b)*G4 + jc] = w;
                } else if (MODE==2){
                    v0 += bias[jc]; v1 += bias[jc+1];
                    int t=m>>3, b=m&7;
                    float2 w = {v0,v1};
                    *(float2*)&C[(size_t)(b*Ssz+t)*Vsz + jc] = w;
                } else {
                    v0 += bias[nz*Dsz+jc]; v1 += bias[nz*Dsz+jc+1];
                    float2 w = {v0,v1};
                    *(float2*)&C[(size_t)(m*Nly+nz)*Dsz + jc] = w;
                }
            }
        }
    }
}

// ---------------- fp32 -> fp16 hi/lo split ------------------------------------
__global__ void __launch_bounds__(256) splitH_k(const float* __restrict__ src,
                                                __half* __restrict__ hi,
                                                __half* __restrict__ lo,
                                                int n)
{
    int i = blockIdx.x*256 + threadIdx.x;
    if (i < n){
        float x = src[i];
        __half h = __float2half(x);
        hi[i] = h;
        lo[i] = __float2half(x - __half2float(h));
    }
}

// ---------------- fp32 -> fp16 single convert ---------------------------------
__global__ void __launch_bounds__(256) cvtH_k(const float* __restrict__ src,
                                              __half* __restrict__ dst, int n)
{
    int i = blockIdx.x*256 + threadIdx.x;
    if (i < n) dst[i] = __float2half(src[i]);
}

// ---------------- fused: embedding gather + fp16 split ------------------------
__global__ void __launch_bounds__(256) embed_split_k(const int* __restrict__ x,
                                                     const float* __restrict__ emb)
{
    int idx = blockIdx.x*256 + threadIdx.x;
    int m = idx>>9, d = idx&511;
    int t = m>>3, b = m&7;
    float v = emb[(size_t)x[b*Ssz+t]*Dsz + d];
    g_X[idx] = v;
    __half h = __float2half(v);
    hX_h[idx] = h;
    hX_l[idx] = __float2half(v - __half2float(h));
}

// ---------------- fused: Wih + Whh -> fp16 + zero layer barriers --------------
__global__ void __launch_bounds__(256) cvtW2_k(const float* __restrict__ s1,
                                               __half* __restrict__ d1,
                                               const float* __restrict__ s2,
                                               __half* __restrict__ d2,
                                               int n)
{
    int i = blockIdx.x*256 + threadIdx.x;
    if (i < Nly) g_bars[i] = 0u;
    if (i < n) d1[i] = __float2half(s1[i]);
    else       d2[i - n] = __float2half(s2[i - n]);
}

// ---------------- SIMT 128x128 GEMM (modes 0,4: fp32 C ; 5: fp16 C) ----------
template<int MODE>
__global__ void __launch_bounds__(256, 2) gemm_k(
    const float* __restrict__ A, const float* __restrict__ Bw,
    float* __restrict__ C, __half* __restrict__ Ch,
    const float* __restrict__ bias, const float* __restrict__ resid)
{
    const int K = 512;
    __shared__ float As[2][8][132];
    __shared__ float Bs[2][8][132];
    int tid = threadIdx.x;
    int bn = blockIdx.x, bm = blockIdx.y, n = blockIdx.z;

    const float* Bp = Bw;
    if (MODE==5) Bp += (size_t)n*Dsz*Rsz;

    int lRow = tid>>1, lK = (tid&1)<<2;
    const float* Aptr = A + (size_t)(bm*128+lRow)*K + lK;
    const float* Bptr;
    int b_k=0, b_j=0;
    if (MODE==5){
        b_k = tid>>5; b_j = (tid&31)<<2;
        Bptr = Bp + (size_t)b_k*Rsz + bn*128 + b_j;
    } else {
        Bptr = Bp + (size_t)(bn*128 + lRow)*K + lK;
    }
    int ty = tid>>4, tx = tid&15;
    float acc[8][8] = {};
    float4 aReg, bReg;

    aReg = *(const float4*)(Aptr);
    bReg = *(const float4*)(Bptr);
    As[0][lK+0][lRow]=aReg.x; As[0][lK+1][lRow]=aReg.y;
    As[0][lK+2][lRow]=aReg.z; As[0][lK+3][lRow]=aReg.w;
    if (MODE==5){ *(float4*)&Bs[0][b_k][b_j] = bReg; }
    else {
        Bs[0][lK+0][lRow]=bReg.x; Bs[0][lK+1][lRow]=bReg.y;
        Bs[0][lK+2][lRow]=bReg.z; Bs[0][lK+3][lRow]=bReg.w;
    }
    __syncthreads();

    int buf = 0;
    for (int kb=8; kb<=K; kb+=8){
        bool more = (kb < K);
        if (more){
            aReg = *(const float4*)(Aptr + kb);
            bReg = (MODE==5) ? *(const float4*)(Bptr + (size_t)kb*Rsz)
                             : *(const float4*)(Bptr + kb);
        }
        #pragma unroll
        for (int k=0;k<8;k++){
            float4 a0 = *(const float4*)&As[buf][k][ty<<2];
            float4 a1 = *(const float4*)&As[buf][k][(ty<<2)+64];
            float4 b0 = *(const float4*)&Bs[buf][k][tx<<2];
            float4 b1 = *(const float4*)&Bs[buf][k][(tx<<2)+64];
            float a[8]={a0.x,a0.y,a0.z,a0.w,a1.x,a1.y,a1.z,a1.w};
            float b[8]={b0.x,b0.y,b0.z,b0.w,b1.x,b1.y,b1.z,b1.w};
            #pragma unroll
            for(int i=0;i<8;i++)
                #pragma unroll
                for(int j=0;j<8;j++) acc[i][j] += a[i]*b[j];
        }
        if (more){
            int nb = buf^1;
            As[nb][lK+0][lRow]=aReg.x; As[nb][lK+1][lRow]=aReg.y;
            As[nb][lK+2][lRow]=aReg.z; As[nb][lK+3][lRow]=aReg.w;
            if (MODE==5){ *(float4*)&Bs[nb][b_k][b_j] = bReg; }
            else {
                Bs[nb][lK+0][lRow]=bReg.x; Bs[nb][lK+1][lRow]=bReg.y;
                Bs[nb][lK+2][lRow]=bReg.z; Bs[nb][lK+3][lRow]=bReg.w;
            }
            __syncthreads();
            buf = nb;
        }
    }

    #pragma unroll
    for(int i=0;i<8;i++){
        int m = bm*128 + (ty<<2) + (i&3) + ((i>>2)<<6);
        #pragma unroll
        for(int j=0;j<8;j++){
            int jc = bn*128 + (tx<<2) + (j&3) + ((j>>2)<<6);
            float v = acc[i][j];
            if (MODE==0){ v += bias[jc]; C[(size_t)m*Dsz+jc]=v; }
            else if (MODE==4){ v += bias[jc] + resid[(size_t)m*Dsz+jc]; C[(size_t)m*Dsz+jc]=v; }
            else { Ch[(size_t)n*Dsz*Rsz + (size_t)m*Rsz + jc] = __float2half(v); }
        }
    }
}

// ---------------- combined k/v biases ----------------------------------------
__global__ void __launch_bounds__(256) ckcv_k(const float* __restrict__ in_w,
                                              const float* __restrict__ in_b,
                                              const float* __restrict__ b_np)
{
    int idx = blockIdx.x*256 + threadIdx.x;
    int n = idx>>9, dc = idx&511;
    const float* Wk = in_w + Dsz*Dsz;
    const float* Wv = in_w + 2*Dsz*Dsz;
    const float* bn = b_np + n*Dsz;
    float sk = in_b[Dsz+dc], sv = in_b[2*Dsz+dc];
    for (int j=0;j<Dsz;j++){
        float bj = bn[j];
        sk += Wk[(size_t)dc*Dsz+j]*bj;
        sv += Wv[(size_t)dc*Dsz+j]*bj;
    }
    g_ck[idx]=sk; g_cv[idx]=sv;
}

// ---------------- persistent LSTM: resident-W half + warp specialization -----
#define LSWR 520
#define L_OFF_WRES 0
#define L_SZ_WRES  (128*LSWR*2)
#define LSW  40
#define L_WSBLK2 (128*LSW)
#define L_OFF_WS   L_SZ_WRES
#define L_SZ_WS    (4*L_WSBLK2*2)
#define LSH 536
#define L_OFF_HH (L_OFF_WS + L_SZ_WS)
#define L_OFF_HL (L_OFF_HH + 8*LSH*2)
#define L_OFF_GA (L_OFF_HL + 8*LSH*2)
#define L_OFF_CS (L_OFF_GA + 256*9*4)
#define L_OFF_GT (L_OFF_CS + 64*9*4)
#define L_SMEM   (L_OFF_GT + 8192)

__global__ void __launch_bounds__(256,1) lstm_mma(
    const __half* __restrict__ W,
    const float* __restrict__ h0, const float* __restrict__ c0,
    float* __restrict__ hfinal,
    __half* __restrict__ hall_h, __half* __restrict__ hall_l,
    const float* __restrict__ Gih, float* __restrict__ cfinal)
{
    extern __shared__ __align__(16) char sm[];
    uint32_t sbase = (uint32_t)__cvta_generic_to_shared(sm);
    __half* hh_s = (__half*)(sm + L_OFF_HH);
    __half* hl_s = (__half*)(sm + L_OFF_HL);
    float* ga  = (float*)(sm + L_OFF_GA);
    float* cs  = (float*)(sm + L_OFF_CS);
    float* gts = (float*)(sm + L_OFF_GT);

    int tid = threadIdx.x, wid = tid>>5, lane = tid&31;
    int chunk = blockIdx.x & 7, n = blockIdx.x >> 3;

    const __half* Wbase = W + (size_t)n*G4*512;

    for (int idx=tid; idx<512; idx+=256){
        int b = idx>>6, r = idx&63;
        cs[r*9+b] = c0[(size_t)(n*8+b)*Rsz + chunk*64 + r];
    }

    int aRow = lane&15, aCol = (lane>>4)*8;
    int bN = lane>>2, bK2 = 2*(lane&3);

    int j = tid - 128;
    const __half* gWs = nullptr;
    if (tid >= 128){
        int m = 128 + j;
        gWs = Wbase + (size_t)((m>>6)*512 + chunk*64 + (m&63))*512;
    }
    auto issueS = [&](int kc, int s){
        uint32_t dw = sbase + L_OFF_WS + (uint32_t)(s*L_WSBLK2 + j*LSW)*2;
        const __half* sw = gWs + kc*32;
        #pragma unroll
        for (int i=0;i<4;i++) cp16(dw + i*16, sw + i*8);
        cp_commit();
    };
    auto issueGt = [&](int t){
        const float* GtBase = Gih + (size_t)t*Nly*Bsz*G4 + (size_t)(n*8)*G4 + chunk*64;
        #pragma unroll
        for (int jj=0; jj<4; jj++){
            int idx = tid + jj*128;
            int b = idx>>6, gate = (idx>>4)&3, quad = idx&15;
            cp16(sbase + L_OFF_GT + (uint32_t)idx*16,
                 GtBase + (size_t)b*G4 + gate*512 + quad*4);
        }
        cp_commit();
    };

    // ---- one-time: resident W rows 0..127 into smem ----
    {
        int row = tid>>1, half = tid&1;
        const __half* gsrc = Wbase + (size_t)((row>>6)*512 + chunk*64 + (row&63))*512 + half*256;
        uint32_t dst = sbase + L_OFF_WRES + (uint32_t)(row*LSWR + half*256)*2;
        #pragma unroll
        for (int i=0;i<32;i++) cp16(dst + i*16, gsrc + i*8);
        cp_commit();
    }
    if (tid < 128){ issueGt(0); cp_wait<1>(); }
    else { issueS(0,0); issueS(1,1); issueS(2,2); cp_wait<3>(); }
    __syncthreads();

    for (int t=0; t<Ssz; t++){
        // ---- load h (prev) into smem fp16 hi/lo ----
        if (t==0){
            for (int idx=tid; idx<4096; idx+=256){
                int b = idx>>9, r = idx&511;
                float v = h0[(size_t)(n*8+b)*Rsz + r];
                __half hh = __float2half(v);
                hh_s[b*LSH + r] = hh;
                hl_s[b*LSH + r] = __float2half(v - __half2float(hh));
            }
        } else {
            const __half* ph = hall_h + (size_t)(t-1)*NBR + (size_t)(n*8)*Rsz;
            const __half* pl = hall_l + (size_t)(t-1)*NBR + (size_t)(n*8)*Rsz;
            for (int idx=tid; idx<512; idx+=256){
                int b = idx>>6, r8 = (idx&63)*8;
                *(uint4*)(hh_s + b*LSH + r8) = *(const uint4*)(ph + b*Rsz + r8);
                *(uint4*)(hl_s + b*LSH + r8) = *(const uint4*)(pl + b*Rsz + r8);
            }
        }
        __syncthreads();

        float acc[2][4];
        #pragma unroll
        for (int f=0;f<2;f++){ acc[f][0]=0.f; acc[f][1]=0.f; acc[f][2]=0.f; acc[f][3]=0.f; }

        if (tid < 128){
            // resident warps 0-3: no syncs
            for (int kc=0; kc<16; kc++){
                #pragma unroll
                for (int kf=0; kf<2; kf++){
                    int kbase = kc*32 + kf*16;
                    uint32_t bhr[2], blr[2];
                    uint32_t hoff = (uint32_t)(bN*LSH + kbase + bK2)*2;
                    bhr[0] = *(const uint32_t*)(sm + L_OFF_HH + hoff);
                    bhr[1] = *(const uint32_t*)(sm + L_OFF_HH + hoff + 16);
                    blr[0] = *(const uint32_t*)(sm + L_OFF_HL + hoff);
                    blr[1] = *(const uint32_t*)(sm + L_OFF_HL + hoff + 16);
                    #pragma unroll
                    for (int f=0; f<2; f++){
                        uint32_t aw[4];
                        uint32_t wadr = sbase + L_OFF_WRES +
                            (uint32_t)((wid*32 + f*16 + aRow)*LSWR + kbase + aCol)*2;
                        ldsm_x4(aw, wadr);
                        mma16816h(acc[f], aw, bhr);
                        mma16816h(acc[f], aw, blr);
                    }
                }
            }
            cp_wait<0>();   // Gt(t) done
        } else {
            // streamed warps 4-7: private pipeline
            int wl = wid - 4;
            for (int kc=0; kc<16; kc++){
                int s = kc&3;
                if      (kc<=13) cp_wait<2>();
                else if (kc==14) cp_wait<1>();
                else             cp_wait<0>();
                asm volatile("bar.sync 1, 128;" ::: "memory");
                if (kc+3 < 16) issueS(kc+3, (kc+3)&3);
                #pragma unroll
                for (int kf=0; kf<2; kf++){
                    int kbase = kc*32 + kf*16;
                    uint32_t bhr[2], blr[2];
                    uint32_t hoff = (uint32_t)(bN*LSH + kbase + bK2)*2;
                    bhr[0] = *(const uint32_t*)(sm + L_OFF_HH + hoff);
                    bhr[1] = *(const uint32_t*)(sm + L_OFF_HH + hoff + 16);
                    blr[0] = *(const uint32_t*)(sm + L_OFF_HL + hoff);
                    blr[1] = *(const uint32_t*)(sm + L_OFF_HL + hoff + 16);
                    #pragma unroll
                    for (int f=0; f<2; f++){
                        uint32_t aw[4];
                        uint32_t wadr = sbase + L_OFF_WS +
                            (uint32_t)(s*L_WSBLK2 + (wl*32 + f*16 + aRow)*LSW + kf*16 + aCol)*2;
                        ldsm_x4(aw, wadr);
                        mma16816h(acc[f], aw, bhr);
                        mma16816h(acc[f], aw, blr);
                    }
                }
            }
        }

        // ---- gates to smem ----
        int rA = lane>>2, cB = 2*(lane&3);
        #pragma unroll
        for (int f=0; f<2; f++){
            int m = wid*32 + f*16 + rA;
            ga[m*9 + cB]       = acc[f][0];
            ga[m*9 + cB + 1]   = acc[f][1];
            ga[(m+8)*9 + cB]   = acc[f][2];
            ga[(m+8)*9 + cB+1] = acc[f][3];
        }
        __syncthreads();

        // ---- elementwise LSTM + h split writeback ----
        for (int idx=tid; idx<512; idx+=256){
            int b = idx>>6, r = idx&63;
            float iv = ga[(      r)*9 + b] + gts[b*256       + r];
            float fv = ga[( 64 + r)*9 + b] + gts[b*256 +  64 + r];
            float gv = ga[(128 + r)*9 + b] + gts[b*256 + 128 + r];
            float ov = ga[(192 + r)*9 + b] + gts[b*256 + 192 + r];
            float cp = cs[r*9+b];
            float cn = sigm(fv)*cp + sigm(iv)*tanhf(gv);
            cs[r*9+b] = cn;
            float hv = sigm(ov)*tanhf(cn);
            size_t ho = (size_t)t*NBR + (size_t)(n*8+b)*Rsz + chunk*64 + r;
            __half hh = __float2half(hv);
            hall_h[ho] = hh;
            hall_l[ho] = __float2half(hv - __half2float(hh));
            if (t == Ssz-1)
                hfinal[(size_t)(n*8+b)*Rsz + chunk*64 + r] = hv;
        }
        __syncthreads();      // all writes done; gts consumed

        if (t+1 < Ssz){
            if (tid < 128) issueGt(t+1);
            else { issueS(0,0); issueS(1,1); issueS(2,2); }
            // CG-style per-layer barrier: release arrive + acquire poll (no membar.gl)
            if (tid==0){
                bar_arrive_release(&g_bars[n]);
                unsigned target = 8u*(unsigned)(t+1);
                while (ld_acquire(&g_bars[n]) < target) { }
            }
            __syncthreads();
        }
    }

    for (int idx=tid; idx<512; idx+=256){
        int b = idx>>6, r = idx&63;
        cfinal[(size_t)(n*8+b)*Rsz + chunk*64 + r] = cs[r*9+b];
    }
}

// ---------------- attention per token ----------------------------------------
__global__ void __launch_bounds__(256) attn_k()
{
    int m = blockIdx.x, tid = threadIdx.x;
    __shared__ float sq[512];
    __shared__ float sc[8][16];
    __shared__ float sw[8][16];
    sq[tid]     = g_q[(size_t)m*Dsz + tid];
    sq[tid+256] = g_q[(size_t)m*Dsz + tid + 256];
    __syncthreads();
    if (tid < 128){
        int h = tid>>4, nn = tid&15;
        const float* kp = g_k + (size_t)(m*Nly+nn)*Dsz + h*64;
        float s = 0.f;
        #pragma unroll 8
        for (int e=0;e<64;e++) s += sq[h*64+e]*kp[e];
        sc[h][nn] = s*0.125f;
    }
    __syncthreads();
    if (tid < 8){
        float mx = -1e30f;
        for (int nn=0;nn<16;nn++) mx = fmaxf(mx, sc[tid][nn]);
        float e[16], sum = 0.f;
        for (int nn=0;nn<16;nn++){ e[nn]=expf(sc[tid][nn]-mx); sum+=e[nn]; }
        float inv = 1.f/sum;
        for (int nn=0;nn<16;nn++) sw[tid][nn]=e[nn]*inv;
    }
    __syncthreads();
    for (int idx=tid; idx<512; idx+=256){
        int h = idx>>6;
        float s = 0.f;
        #pragma unroll
        for (int nn=0;nn<16;nn++)
            s += sw[h][nn]*g_v[(size_t)(m*Nly+nn)*Dsz + idx];
        g_att[(size_t)m*Dsz + idx] = s;
    }
}

// ---------------- layernorm (in-place on g_mix) ------------------------------
__global__ void __launch_bounds__(256) ln_k(const float* __restrict__ gam,
                                            const float* __restrict__ bet)
{
    int m = blockIdx.x, tid = threadIdx.x;
    __shared__ float sh[8];
    __shared__ float sh2[8];
    float* row = g_mix + (size_t)m*Dsz;
    float v0 = row[tid], v1 = row[tid+256];
    int lane = tid&31, w = tid>>5;

    float s = v0+v1;
    #pragma unroll
    for (int o=16;o>0;o>>=1) s += __shfl_xor_sync(0xffffffffu, s, o);
    if (lane==0) sh[w]=s;
    __syncthreads();
    float tot = sh[0]+sh[1]+sh[2]+sh[3]+sh[4]+sh[5]+sh[6]+sh[7];
    float mu = tot*(1.f/512.f);

    float d0=v0-mu, d1=v1-mu;
    float s2 = d0*d0+d1*d1;
    #pragma unroll
    for (int o=16;o>0;o>>=1) s2 += __shfl_xor_sync(0xffffffffu, s2, o);
    if (lane==0) sh2[w]=s2;
    __syncthreads();
    float tot2 = sh2[0]+sh2[1]+sh2[2]+sh2[3]+sh2[4]+sh2[5]+sh2[6]+sh2[7];
    float inv = rsqrtf(tot2*(1.f/512.f) + 1e-5f);

    row[tid]     = d0*inv*gam[tid]     + bet[tid];
    row[tid+256] = d1*inv*gam[tid+256] + bet[tid+256];
}

// ---------------- final state copy ------------------------------------------
__global__ void __launch_bounds__(256) copyhc_k(const float* __restrict__ hf,
                                                const float* __restrict__ cf,
                                                float* __restrict__ out)
{
    int idx = blockIdx.x*256 + threadIdx.x;
    const size_t L = (size_t)Bsz*Ssz*Vsz;
    out[L + idx]       = hf[idx];
    out[L + NBR + idx] = cf[idx];
}

// =============================================================================
extern "C" void kernel_launch(void* const* d_in, const int* in_sizes, int n_in,
                              void* d_out, int out_size)
{
    const int*   x      = (const int*)  d_in[0];
    const float* h0     = (const float*)d_in[1];
    const float* c0     = (const float*)d_in[2];
    const float* emb    = (const float*)d_in[3];
    const float* W_ih   = (const float*)d_in[4];
    const float* b_ih   = (const float*)d_in[5];
    const float* W_hh   = (const float*)d_in[6];
    const float* b_hh   = (const float*)d_in[7];
    const float* W_np   = (const float*)d_in[8];
    const float* b_np   = (const float*)d_in[9];
    const float* in_w   = (const float*)d_in[10];
    const float* in_b   = (const float*)d_in[11];
    const float* op_w   = (const float*)d_in[12];
    const float* op_b   = (const float*)d_in[13];
    const float* ln_g   = (const float*)d_in[14];
    const float* ln_b   = (const float*)d_in[15];
    const float* head_w = (const float*)d_in[16];
    const float* head_b = (const float*)d_in[17];
    float* out = (float*)d_out;

    cudaFuncSetAttribute(tgemm_k<1>, cudaFuncAttributeMaxDynamicSharedMemorySize, TG_SMEM);
    cudaFuncSetAttribute(tgemm_k<2>, cudaFuncAttributeMaxDynamicSharedMemorySize, TG_SMEM);
    cudaFuncSetAttribute(tgemm_k<3>, cudaFuncAttributeMaxDynamicSharedMemorySize, TG_SMEM);
    cudaFuncSetAttribute(lstm_mma,   cudaFuncAttributeMaxDynamicSharedMemorySize, L_SMEM);

    float *pX,*pGih,*pHall,*pCf,*pQ,*pCk,*pCv,*pK,*pV,*pAtt,*pMix;
    __half *pWih,*pWhh,*pHead,*pXH,*pXL,*pHallH,*pHallL,*pWnkH,*pWnvH,*pMixH,*pMixL;
    cudaGetSymbolAddress((void**)&pX,    g_X);
    cudaGetSymbolAddress((void**)&pGih,  g_Gih);
    cudaGetSymbolAddress((void**)&pHall, g_hall);
    cudaGetSymbolAddress((void**)&pCf,   g_cf);
    cudaGetSymbolAddress((void**)&pQ,    g_q);
    cudaGetSymbolAddress((void**)&pCk,   g_ck);
    cudaGetSymbolAddress((void**)&pCv,   g_cv);
    cudaGetSymbolAddress((void**)&pK,    g_k);
    cudaGetSymbolAddress((void**)&pV,    g_v);
    cudaGetSymbolAddress((void**)&pAtt,  g_att);
    cudaGetSymbolAddress((void**)&pMix,  g_mix);
    cudaGetSymbolAddress((void**)&pWih,  hWih);
    cudaGetSymbolAddress((void**)&pWhh,  hWhh);
    cudaGetSymbolAddress((void**)&pHead, hHead);
    cudaGetSymbolAddress((void**)&pXH,   hX_h);    cudaGetSymbolAddress((void**)&pXL, hX_l);
    cudaGetSymbolAddress((void**)&pHallH,hHall_h); cudaGetSymbolAddress((void**)&pHallL,hHall_l);
    cudaGetSymbolAddress((void**)&pWnkH, hWnk);
    cudaGetSymbolAddress((void**)&pWnvH, hWnv);
    cudaGetSymbolAddress((void**)&pMixH, hMix_h);  cudaGetSymbolAddress((void**)&pMixL, hMix_l);

    // Launch order: index 3 = tgemm_k<1> (ncu captures 4th launch)
    embed_split_k<<<(Mtok*Dsz)/256, 256>>>(x, emb);                              // 0
    cvtW2_k<<<2*(Nly*G4*Dsz)/256,256>>>(W_ih,pWih, W_hh,pWhh, Nly*G4*Dsz);       // 1 (+bars=0)
    cvtH_k<<<(Vsz*Dsz)/256,256>>>(head_w, pHead, Vsz*Dsz);                       // 2
    tgemm_k<1><<<dim3(16,16,16),256,TG_SMEM>>>(pXH,pXL,pWih,pGih,b_ih,b_hh);     // 3 <- profiled
    lstm_mma<<<128,256,L_SMEM>>>(pWhh, h0, c0, pHall, pHallH, pHallL, pGih, pCf);// 4

    // Phase 1 remainder + Phase 3
    gemm_k<0><<<dim3(4,16),256>>>(pX, in_w, pQ, nullptr, in_b, nullptr);
    gemm_k<5><<<dim3(4,4,16),256>>>(in_w +   Dsz*Dsz, W_np, nullptr, pWnkH, nullptr, nullptr);
    gemm_k<5><<<dim3(4,4,16),256>>>(in_w + 2*Dsz*Dsz, W_np, nullptr, pWnvH, nullptr, nullptr);
    ckcv_k<<<(Nly*Dsz)/256, 256>>>(in_w, in_b, b_np);
    tgemm_k<3><<<dim3(4,16,16),256,TG_SMEM>>>(pHallH,pHallL,pWnkH,pK,pCk,nullptr);
    tgemm_k<3><<<dim3(4,16,16),256,TG_SMEM>>>(pHallH,pHallL,pWnvH,pV,pCv,nullptr);
    attn_k<<<Mtok,256>>>();
    gemm_k<4><<<dim3(4,16),256>>>(pAtt, op_w, pMix, nullptr, op_b, pX);
    ln_k<<<Mtok,256>>>(ln_g, ln_b);
    splitH_k<<<(Mtok*Dsz)/256,256>>>(pMix, pMixH, pMixL, Mtok*Dsz);
    tgemm_k<2><<<dim3(250,16),256,TG_SMEM>>>(pMixH,pMixL,pHead,out,head_b,nullptr);

    // hf / cf
    copyhc_k<<<NBR/256,256>>>(pHall, pCf, out);
}

// round 16
// speedup vs baseline: 3.7993x; 1.0365x over previous
#include <cuda_runtime.h>
#include <cuda_bf16.h>
#include <cuda_fp16.h>
#include <math.h>
#include <stdint.h>

// Problem dims
#define Bsz 8
#define Ssz 256
#define Vsz 32000
#define Dsz 512
#define Nly 16
#define Rsz 512
#define G4  2048            // 4*R
#define Mtok (Bsz*Ssz)      // 2048 tokens
#define NBR (Nly*Bsz*Rsz)   // 65536

// ---------------- scratch (static device globals; no runtime alloc) ----------
__device__ float g_X   [Mtok*Dsz];
__device__ float g_Gih [(size_t)Ssz*Nly*Bsz*G4];         // [t][n][b][g]
__device__ float g_hall[NBR];                            // final-step h only (hf)
__device__ float g_cf  [NBR];
__device__ float g_q   [Mtok*Dsz];
__device__ float g_ck  [Nly*Dsz];
__device__ float g_cv  [Nly*Dsz];
__device__ float g_k   [(size_t)Mtok*Nly*Dsz];
__device__ float g_v   [(size_t)Mtok*Nly*Dsz];
__device__ float g_att [Mtok*Dsz];
__device__ float g_mix [Mtok*Dsz];
__device__ unsigned g_bars[Nly];

// fp16 buffers
__device__ __align__(16) __half hWih   [(size_t)Nly*G4*Dsz];   // single
__device__ __align__(16) __half hWhh   [(size_t)Nly*G4*Dsz];   // single
__device__ __align__(16) __half hHead  [(size_t)Vsz*Dsz];      // single
__device__ __align__(16) __half hX_h   [Mtok*Dsz];
__device__ __align__(16) __half hX_l   [Mtok*Dsz];
__device__ __align__(16) __half hHall_h[(size_t)Ssz*NBR];
__device__ __align__(16) __half hHall_l[(size_t)Ssz*NBR];
__device__ __align__(16) __half hWnk   [Nly*Dsz*Rsz];          // single
__device__ __align__(16) __half hWnv   [Nly*Dsz*Rsz];          // single
__device__ __align__(16) __half hMix_h [Mtok*Dsz];
__device__ __align__(16) __half hMix_l [Mtok*Dsz];

__device__ __forceinline__ float sigm(float x){ return 1.f/(1.f+__expf(-x)); }

// ======================= PTX helpers (compute_103-safe) ======================
__device__ __forceinline__ void cp16(uint32_t sdst, const void* gsrc){
    asm volatile("cp.async.cg.shared.global [%0], [%1], 16;" :: "r"(sdst), "l"(gsrc));
}
__device__ __forceinline__ void cp_commit(){
    asm volatile("cp.async.commit_group;" ::: "memory");
}
template<int N>
__device__ __forceinline__ void cp_wait(){
    asm volatile("cp.async.wait_group %0;" :: "n"(N) : "memory");
}
__device__ __forceinline__ void ldsm_x4(uint32_t* r, uint32_t addr){
    asm volatile("ldmatrix.sync.aligned.m8n8.x4.shared.b16 {%0,%1,%2,%3}, [%4];"
        : "=r"(r[0]),"=r"(r[1]),"=r"(r[2]),"=r"(r[3]) : "r"(addr));
}
__device__ __forceinline__ void mma16816h(float* d, const uint32_t* a, const uint32_t* b){
    asm volatile("mma.sync.aligned.m16n8k16.row.col.f32.f16.f16.f32 "
        "{%0,%1,%2,%3}, {%4,%5,%6,%7}, {%8,%9}, {%0,%1,%2,%3};"
        : "+f"(d[0]),"+f"(d[1]),"+f"(d[2]),"+f"(d[3])
        : "r"(a[0]),"r"(a[1]),"r"(a[2]),"r"(a[3]), "r"(b[0]),"r"(b[1]));
}
__device__ __forceinline__ void bar_arrive_release(unsigned* p){
    asm volatile("red.release.gpu.global.add.u32 [%0], 1;" :: "l"(p) : "memory");
}
__device__ __forceinline__ unsigned ld_acquire(const unsigned* p){
    unsigned v;
    asm volatile("ld.acquire.gpu.global.u32 %0, [%1];" : "=r"(v) : "l"(p) : "memory");
    return v;
}

// ======================= mma.sync fp16 2-product GEMM ========================
// K-chunk 32, 2 stages, 61 KB smem -> 2 CTAs/SM so sync bubbles overlap.
#define TG_LD   40                 // 32 + 8 pad (halfs): ldsm bank-clean
#define TG_BLK  (128*TG_LD)        // 5120 halfs
#define TG_SMEM (2*3*TG_BLK*2)     // 61440 B

template<int MODE>
__global__ void __launch_bounds__(256,2) tgemm_k(
    const __half* __restrict__ Ah, const __half* __restrict__ Al,
    const __half* __restrict__ B,
    float* __restrict__ C, const float* __restrict__ bias,
    const float* __restrict__ bias2)
{
    extern __shared__ __align__(16) __half smb[];
    uint32_t sbase = (uint32_t)__cvta_generic_to_shared(smb);
    int tid = threadIdx.x, wid = tid>>5, lane = tid&31;
    int wm = wid>>2, wn = wid&3;
    int bn = blockIdx.x, bm = blockIdx.y, nz = blockIdx.z;

    const __half *BP = B;
    if (MODE==1) BP += (size_t)nz*G4 *512;
    if (MODE==3) BP += (size_t)nz*Dsz*512;

    int lrow = tid>>1, lk = (tid&1)*16;
    int am = bm*128 + lrow;
    int ag = (MODE==3) ? ((am>>3)*128 + nz*8 + (am&7)) : am;
    const __half* gAh = Ah + (size_t)ag*512 + lk;
    const __half* gAl = Al + (size_t)ag*512 + lk;
    const __half* gB  = BP + (size_t)(bn*128 + lrow)*512 + lk;
    uint32_t sRowOff = (uint32_t)(lrow*TG_LD + lk)*2;

    int aRowL = wm*64 + (lane&15);
    int aColL = (lane>>4)*8;
    int bRowL = wn*32 + ((lane>>4)&1)*8 + (lane&7);
    int bColL = ((lane>>3)&1)*8;

    float acc[4][4][4];
    #pragma unroll
    for (int i=0;i<4;i++){
        #pragma unroll
        for (int j=0;j<4;j++){
            acc[i][j][0]=0.f; acc[i][j][1]=0.f; acc[i][j][2]=0.f; acc[i][j][3]=0.f;
        }
    }

    auto issue = [&](int s, int kb){
        uint32_t d0 = sbase + (uint32_t)((s*3+0)*TG_BLK)*2 + sRowOff;
        uint32_t d1 = sbase + (uint32_t)((s*3+1)*TG_BLK)*2 + sRowOff;
        uint32_t d2 = sbase + (uint32_t)((s*3+2)*TG_BLK)*2 + sRowOff;
        #pragma unroll
        for (int i=0;i<2;i++){
            cp16(d0 + i*16, gAh + kb + i*8);
            cp16(d1 + i*16, gAl + kb + i*8);
            cp16(d2 + i*16, gB  + kb + i*8);
        }
        cp_commit();
    };

    issue(0, 0);
    for (int c=0;c<16;c++){
        int s = c&1;
        cp_wait<0>();
        __syncthreads();      // chunk c visible AND prev reads of stage s^1 done
        if (c<15) issue(s^1, (c+1)*32);

        #pragma unroll
        for (int ks=0; ks<2; ks++){
            int kc = ks*16;
            uint32_t ah[4][4], al[4][4];
            #pragma unroll
            for (int mf=0; mf<4; mf++){
                uint32_t addrh = sbase + (uint32_t)((s*3+0)*TG_BLK + (aRowL+mf*16)*TG_LD + aColL + kc)*2;
                uint32_t addrl = sbase + (uint32_t)((s*3+1)*TG_BLK + (aRowL+mf*16)*TG_LD + aColL + kc)*2;
                ldsm_x4(ah[mf], addrh);
                ldsm_x4(al[mf], addrl);
            }
            uint32_t bb[2][4];
            #pragma unroll
            for (int nfh=0; nfh<2; nfh++){
                uint32_t addrb = sbase + (uint32_t)((s*3+2)*TG_BLK + (bRowL+nfh*16)*TG_LD + bColL + kc)*2;
                ldsm_x4(bb[nfh], addrb);
            }
            #pragma unroll
            for (int mf=0; mf<4; mf++){
                #pragma unroll
                for (int nf=0; nf<4; nf++){
                    const uint32_t* bp = &bb[nf>>1][(nf&1)*2];
                    mma16816h(acc[mf][nf], ah[mf], bp);
                    mma16816h(acc[mf][nf], al[mf], bp);
                }
            }
        }
    }

    int rA = lane>>2, cA = (lane&3)*2;
    #pragma unroll
    for (int mf=0; mf<4; mf++){
        #pragma unroll
        for (int nf=0; nf<4; nf++){
            #pragma unroll
            for (int half=0; half<2; half++){
                int m  = bm*128 + wm*64 + mf*16 + rA + half*8;
                int jc = bn*128 + wn*32 + nf*8 + cA;
                float v0 = acc[mf][nf][half*2+0];
                float v1 = acc[mf][nf][half*2+1];
                if (MODE==1){
                    v0 += bias[nz*G4+jc]   + bias2[nz*G4+jc];
                    v1 += bias[nz*G4+jc+1] + bias2[nz*G4+jc+1];
                    int t=m>>3, b=m&7;
                    float2 w = {v0,v1};
                    *(float2*)&C[(size_t)(t*128+nz*8+b)*G4 + jc] = w;
                } else if (MODE==2){
                    v0 += bias[jc]; v1 += bias[jc+1];
                    int t=m>>3, b=m&7;
                    float2 w = {v0,v1};
                    *(float2*)&C[(size_t)(b*Ssz+t)*Vsz + jc] = w;
                } else {
                    v0 += bias[nz*Dsz+jc]; v1 += bias[nz*Dsz+jc+1];
                    float2 w = {v0,v1};
                    *(float2*)&C[(size_t)(m*Nly+nz)*Dsz + jc] = w;
                }
            }
        }
    }
}

// ---------------- fp32 -> fp16 single convert ---------------------------------
__global__ void __launch_bounds__(256) cvtH_k(const float* __restrict__ src,
                                              __half* __restrict__ dst, int n)
{
    int i = blockIdx.x*256 + threadIdx.x;
    if (i < n) dst[i] = __float2half(src[i]);
}

// ---------------- fused: embedding gather + fp16 split ------------------------
__global__ void __launch_bounds__(256) embed_split_k(const int* __restrict__ x,
                                                     const float* __restrict__ emb)
{
    int idx = blockIdx.x*256 + threadIdx.x;
    int m = idx>>9, d = idx&511;
    int t = m>>3, b = m&7;
    float v = emb[(size_t)x[b*Ssz+t]*Dsz + d];
    g_X[idx] = v;
    __half h = __float2half(v);
    hX_h[idx] = h;
    hX_l[idx] = __float2half(v - __half2float(h));
}

// ---------------- fused: Wih + Whh -> fp16 + zero layer barriers --------------
__global__ void __launch_bounds__(256) cvtW2_k(const float* __restrict__ s1,
                                               __half* __restrict__ d1,
                                               const float* __restrict__ s2,
                                               __half* __restrict__ d2,
                                               int n)
{
    int i = blockIdx.x*256 + threadIdx.x;
    if (i < Nly) g_bars[i] = 0u;
    if (i < n) d1[i] = __float2half(s1[i]);
    else       d2[i - n] = __float2half(s2[i - n]);
}

// ---------------- SIMT 128x128 GEMM (modes 0,4: fp32 C ; 5: fp16 C) ----------
template<int MODE>
__global__ void __launch_bounds__(256, 2) gemm_k(
    const float* __restrict__ A, const float* __restrict__ Bw,
    float* __restrict__ C, __half* __restrict__ Ch,
    const float* __restrict__ bias, const float* __restrict__ resid)
{
    const int K = 512;
    __shared__ float As[2][8][132];
    __shared__ float Bs[2][8][132];
    int tid = threadIdx.x;
    int bn = blockIdx.x, bm = blockIdx.y, n = blockIdx.z;

    const float* Bp = Bw;
    if (MODE==5) Bp += (size_t)n*Dsz*Rsz;

    int lRow = tid>>1, lK = (tid&1)<<2;
    const float* Aptr = A + (size_t)(bm*128+lRow)*K + lK;
    const float* Bptr;
    int b_k=0, b_j=0;
    if (MODE==5){
        b_k = tid>>5; b_j = (tid&31)<<2;
        Bptr = Bp + (size_t)b_k*Rsz + bn*128 + b_j;
    } else {
        Bptr = Bp + (size_t)(bn*128 + lRow)*K + lK;
    }
    int ty = tid>>4, tx = tid&15;
    float acc[8][8] = {};
    float4 aReg, bReg;

    aReg = *(const float4*)(Aptr);
    bReg = *(const float4*)(Bptr);
    As[0][lK+0][lRow]=aReg.x; As[0][lK+1][lRow]=aReg.y;
    As[0][lK+2][lRow]=aReg.z; As[0][lK+3][lRow]=aReg.w;
    if (MODE==5){ *(float4*)&Bs[0][b_k][b_j] = bReg; }
    else {
        Bs[0][lK+0][lRow]=bReg.x; Bs[0][lK+1][lRow]=bReg.y;
        Bs[0][lK+2][lRow]=bReg.z; Bs[0][lK+3][lRow]=bReg.w;
    }
    __syncthreads();

    int buf = 0;
    for (int kb=8; kb<=K; kb+=8){
        bool more = (kb < K);
        if (more){
            aReg = *(const float4*)(Aptr + kb);
            bReg = (MODE==5) ? *(const float4*)(Bptr + (size_t)kb*Rsz)
                             : *(const float4*)(Bptr + kb);
        }
        #pragma unroll
        for (int k=0;k<8;k++){
            float4 a0 = *(const float4*)&As[buf][k][ty<<2];
            float4 a1 = *(const float4*)&As[buf][k][(ty<<2)+64];
            float4 b0 = *(const float4*)&Bs[buf][k][tx<<2];
            float4 b1 = *(const float4*)&Bs[buf][k][(tx<<2)+64];
            float a[8]={a0.x,a0.y,a0.z,a0.w,a1.x,a1.y,a1.z,a1.w};
            float b[8]={b0.x,b0.y,b0.z,b0.w,b1.x,b1.y,b1.z,b1.w};
            #pragma unroll
            for(int i=0;i<8;i++)
                #pragma unroll
                for(int j=0;j<8;j++) acc[i][j] += a[i]*b[j];
        }
        if (more){
            int nb = buf^1;
            As[nb][lK+0][lRow]=aReg.x; As[nb][lK+1][lRow]=aReg.y;
            As[nb][lK+2][lRow]=aReg.z; As[nb][lK+3][lRow]=aReg.w;
            if (MODE==5){ *(float4*)&Bs[nb][b_k][b_j] = bReg; }
            else {
                Bs[nb][lK+0][lRow]=bReg.x; Bs[nb][lK+1][lRow]=bReg.y;
                Bs[nb][lK+2][lRow]=bReg.z; Bs[nb][lK+3][lRow]=bReg.w;
            }
            __syncthreads();
            buf = nb;
        }
    }

    #pragma unroll
    for(int i=0;i<8;i++){
        int m = bm*128 + (ty<<2) + (i&3) + ((i>>2)<<6);
        #pragma unroll
        for(int j=0;j<8;j++){
            int jc = bn*128 + (tx<<2) + (j&3) + ((j>>2)<<6);
            float v = acc[i][j];
            if (MODE==0){ v += bias[jc]; C[(size_t)m*Dsz+jc]=v; }
            else if (MODE==4){ v += bias[jc] + resid[(size_t)m*Dsz+jc]; C[(size_t)m*Dsz+jc]=v; }
            else { Ch[(size_t)n*Dsz*Rsz + (size_t)m*Rsz + jc] = __float2half(v); }
        }
    }
}

// ---------------- combined k/v biases ----------------------------------------
__global__ void __launch_bounds__(256) ckcv_k(const float* __restrict__ in_w,
                                              const float* __restrict__ in_b,
                                              const float* __restrict__ b_np)
{
    int idx = blockIdx.x*256 + threadIdx.x;
    int n = idx>>9, dc = idx&511;
    const float* Wk = in_w + Dsz*Dsz;
    const float* Wv = in_w + 2*Dsz*Dsz;
    const float* bn = b_np + n*Dsz;
    float sk = in_b[Dsz+dc], sv = in_b[2*Dsz+dc];
    for (int j=0;j<Dsz;j++){
        float bj = bn[j];
        sk += Wk[(size_t)dc*Dsz+j]*bj;
        sv += Wv[(size_t)dc*Dsz+j]*bj;
    }
    g_ck[idx]=sk; g_cv[idx]=sv;
}

// ---------------- persistent LSTM: resident-W half + warp specialization -----
#define LSWR 520
#define L_OFF_WRES 0
#define L_SZ_WRES  (128*LSWR*2)
#define LSW  40
#define L_WSBLK2 (128*LSW)
#define L_OFF_WS   L_SZ_WRES
#define L_SZ_WS    (4*L_WSBLK2*2)
#define LSH 536
#define L_OFF_HH (L_OFF_WS + L_SZ_WS)
#define L_OFF_HL (L_OFF_HH + 8*LSH*2)
#define L_OFF_GA (L_OFF_HL + 8*LSH*2)
#define L_OFF_CS (L_OFF_GA + 256*9*4)
#define L_OFF_GT (L_OFF_CS + 64*9*4)
#define L_SMEM   (L_OFF_GT + 8192)

__global__ void __launch_bounds__(256,1) lstm_mma(
    const __half* __restrict__ W,
    const float* __restrict__ h0, const float* __restrict__ c0,
    float* __restrict__ hfinal,
    __half* __restrict__ hall_h, __half* __restrict__ hall_l,
    const float* __restrict__ Gih, float* __restrict__ cfinal)
{
    extern __shared__ __align__(16) char sm[];
    uint32_t sbase = (uint32_t)__cvta_generic_to_shared(sm);
    __half* hh_s = (__half*)(sm + L_OFF_HH);
    __half* hl_s = (__half*)(sm + L_OFF_HL);
    float* ga  = (float*)(sm + L_OFF_GA);
    float* cs  = (float*)(sm + L_OFF_CS);
    float* gts = (float*)(sm + L_OFF_GT);

    int tid = threadIdx.x, wid = tid>>5, lane = tid&31;
    int chunk = blockIdx.x & 7, n = blockIdx.x >> 3;

    const __half* Wbase = W + (size_t)n*G4*512;

    for (int idx=tid; idx<512; idx+=256){
        int b = idx>>6, r = idx&63;
        cs[r*9+b] = c0[(size_t)(n*8+b)*Rsz + chunk*64 + r];
    }

    int aRow = lane&15, aCol = (lane>>4)*8;
    int bN = lane>>2, bK2 = 2*(lane&3);

    int j = tid - 128;
    const __half* gWs = nullptr;
    if (tid >= 128){
        int m = 128 + j;
        gWs = Wbase + (size_t)((m>>6)*512 + chunk*64 + (m&63))*512;
    }
    auto issueS = [&](int kc, int s){
        uint32_t dw = sbase + L_OFF_WS + (uint32_t)(s*L_WSBLK2 + j*LSW)*2;
        const __half* sw = gWs + kc*32;
        #pragma unroll
        for (int i=0;i<4;i++) cp16(dw + i*16, sw + i*8);
        cp_commit();
    };
    auto issueGt = [&](int t){
        const float* GtBase = Gih + (size_t)t*Nly*Bsz*G4 + (size_t)(n*8)*G4 + chunk*64;
        #pragma unroll
        for (int jj=0; jj<4; jj++){
            int idx = tid + jj*128;
            int b = idx>>6, gate = (idx>>4)&3, quad = idx&15;
            cp16(sbase + L_OFF_GT + (uint32_t)idx*16,
                 GtBase + (size_t)b*G4 + gate*512 + quad*4);
        }
        cp_commit();
    };

    // ---- one-time: resident W rows 0..127 into smem ----
    {
        int row = tid>>1, half = tid&1;
        const __half* gsrc = Wbase + (size_t)((row>>6)*512 + chunk*64 + (row&63))*512 + half*256;
        uint32_t dst = sbase + L_OFF_WRES + (uint32_t)(row*LSWR + half*256)*2;
        #pragma unroll
        for (int i=0;i<32;i++) cp16(dst + i*16, gsrc + i*8);
        cp_commit();
    }
    if (tid < 128){ issueGt(0); cp_wait<1>(); }
    else { issueS(0,0); issueS(1,1); issueS(2,2); cp_wait<3>(); }
    __syncthreads();

    for (int t=0; t<Ssz; t++){
        // ---- load h (prev) into smem fp16 hi/lo ----
        if (t==0){
            for (int idx=tid; idx<4096; idx+=256){
                int b = idx>>9, r = idx&511;
                float v = h0[(size_t)(n*8+b)*Rsz + r];
                __half hh = __float2half(v);
                hh_s[b*LSH + r] = hh;
                hl_s[b*LSH + r] = __float2half(v - __half2float(hh));
            }
        } else {
            const __half* ph = hall_h + (size_t)(t-1)*NBR + (size_t)(n*8)*Rsz;
            const __half* pl = hall_l + (size_t)(t-1)*NBR + (size_t)(n*8)*Rsz;
            for (int idx=tid; idx<512; idx+=256){
                int b = idx>>6, r8 = (idx&63)*8;
                *(uint4*)(hh_s + b*LSH + r8) = *(const uint4*)(ph + b*Rsz + r8);
                *(uint4*)(hl_s + b*LSH + r8) = *(const uint4*)(pl + b*Rsz + r8);
            }
        }
        __syncthreads();

        float acc[2][4];
        #pragma unroll
        for (int f=0;f<2;f++){ acc[f][0]=0.f; acc[f][1]=0.f; acc[f][2]=0.f; acc[f][3]=0.f; }

        if (tid < 128){
            // resident warps 0-3: no syncs
            for (int kc=0; kc<16; kc++){
                #pragma unroll
                for (int kf=0; kf<2; kf++){
                    int kbase = kc*32 + kf*16;
                    uint32_t bhr[2], blr[2];
                    uint32_t hoff = (uint32_t)(bN*LSH + kbase + bK2)*2;
                    bhr[0] = *(const uint32_t*)(sm + L_OFF_HH + hoff);
                    bhr[1] = *(const uint32_t*)(sm + L_OFF_HH + hoff + 16);
                    blr[0] = *(const uint32_t*)(sm + L_OFF_HL + hoff);
                    blr[1] = *(const uint32_t*)(sm + L_OFF_HL + hoff + 16);
                    #pragma unroll
                    for (int f=0; f<2; f++){
                        uint32_t aw[4];
                        uint32_t wadr = sbase + L_OFF_WRES +
                            (uint32_t)((wid*32 + f*16 + aRow)*LSWR + kbase + aCol)*2;
                        ldsm_x4(aw, wadr);
                        mma16816h(acc[f], aw, bhr);
                        mma16816h(acc[f], aw, blr);
                    }
                }
            }
            cp_wait<0>();   // Gt(t) done
        } else {
            // streamed warps 4-7: private pipeline
            int wl = wid - 4;
            for (int kc=0; kc<16; kc++){
                int s = kc&3;
                if      (kc<=13) cp_wait<2>();
                else if (kc==14) cp_wait<1>();
                else             cp_wait<0>();
                asm volatile("bar.sync 1, 128;" ::: "memory");
                if (kc+3 < 16) issueS(kc+3, (kc+3)&3);
                #pragma unroll
                for (int kf=0; kf<2; kf++){
                    int kbase = kc*32 + kf*16;
                    uint32_t bhr[2], blr[2];
                    uint32_t hoff = (uint32_t)(bN*LSH + kbase + bK2)*2;
                    bhr[0] = *(const uint32_t*)(sm + L_OFF_HH + hoff);
                    bhr[1] = *(const uint32_t*)(sm + L_OFF_HH + hoff + 16);
                    blr[0] = *(const uint32_t*)(sm + L_OFF_HL + hoff);
                    blr[1] = *(const uint32_t*)(sm + L_OFF_HL + hoff + 16);
                    #pragma unroll
                    for (int f=0; f<2; f++){
                        uint32_t aw[4];
                        uint32_t wadr = sbase + L_OFF_WS +
                            (uint32_t)(s*L_WSBLK2 + (wl*32 + f*16 + aRow)*LSW + kf*16 + aCol)*2;
                        ldsm_x4(aw, wadr);
                        mma16816h(acc[f], aw, bhr);
                        mma16816h(acc[f], aw, blr);
                    }
                }
            }
        }

        // ---- gates to smem ----
        int rA = lane>>2, cB = 2*(lane&3);
        #pragma unroll
        for (int f=0; f<2; f++){
            int m = wid*32 + f*16 + rA;
            ga[m*9 + cB]       = acc[f][0];
            ga[m*9 + cB + 1]   = acc[f][1];
            ga[(m+8)*9 + cB]   = acc[f][2];
            ga[(m+8)*9 + cB+1] = acc[f][3];
        }
        __syncthreads();

        // ---- elementwise LSTM + h split writeback ----
        for (int idx=tid; idx<512; idx+=256){
            int b = idx>>6, r = idx&63;
            float iv = ga[(      r)*9 + b] + gts[b*256       + r];
            float fv = ga[( 64 + r)*9 + b] + gts[b*256 +  64 + r];
            float gv = ga[(128 + r)*9 + b] + gts[b*256 + 128 + r];
            float ov = ga[(192 + r)*9 + b] + gts[b*256 + 192 + r];
            float cp = cs[r*9+b];
            float cn = sigm(fv)*cp + sigm(iv)*tanhf(gv);
            cs[r*9+b] = cn;
            float hv = sigm(ov)*tanhf(cn);
            size_t ho = (size_t)t*NBR + (size_t)(n*8+b)*Rsz + chunk*64 + r;
            __half hh = __float2half(hv);
            hall_h[ho] = hh;
            hall_l[ho] = __float2half(hv - __half2float(hh));
            if (t == Ssz-1)
                hfinal[(size_t)(n*8+b)*Rsz + chunk*64 + r] = hv;
        }
        __syncthreads();

        if (t+1 < Ssz){
            if (tid < 128) issueGt(t+1);
            else { issueS(0,0); issueS(1,1); issueS(2,2); }
            if (tid==0){
                bar_arrive_release(&g_bars[n]);
                unsigned target = 8u*(unsigned)(t+1);
                while (ld_acquire(&g_bars[n]) < target) { }
            }
            __syncthreads();
        }
    }

    for (int idx=tid; idx<512; idx+=256){
        int b = idx>>6, r = idx&63;
        cfinal[(size_t)(n*8+b)*Rsz + chunk*64 + r] = cs[r*9+b];
    }
}

// ---------------- attention per token ----------------------------------------
__global__ void __launch_bounds__(256) attn_k()
{
    int m = blockIdx.x, tid = threadIdx.x;
    __shared__ float sq[512];
    __shared__ float sc[8][16];
    __shared__ float sw[8][16];
    sq[tid]     = g_q[(size_t)m*Dsz + tid];
    sq[tid+256] = g_q[(size_t)m*Dsz + tid + 256];
    __syncthreads();
    if (tid < 128){
        int h = tid>>4, nn = tid&15;
        const float* kp = g_k + (size_t)(m*Nly+nn)*Dsz + h*64;
        float s = 0.f;
        #pragma unroll 8
        for (int e=0;e<64;e++) s += sq[h*64+e]*kp[e];
        sc[h][nn] = s*0.125f;
    }
    __syncthreads();
    if (tid < 8){
        float mx = -1e30f;
        for (int nn=0;nn<16;nn++) mx = fmaxf(mx, sc[tid][nn]);
        float e[16], sum = 0.f;
        for (int nn=0;nn<16;nn++){ e[nn]=expf(sc[tid][nn]-mx); sum+=e[nn]; }
        float inv = 1.f/sum;
        for (int nn=0;nn<16;nn++) sw[tid][nn]=e[nn]*inv;
    }
    __syncthreads();
    for (int idx=tid; idx<512; idx+=256){
        int h = idx>>6;
        float s = 0.f;
        #pragma unroll
        for (int nn=0;nn<16;nn++)
            s += sw[h][nn]*g_v[(size_t)(m*Nly+nn)*Dsz + idx];
        g_att[(size_t)m*Dsz + idx] = s;
    }
}

// ---------------- layernorm + fp16 hi/lo split (fused) ------------------------
__global__ void __launch_bounds__(256) ln_k(const float* __restrict__ gam,
                                            const float* __restrict__ bet)
{
    int m = blockIdx.x, tid = threadIdx.x;
    __shared__ float sh[8];
    __shared__ float sh2[8];
    float* row = g_mix + (size_t)m*Dsz;
    float v0 = row[tid], v1 = row[tid+256];
    int lane = tid&31, w = tid>>5;

    float s = v0+v1;
    #pragma unroll
    for (int o=16;o>0;o>>=1) s += __shfl_xor_sync(0xffffffffu, s, o);
    if (lane==0) sh[w]=s;
    __syncthreads();
    float tot = sh[0]+sh[1]+sh[2]+sh[3]+sh[4]+sh[5]+sh[6]+sh[7];
    float mu = tot*(1.f/512.f);

    float d0=v0-mu, d1=v1-mu;
    float s2 = d0*d0+d1*d1;
    #pragma unroll
    for (int o=16;o>0;o>>=1) s2 += __shfl_xor_sync(0xffffffffu, s2, o);
    if (lane==0) sh2[w]=s2;
    __syncthreads();
    float tot2 = sh2[0]+sh2[1]+sh2[2]+sh2[3]+sh2[4]+sh2[5]+sh2[6]+sh2[7];
    float inv = rsqrtf(tot2*(1.f/512.f) + 1e-5f);

    float r0 = d0*inv*gam[tid]     + bet[tid];
    float r1 = d1*inv*gam[tid+256] + bet[tid+256];
    size_t o0 = (size_t)m*Dsz + tid, o1 = o0 + 256;
    __half h0 = __float2half(r0), h1 = __float2half(r1);
    hMix_h[o0] = h0; hMix_l[o0] = __float2half(r0 - __half2float(h0));
    hMix_h[o1] = h1; hMix_l[o1] = __float2half(r1 - __half2float(h1));
}

// ---------------- final state copy ------------------------------------------
__global__ void __launch_bounds__(256) copyhc_k(const float* __restrict__ hf,
                                                const float* __restrict__ cf,
                                                float* __restrict__ out)
{
    int idx = blockIdx.x*256 + threadIdx.x;
    const size_t L = (size_t)Bsz*Ssz*Vsz;
    out[L + idx]       = hf[idx];
    out[L + NBR + idx] = cf[idx];
}

// =============================================================================
extern "C" void kernel_launch(void* const* d_in, const int* in_sizes, int n_in,
                              void* d_out, int out_size)
{
    const int*   x      = (const int*)  d_in[0];
    const float* h0     = (const float*)d_in[1];
    const float* c0     = (const float*)d_in[2];
    const float* emb    = (const float*)d_in[3];
    const float* W_ih   = (const float*)d_in[4];
    const float* b_ih   = (const float*)d_in[5];
    const float* W_hh   = (const float*)d_in[6];
    const float* b_hh   = (const float*)d_in[7];
    const float* W_np   = (const float*)d_in[8];
    const float* b_np   = (const float*)d_in[9];
    const float* in_w   = (const float*)d_in[10];
    const float* in_b   = (const float*)d_in[11];
    const float* op_w   = (const float*)d_in[12];
    const float* op_b   = (const float*)d_in[13];
    const float* ln_g   = (const float*)d_in[14];
    const float* ln_b   = (const float*)d_in[15];
    const float* head_w = (const float*)d_in[16];
    const float* head_b = (const float*)d_in[17];
    float* out = (float*)d_out;

    cudaFuncSetAttribute(tgemm_k<1>, cudaFuncAttributeMaxDynamicSharedMemorySize, TG_SMEM);
    cudaFuncSetAttribute(tgemm_k<2>, cudaFuncAttributeMaxDynamicSharedMemorySize, TG_SMEM);
    cudaFuncSetAttribute(tgemm_k<3>, cudaFuncAttributeMaxDynamicSharedMemorySize, TG_SMEM);
    cudaFuncSetAttribute(lstm_mma,   cudaFuncAttributeMaxDynamicSharedMemorySize, L_SMEM);

    float *pX,*pGih,*pHall,*pCf,*pQ,*pCk,*pCv,*pK,*pV,*pAtt,*pMix;
    __half *pWih,*pWhh,*pHead,*pXH,*pXL,*pHallH,*pHallL,*pWnkH,*pWnvH,*pMixH,*pMixL;
    cudaGetSymbolAddress((void**)&pX,    g_X);
    cudaGetSymbolAddress((void**)&pGih,  g_Gih);
    cudaGetSymbolAddress((void**)&pHall, g_hall);
    cudaGetSymbolAddress((void**)&pCf,   g_cf);
    cudaGetSymbolAddress((void**)&pQ,    g_q);
    cudaGetSymbolAddress((void**)&pCk,   g_ck);
    cudaGetSymbolAddress((void**)&pCv,   g_cv);
    cudaGetSymbolAddress((void**)&pK,    g_k);
    cudaGetSymbolAddress((void**)&pV,    g_v);
    cudaGetSymbolAddress((void**)&pAtt,  g_att);
    cudaGetSymbolAddress((void**)&pMix,  g_mix);
    cudaGetSymbolAddress((void**)&pWih,  hWih);
    cudaGetSymbolAddress((void**)&pWhh,  hWhh);
    cudaGetSymbolAddress((void**)&pHead, hHead);
    cudaGetSymbolAddress((void**)&pXH,   hX_h);    cudaGetSymbolAddress((void**)&pXL, hX_l);
    cudaGetSymbolAddress((void**)&pHallH,hHall_h); cudaGetSymbolAddress((void**)&pHallL,hHall_l);
    cudaGetSymbolAddress((void**)&pWnkH, hWnk);
    cudaGetSymbolAddress((void**)&pWnvH, hWnv);
    cudaGetSymbolAddress((void**)&pMixH, hMix_h);  cudaGetSymbolAddress((void**)&pMixL, hMix_l);

    // Launch order: index 3 = tgemm_k<1> (ncu captures 4th launch)
    embed_split_k<<<(Mtok*Dsz)/256, 256>>>(x, emb);                              // 0
    cvtW2_k<<<2*(Nly*G4*Dsz)/256,256>>>(W_ih,pWih, W_hh,pWhh, Nly*G4*Dsz);       // 1 (+bars=0)
    cvtH_k<<<(Vsz*Dsz)/256,256>>>(head_w, pHead, Vsz*Dsz);                       // 2
    tgemm_k<1><<<dim3(16,16,16),256,TG_SMEM>>>(pXH,pXL,pWih,pGih,b_ih,b_hh);     // 3 <- profiled
    lstm_mma<<<128,256,L_SMEM>>>(pWhh, h0, c0, pHall, pHallH, pHallL, pGih, pCf);// 4

    // Phase 1 remainder + Phase 3
    gemm_k<0><<<dim3(4,16),256>>>(pX, in_w, pQ, nullptr, in_b, nullptr);
    gemm_k<5><<<dim3(4,4,16),256>>>(in_w +   Dsz*Dsz, W_np, nullptr, pWnkH, nullptr, nullptr);
    gemm_k<5><<<dim3(4,4,16),256>>>(in_w + 2*Dsz*Dsz, W_np, nullptr, pWnvH, nullptr, nullptr);
    ckcv_k<<<(Nly*Dsz)/256, 256>>>(in_w, in_b, b_np);
    tgemm_k<3><<<dim3(4,16,16),256,TG_SMEM>>>(pHallH,pHallL,pWnkH,pK,pCk,nullptr);
    tgemm_k<3><<<dim3(4,16,16),256,TG_SMEM>>>(pHallH,pHallL,pWnvH,pV,pCv,nullptr);
    attn_k<<<Mtok,256>>>();
    gemm_k<4><<<dim3(4,16),256>>>(pAtt, op_w, pMix, nullptr, op_b, pX);
    ln_k<<<Mtok,256>>>(ln_g, ln_b);
    tgemm_k<2><<<dim3(250,16),256,TG_SMEM>>>(pMixH,pMixL,pHead,out,head_b,nullptr);

    // hf / cf
    copyhc_k<<<NBR/256,256>>>(pHall, pCf, out);
}